// round 5
// baseline (speedup 1.0000x reference)
#include <cuda_runtime.h>
#include <cuda_bf16.h>
#include <cstdint>

#define RDIM 128
#define CDIM 384
#define EDIM 768
#define HDIM 12
#define DDIM 64
#define MDIM (RDIM * CDIM)   // 49152

// GEMM tiling
#define BK 64
#define PITCH 72                            // bf16/row (144B)
#define MTX_BYTES (128 * PITCH * 2)         // 18432
#define BUF_BYTES (4 * MTX_BYTES)           // 73728

// attention smem map (per-tile, bytes)
#define PA 72      // q/k rows: 144B
#define PVT 136    // vt rows: 272B
#define AQH 0
#define AQL 18432
#define AKH 36864
#define AKL 55296
#define AVTH 73728
#define AVTL 91136
#define ATS 108544             /* per-tile stride */
#define ABM (2 * ATS)          /* mask bitmap (4 x u32) */
#define ATOT (ABM + 16)

// ---------------- device scratch (allocation-free rule) ----------------
__device__ __nv_bfloat16 g_ah[(size_t)MDIM * EDIM];     // A hi (x, then ctx)
__device__ __nv_bfloat16 g_al[(size_t)MDIM * EDIM];     // A lo
__device__ __nv_bfloat16 g_wh[(size_t)4 * EDIM * EDIM]; // packed wq|wk|wv|wo hi
__device__ __nv_bfloat16 g_wl[(size_t)4 * EDIM * EDIM]; // lo
__device__ float g_bias[4 * EDIM];
__device__ __nv_bfloat16 g_qh[(size_t)MDIM * EDIM];     // [c][h][i][d]
__device__ __nv_bfloat16 g_ql[(size_t)MDIM * EDIM];
__device__ __nv_bfloat16 g_kh[(size_t)MDIM * EDIM];
__device__ __nv_bfloat16 g_kl[(size_t)MDIM * EDIM];
__device__ __nv_bfloat16 g_vh[(size_t)MDIM * EDIM];     // TRANSPOSED [c][h][d][i]
__device__ __nv_bfloat16 g_vl[(size_t)MDIM * EDIM];

// ---------------- helpers ----------------
__device__ __forceinline__ uint32_t smem_to_u32(const void* p) {
    uint32_t a;
    asm("{ .reg .u64 t; cvta.to.shared.u64 t, %1; cvt.u32.u64 %0, t; }"
        : "=r"(a) : "l"(p));
    return a;
}
__device__ __forceinline__ void cp16(uint32_t dst, const void* src) {
    asm volatile("cp.async.cg.shared.global [%0], [%1], 16;"
                 :: "r"(dst), "l"(src) : "memory");
}
__device__ __forceinline__ void cp_commit() {
    asm volatile("cp.async.commit_group;" ::: "memory");
}
__device__ __forceinline__ void cp_wait0() {
    asm volatile("cp.async.wait_group 0;" ::: "memory");
}
__device__ __forceinline__ void ldmx4(uint32_t (&r)[4], uint32_t addr) {
    asm volatile("ldmatrix.sync.aligned.m8n8.x4.shared.b16 {%0,%1,%2,%3}, [%4];"
                 : "=r"(r[0]), "=r"(r[1]), "=r"(r[2]), "=r"(r[3]) : "r"(addr));
}
__device__ __forceinline__ void mma16816(float (&d)[4], const uint32_t (&a)[4],
                                         uint32_t b0, uint32_t b1) {
    asm volatile(
        "mma.sync.aligned.m16n8k16.row.col.f32.bf16.bf16.f32 "
        "{%0,%1,%2,%3}, {%4,%5,%6,%7}, {%8,%9}, {%0,%1,%2,%3};"
        : "+f"(d[0]), "+f"(d[1]), "+f"(d[2]), "+f"(d[3])
        : "r"(a[0]), "r"(a[1]), "r"(a[2]), "r"(a[3]), "r"(b0), "r"(b1));
}
__device__ __forceinline__ void split2(float f, __nv_bfloat16& h, __nv_bfloat16& l) {
    h = __float2bfloat16(f);
    l = __float2bfloat16(f - __bfloat162float(h));
}
__device__ __forceinline__ uint32_t packsplit_hi(float a, float b) {
    __nv_bfloat16 ha = __float2bfloat16(a), hb = __float2bfloat16(b);
    __nv_bfloat162 p(ha, hb);
    return *(uint32_t*)&p;
}
__device__ __forceinline__ uint32_t packsplit_lo(float a, float b) {
    __nv_bfloat16 ha = __float2bfloat16(a), hb = __float2bfloat16(b);
    __nv_bfloat16 la = __float2bfloat16(a - __bfloat162float(ha));
    __nv_bfloat16 lb = __float2bfloat16(b - __bfloat162float(hb));
    __nv_bfloat162 p(la, lb);
    return *(uint32_t*)&p;
}

// ---------------- conversion kernels ----------------
__global__ void conv_x(const float* __restrict__ src, int n4) {
    int i = blockIdx.x * blockDim.x + threadIdx.x;
    if (i >= n4) return;
    float4 v = ((const float4*)src)[i];
    __nv_bfloat16 h0, h1, h2, h3, l0, l1, l2, l3;
    split2(v.x, h0, l0); split2(v.y, h1, l1); split2(v.z, h2, l2); split2(v.w, h3, l3);
    size_t o = (size_t)i * 4;
    *(__nv_bfloat162*)(g_ah + o)     = __nv_bfloat162(h0, h1);
    *(__nv_bfloat162*)(g_ah + o + 2) = __nv_bfloat162(h2, h3);
    *(__nv_bfloat162*)(g_al + o)     = __nv_bfloat162(l0, l1);
    *(__nv_bfloat162*)(g_al + o + 2) = __nv_bfloat162(l2, l3);
}

__global__ void conv_w(const float* __restrict__ wq, const float* __restrict__ wk,
                       const float* __restrict__ wv, const float* __restrict__ wo,
                       const float* __restrict__ bq, const float* __restrict__ bk,
                       const float* __restrict__ bv, const float* __restrict__ bo)
{
    const size_t WSZ = (size_t)EDIM * EDIM;
    size_t i = (size_t)blockIdx.x * blockDim.x + threadIdx.x;
    int sel = (int)(i / WSZ);
    size_t off = i - (size_t)sel * WSZ;
    const float* w = (sel == 0) ? wq : (sel == 1) ? wk : (sel == 2) ? wv : wo;
    __nv_bfloat16 h, l;
    split2(w[off], h, l);
    g_wh[i] = h; g_wl[i] = l;
    if (i < 4 * EDIM) {
        int s = (int)(i / EDIM), r = (int)(i % EDIM);
        const float* b = (s == 0) ? bq : (s == 1) ? bk : (s == 2) ? bv : bo;
        g_bias[i] = b[r];
    }
}

// ---------------- split-bf16 HMMA GEMM (BK=64, swizzled 1-D grid) ----------------
__global__ __launch_bounds__(512)
void gemm_tc(int n_off, int mode, int ny, float* __restrict__ outp)
{
    extern __shared__ char smdyn[];
    const uint32_t smb = smem_to_u32(smdyn);
    const int t = threadIdx.x;
    const int wid = t >> 5, lane = t & 31;
    const int wm = wid & 3, wn = wid >> 2;
    const int bm = (blockIdx.x / ny) * 128;          // ny-fastest: W stays in L2
    const int nb = n_off + (blockIdx.x % ny) * 128;

    const __nv_bfloat16* srcs[4] = {
        g_ah + (size_t)bm * EDIM, g_al + (size_t)bm * EDIM,
        g_wh + (size_t)nb * EDIM, g_wl + (size_t)nb * EDIM };

    float acc[2][4][4];
#pragma unroll
    for (int mi = 0; mi < 2; ++mi)
#pragma unroll
        for (int ni = 0; ni < 4; ++ni)
#pragma unroll
            for (int e = 0; e < 4; ++e) acc[mi][ni][e] = 0.0f;

    const int lrow8 = (lane & 7) + ((lane >> 3) & 1) * 8;
    const int lkoff = (lane >> 4) * 8;

    {
#pragma unroll
        for (int kk = 0; kk < 2; ++kk) {
            const int id = t + kk * 512;
            const int r = id >> 3, cl = id & 7;
            const uint32_t d = smb + (uint32_t)(r * (PITCH * 2) + cl * 16);
            const int s = r * EDIM + cl * 8;
#pragma unroll
            for (int m = 0; m < 4; ++m)
                cp16(d + m * MTX_BYTES, srcs[m] + s);
        }
        cp_commit();
    }

    const int NC = EDIM / BK;  // 12
#pragma unroll 1
    for (int ch = 0; ch < NC; ++ch) {
        cp_wait0();
        __syncthreads();
        if (ch + 1 < NC) {
            const uint32_t bufn = ((ch + 1) & 1) * BUF_BYTES;
#pragma unroll
            for (int kk = 0; kk < 2; ++kk) {
                const int id = t + kk * 512;
                const int r = id >> 3, cl = id & 7;
                const uint32_t d = smb + bufn + (uint32_t)(r * (PITCH * 2) + cl * 16);
                const int s = r * EDIM + (ch + 1) * BK + cl * 8;
#pragma unroll
                for (int m = 0; m < 4; ++m)
                    cp16(d + m * MTX_BYTES, srcs[m] + s);
            }
            cp_commit();
        }
        const uint32_t buf = smb + (ch & 1) * BUF_BYTES;
        const uint32_t aAh = buf + (uint32_t)((wm * 32 + lrow8) * (PITCH * 2));
        const uint32_t aB  = buf + 2 * MTX_BYTES +
                             (uint32_t)((wn * 32 + lrow8) * (PITCH * 2));
#pragma unroll
        for (int ks = 0; ks < 4; ++ks) {
            const uint32_t kbyte = (uint32_t)((ks * 16 + lkoff) * 2);
            uint32_t ah[2][4], al[2][4], bh[2][4], bl[2][4];
#pragma unroll
            for (int mi = 0; mi < 2; ++mi) {
                ldmx4(ah[mi], aAh + (uint32_t)(mi * 16 * PITCH * 2) + kbyte);
                ldmx4(al[mi], aAh + MTX_BYTES + (uint32_t)(mi * 16 * PITCH * 2) + kbyte);
            }
#pragma unroll
            for (int nbk = 0; nbk < 2; ++nbk) {
                ldmx4(bh[nbk], aB + (uint32_t)(nbk * 16 * PITCH * 2) + kbyte);
                ldmx4(bl[nbk], aB + MTX_BYTES + (uint32_t)(nbk * 16 * PITCH * 2) + kbyte);
            }
#pragma unroll
            for (int mi = 0; mi < 2; ++mi)
#pragma unroll
                for (int ni = 0; ni < 4; ++ni) {
                    const int nk = ni >> 1, lo = ni & 1;
                    mma16816(acc[mi][ni], ah[mi], bh[nk][lo], bh[nk][lo + 2]);
                    mma16816(acc[mi][ni], ah[mi], bl[nk][lo], bl[nk][lo + 2]);
                    mma16816(acc[mi][ni], al[mi], bh[nk][lo], bh[nk][lo + 2]);
                }
        }
    }

    const int r0 = bm + wm * 32 + (lane >> 2);
    const int cbase = nb + wn * 32 + (lane & 3) * 2;
#pragma unroll
    for (int mi = 0; mi < 2; ++mi) {
#pragma unroll
        for (int half = 0; half < 2; ++half) {
            const int m = r0 + mi * 16 + half * 8;
            const int i_ = m / CDIM, c_ = m % CDIM;
#pragma unroll
            for (int ni = 0; ni < 4; ++ni) {
                const int ng = cbase + ni * 8;
                float ox = acc[mi][ni][half * 2 + 0] + g_bias[ng + 0];
                float oy = acc[mi][ni][half * 2 + 1] + g_bias[ng + 1];
                if (mode == 0) {
                    if (ng < EDIM) { ox *= 0.125f; oy *= 0.125f; }
                    const int sel = ng / EDIM, f = ng % EDIM, h = f >> 6, d = f & 63;
                    __nv_bfloat16 hx, lx, hy, ly;
                    split2(ox, hx, lx); split2(oy, hy, ly);
                    if (sel == 2) {  // V: store transposed [c][h][d][i]
                        const size_t ot = (((size_t)c_ * HDIM + h) * DDIM + d) * RDIM + i_;
                        g_vh[ot] = hx; g_vh[ot + RDIM] = hy;
                        g_vl[ot] = lx; g_vl[ot + RDIM] = ly;
                    } else {
                        __nv_bfloat16* dh = (sel == 0) ? g_qh : g_kh;
                        __nv_bfloat16* dl = (sel == 0) ? g_ql : g_kl;
                        const size_t off = (((size_t)c_ * HDIM + h) * RDIM + i_) * DDIM + d;
                        *(__nv_bfloat162*)(dh + off) = __nv_bfloat162(hx, hy);
                        *(__nv_bfloat162*)(dl + off) = __nv_bfloat162(lx, ly);
                    }
                } else {
                    float2 o; o.x = ox; o.y = oy;
                    *(float2*)(outp + (size_t)m * EDIM + (ng - 3 * EDIM)) = o;
                }
            }
        }
    }
}

// ---------------- register-flash HMMA attention ----------------
// CTA: (c, head-pair). 512 threads = 16 warps; warp = (tile = wid>>3, rw = wid&7),
// warp owns rows [16rw, 16rw+16) of the full 128x128 S for head 2*hp + tile.
__global__ __launch_bounds__(512, 1)
void attn_tc(const unsigned char* __restrict__ mask, float* __restrict__ probs)
{
    extern __shared__ char sm[];
    const uint32_t smb = smem_to_u32(sm);
    const int c = blockIdx.x, hp = blockIdx.y;
    const int t = threadIdx.x, wid = t >> 5, lane = t & 31;

    // ---- loads (both tiles, all threads) ----
#pragma unroll
    for (int tl = 0; tl < 2; ++tl) {
        const size_t gb = ((size_t)c * HDIM + (hp * 2 + tl)) * (RDIM * DDIM);
        const __nv_bfloat16* sq[4] = { g_qh + gb, g_ql + gb, g_kh + gb, g_kl + gb };
        const uint32_t qo[4] = { AQH, AQL, AKH, AKL };
#pragma unroll
        for (int m = 0; m < 4; ++m)
#pragma unroll
            for (int k = 0; k < 2; ++k) {
                const int id = t + k * 512;
                const int r = id >> 3, cl = id & 7;
                cp16(smb + tl * ATS + qo[m] + (uint32_t)(r * (PA * 2) + cl * 16),
                     sq[m] + (size_t)r * DDIM + cl * 8);
            }
        const __nv_bfloat16* sv[2] = { g_vh + gb, g_vl + gb };
        const uint32_t vo[2] = { AVTH, AVTL };
#pragma unroll
        for (int m = 0; m < 2; ++m)
#pragma unroll
            for (int k = 0; k < 2; ++k) {
                const int id = t + k * 512;
                const int r = id >> 4, cl = id & 15;
                cp16(smb + tl * ATS + vo[m] + (uint32_t)(r * (PVT * 2) + cl * 16),
                     sv[m] + (size_t)r * RDIM + cl * 8);
            }
    }
    cp_commit();

    // mask bitmap
    uint32_t* bmw = (uint32_t*)(sm + ABM);
    if (t < 4) bmw[t] = 0;
    __syncthreads();
    if (t < RDIM && mask[(size_t)t * CDIM + c]) atomicOr(&bmw[t >> 5], 1u << (t & 31));
    cp_wait0();
    __syncthreads();
    const uint32_t mb[4] = { bmw[0], bmw[1], bmw[2], bmw[3] };
    const bool any_mask = (mb[0] | mb[1] | mb[2] | mb[3]) != 0;

    const int tl = wid >> 3, rw = wid & 7;
    const int h = hp * 2 + tl;
    const uint32_t tb = smb + tl * ATS;
    const int lrow8 = (lane & 7) + ((lane >> 3) & 1) * 8;
    const int lkoff = (lane >> 4) * 8;

    // ---- S = Q K^T : warp tile 16(m) x 128(n), k=64 ----
    float sacc[16][4];
#pragma unroll
    for (int ni = 0; ni < 16; ++ni)
#pragma unroll
        for (int e = 0; e < 4; ++e) sacc[ni][e] = 0.0f;

    const uint32_t qb = tb + AQH + (uint32_t)((rw * 16 + lrow8) * (PA * 2));
    const uint32_t kbse = tb + AKH + (uint32_t)(lrow8 * (PA * 2));
#pragma unroll
    for (int ks = 0; ks < 4; ++ks) {
        const uint32_t ko = (uint32_t)((ks * 16 + lkoff) * 2);
        uint32_t qh[4], ql[4];
        ldmx4(qh, qb + ko);
        ldmx4(ql, qb + 18432u + ko);
#pragma unroll
        for (int nh = 0; nh < 2; ++nh) {
            uint32_t kh[4][4], kl[4][4];
#pragma unroll
            for (int nb8 = 0; nb8 < 4; ++nb8) {
                const uint32_t ra = (uint32_t)((nh * 64 + nb8 * 16) * (PA * 2));
                ldmx4(kh[nb8], kbse + ra + ko);
                ldmx4(kl[nb8], kbse + 18432u + ra + ko);
            }
#pragma unroll
            for (int ni = 0; ni < 8; ++ni) {
                const int g = ni >> 1, lo = ni & 1, idx = nh * 8 + ni;
                mma16816(sacc[idx], qh, kh[g][lo], kh[g][lo + 2]);
                mma16816(sacc[idx], qh, kl[g][lo], kl[g][lo + 2]);
                mma16816(sacc[idx], ql, kh[g][lo], kh[g][lo + 2]);
            }
        }
    }

    // ---- mask + warp-local softmax (rows r0 = rw*16 + lane>>2, r0+8) ----
    if (any_mask) {
#pragma unroll
        for (int ni = 0; ni < 16; ++ni) {
            const uint32_t w = mb[ni >> 2];
            const int b0 = (ni & 3) * 8 + (lane & 3) * 2;
            if ((w >> b0) & 1)       { sacc[ni][0] = -10000.0f; sacc[ni][2] = -10000.0f; }
            if ((w >> (b0 + 1)) & 1) { sacc[ni][1] = -10000.0f; sacc[ni][3] = -10000.0f; }
        }
    }
    float mx0 = -3.0e38f, mx1 = -3.0e38f;
#pragma unroll
    for (int ni = 0; ni < 16; ++ni) {
        mx0 = fmaxf(mx0, fmaxf(sacc[ni][0], sacc[ni][1]));
        mx1 = fmaxf(mx1, fmaxf(sacc[ni][2], sacc[ni][3]));
    }
    mx0 = fmaxf(mx0, __shfl_xor_sync(0xffffffffu, mx0, 1));
    mx0 = fmaxf(mx0, __shfl_xor_sync(0xffffffffu, mx0, 2));
    mx1 = fmaxf(mx1, __shfl_xor_sync(0xffffffffu, mx1, 1));
    mx1 = fmaxf(mx1, __shfl_xor_sync(0xffffffffu, mx1, 2));

    float s0 = 0.0f, s1 = 0.0f;
#pragma unroll
    for (int ni = 0; ni < 16; ++ni) {
        sacc[ni][0] = __expf(sacc[ni][0] - mx0);
        sacc[ni][1] = __expf(sacc[ni][1] - mx0);
        sacc[ni][2] = __expf(sacc[ni][2] - mx1);
        sacc[ni][3] = __expf(sacc[ni][3] - mx1);
        s0 += sacc[ni][0] + sacc[ni][1];
        s1 += sacc[ni][2] + sacc[ni][3];
    }
    s0 += __shfl_xor_sync(0xffffffffu, s0, 1);
    s0 += __shfl_xor_sync(0xffffffffu, s0, 2);
    s1 += __shfl_xor_sync(0xffffffffu, s1, 1);
    s1 += __shfl_xor_sync(0xffffffffu, s1, 2);
    const float inv0 = 1.0f / s0, inv1 = 1.0f / s1;

    // ---- probs (normalized fp32) straight from registers ----
    {
        const int r0 = rw * 16 + (lane >> 2);
        float* pb = probs + (((size_t)h * CDIM + c) * RDIM + r0) * RDIM + (lane & 3) * 2;
#pragma unroll
        for (int ni = 0; ni < 16; ++ni) {
            float2 a; a.x = sacc[ni][0] * inv0; a.y = sacc[ni][1] * inv0;
            float2 b; b.x = sacc[ni][2] * inv1; b.y = sacc[ni][3] * inv1;
            *(float2*)(pb + ni * 8) = a;
            *(float2*)(pb + 8 * RDIM + ni * 8) = b;
        }
    }

    // ---- pack unnormalized P -> bf16 hi/lo A-fragments (in registers) ----
    uint32_t ph0[16], ph1[16], pl0[16], pl1[16];
#pragma unroll
    for (int ni = 0; ni < 16; ++ni) {
        ph0[ni] = packsplit_hi(sacc[ni][0], sacc[ni][1]);
        pl0[ni] = packsplit_lo(sacc[ni][0], sacc[ni][1]);
        ph1[ni] = packsplit_hi(sacc[ni][2], sacc[ni][3]);
        pl1[ni] = packsplit_lo(sacc[ni][2], sacc[ni][3]);
    }

    // ---- ctx = P V : warp tile 16(m) x 64(n), k=128, Vt is n-major ----
    float cacc[8][4];
#pragma unroll
    for (int ni = 0; ni < 8; ++ni)
#pragma unroll
        for (int e = 0; e < 4; ++e) cacc[ni][e] = 0.0f;

    const uint32_t vb = tb + AVTH + (uint32_t)(lrow8 * (PVT * 2));
#pragma unroll
    for (int kb = 0; kb < 8; ++kb) {
        const uint32_t ko = (uint32_t)((kb * 16 + lkoff) * 2);
        const uint32_t a_h[4] = { ph0[2 * kb], ph1[2 * kb], ph0[2 * kb + 1], ph1[2 * kb + 1] };
        const uint32_t a_l[4] = { pl0[2 * kb], pl1[2 * kb], pl0[2 * kb + 1], pl1[2 * kb + 1] };
#pragma unroll
        for (int vh2 = 0; vh2 < 2; ++vh2) {
            uint32_t vh[2][4], vl[2][4];
#pragma unroll
            for (int nb8 = 0; nb8 < 2; ++nb8) {
                const uint32_t ra = (uint32_t)((vh2 * 32 + nb8 * 16) * (PVT * 2));
                ldmx4(vh[nb8], vb + ra + ko);
                ldmx4(vl[nb8], vb + 17408u + ra + ko);
            }
#pragma unroll
            for (int nl = 0; nl < 4; ++nl) {
                const int g = nl >> 1, lo = nl & 1, idx = vh2 * 4 + nl;
                mma16816(cacc[idx], a_h, vh[g][lo], vh[g][lo + 2]);
                mma16816(cacc[idx], a_h, vl[g][lo], vl[g][lo + 2]);
                mma16816(cacc[idx], a_l, vh[g][lo], vh[g][lo + 2]);
            }
        }
    }

    // ---- ctx epilogue (normalize rows, split, feed out-projection) ----
    {
        const int r0 = rw * 16 + (lane >> 2);
#pragma unroll
        for (int ni = 0; ni < 8; ++ni) {
            const int d = ni * 8 + (lane & 3) * 2;
            const size_t ob0 = ((size_t)r0 * CDIM + c) * EDIM + h * DDIM + d;
            const size_t ob1 = ((size_t)(r0 + 8) * CDIM + c) * EDIM + h * DDIM + d;
            __nv_bfloat16 hx, lx, hy, ly;
            split2(cacc[ni][0] * inv0, hx, lx);
            split2(cacc[ni][1] * inv0, hy, ly);
            *(__nv_bfloat162*)(g_ah + ob0) = __nv_bfloat162(hx, hy);
            *(__nv_bfloat162*)(g_al + ob0) = __nv_bfloat162(lx, ly);
            split2(cacc[ni][2] * inv1, hx, lx);
            split2(cacc[ni][3] * inv1, hy, ly);
            *(__nv_bfloat162*)(g_ah + ob1) = __nv_bfloat162(hx, hy);
            *(__nv_bfloat162*)(g_al + ob1) = __nv_bfloat162(lx, ly);
        }
    }
}

// ---------------------------------------------------------------------------
extern "C" void kernel_launch(void* const* d_in, const int* in_sizes, int n_in,
                              void* d_out, int out_size)
{
    const float* x  = (const float*)d_in[0];
    const unsigned char* mask = (const unsigned char*)d_in[2];
    const float* wq = (const float*)d_in[3];
    const float* bq = (const float*)d_in[4];
    const float* wk = (const float*)d_in[5];
    const float* bk = (const float*)d_in[6];
    const float* wv = (const float*)d_in[7];
    const float* bv = (const float*)d_in[8];
    const float* wo = (const float*)d_in[9];
    const float* bo = (const float*)d_in[10];

    float* out   = (float*)d_out;                    // (R, C, 1, E)
    float* probs = out + (size_t)MDIM * EDIM;        // (H, C, 1, R, R)

    const int gemm_smem = 2 * BUF_BYTES;             // 147456
    cudaFuncSetAttribute(gemm_tc, cudaFuncAttributeMaxDynamicSharedMemorySize, gemm_smem);
    cudaFuncSetAttribute(attn_tc, cudaFuncAttributeMaxDynamicSharedMemorySize, ATOT);

    conv_w<<<2304, 1024>>>(wq, wk, wv, wo, bq, bk, bv, bo);
    conv_x<<<9216, 1024>>>(x, MDIM * EDIM / 4);
    gemm_tc<<<384 * 18, 512, gemm_smem>>>(0, 0, 18, out);            // qkv
    attn_tc<<<dim3(CDIM, HDIM / 2), 512, ATOT>>>(mask, probs);
    gemm_tc<<<384 * 6, 512, gemm_smem>>>(3 * EDIM, 1, 6, out);       // out proj
}

// round 6
// speedup vs baseline: 1.2293x; 1.2293x over previous
#include <cuda_runtime.h>
#include <cuda_bf16.h>
#include <cstdint>

#define RDIM 128
#define CDIM 384
#define EDIM 768
#define HDIM 12
#define DDIM 64
#define MDIM (RDIM * CDIM)   // 49152

// GEMM tiling: CTA 128x128, 4 warps (2x2), warp tile 64x64, BK=32
#define BK 32
#define GP 40                              // bf16/row (80B), conflict-free
#define MTX (128 * GP * 2)                 // 10240 B per matrix tile
#define GBUF (4 * MTX)                     // 40960 (Ah, Al, Bh, Bl)

// attention smem map (per-tile, bytes); V stored [i][d] like Q/K
#define PA 72      // q/k/v rows: 144B
#define PVT 136    // vt rows: 272B
#define AQH 0
#define AQL 18432
#define AKH 36864
#define AKL 55296
#define AVH 73728
#define AVL 92160
#define ATS 110592             /* per-tile stride */
#define AVTH 0                 /* Vt aliases Q region after S */
#define AVTL 17408
#define ABM (2 * ATS)          /* mask bitmap (4 x u32) */
#define ATOT (ABM + 16)

// ---------------- device scratch (allocation-free rule) ----------------
__device__ __nv_bfloat16 g_ah[(size_t)MDIM * EDIM];     // A hi (x, then ctx)
__device__ __nv_bfloat16 g_al[(size_t)MDIM * EDIM];     // A lo
__device__ __nv_bfloat16 g_wh[(size_t)4 * EDIM * EDIM]; // packed wq|wk|wv|wo hi
__device__ __nv_bfloat16 g_wl[(size_t)4 * EDIM * EDIM]; // lo
__device__ float g_bias[4 * EDIM];
__device__ __nv_bfloat16 g_qh[(size_t)MDIM * EDIM];     // [c][h][i][d]
__device__ __nv_bfloat16 g_ql[(size_t)MDIM * EDIM];
__device__ __nv_bfloat16 g_kh[(size_t)MDIM * EDIM];
__device__ __nv_bfloat16 g_kl[(size_t)MDIM * EDIM];
__device__ __nv_bfloat16 g_vh[(size_t)MDIM * EDIM];     // [c][h][i][d]
__device__ __nv_bfloat16 g_vl[(size_t)MDIM * EDIM];

// ---------------- helpers ----------------
__device__ __forceinline__ uint32_t smem_to_u32(const void* p) {
    uint32_t a;
    asm("{ .reg .u64 t; cvta.to.shared.u64 t, %1; cvt.u32.u64 %0, t; }"
        : "=r"(a) : "l"(p));
    return a;
}
__device__ __forceinline__ void cp16(uint32_t dst, const void* src) {
    asm volatile("cp.async.cg.shared.global [%0], [%1], 16;"
                 :: "r"(dst), "l"(src) : "memory");
}
__device__ __forceinline__ void cp_commit() {
    asm volatile("cp.async.commit_group;" ::: "memory");
}
__device__ __forceinline__ void cp_wait0() {
    asm volatile("cp.async.wait_group 0;" ::: "memory");
}
__device__ __forceinline__ void ldmx4(uint32_t (&r)[4], uint32_t addr) {
    asm volatile("ldmatrix.sync.aligned.m8n8.x4.shared.b16 {%0,%1,%2,%3}, [%4];"
                 : "=r"(r[0]), "=r"(r[1]), "=r"(r[2]), "=r"(r[3]) : "r"(addr));
}
__device__ __forceinline__ void mma16816(float (&d)[4], const uint32_t (&a)[4],
                                         uint32_t b0, uint32_t b1) {
    asm volatile(
        "mma.sync.aligned.m16n8k16.row.col.f32.bf16.bf16.f32 "
        "{%0,%1,%2,%3}, {%4,%5,%6,%7}, {%8,%9}, {%0,%1,%2,%3};"
        : "+f"(d[0]), "+f"(d[1]), "+f"(d[2]), "+f"(d[3])
        : "r"(a[0]), "r"(a[1]), "r"(a[2]), "r"(a[3]), "r"(b0), "r"(b1));
}
__device__ __forceinline__ void split2(float f, __nv_bfloat16& h, __nv_bfloat16& l) {
    h = __float2bfloat16(f);
    l = __float2bfloat16(f - __bfloat162float(h));
}
__device__ __forceinline__ uint32_t packsplit_hi(float a, float b) {
    __nv_bfloat16 ha = __float2bfloat16(a), hb = __float2bfloat16(b);
    __nv_bfloat162 p(ha, hb);
    return *(uint32_t*)&p;
}
__device__ __forceinline__ uint32_t packsplit_lo(float a, float b) {
    __nv_bfloat16 ha = __float2bfloat16(a), hb = __float2bfloat16(b);
    __nv_bfloat16 la = __float2bfloat16(a - __bfloat162float(ha));
    __nv_bfloat16 lb = __float2bfloat16(b - __bfloat162float(hb));
    __nv_bfloat162 p(la, lb);
    return *(uint32_t*)&p;
}

// ---------------- conversion kernels ----------------
__global__ void conv_x(const float* __restrict__ src, int n4) {
    int i = blockIdx.x * blockDim.x + threadIdx.x;
    if (i >= n4) return;
    float4 v = ((const float4*)src)[i];
    __nv_bfloat16 h0, h1, h2, h3, l0, l1, l2, l3;
    split2(v.x, h0, l0); split2(v.y, h1, l1); split2(v.z, h2, l2); split2(v.w, h3, l3);
    size_t o = (size_t)i * 4;
    *(__nv_bfloat162*)(g_ah + o)     = __nv_bfloat162(h0, h1);
    *(__nv_bfloat162*)(g_ah + o + 2) = __nv_bfloat162(h2, h3);
    *(__nv_bfloat162*)(g_al + o)     = __nv_bfloat162(l0, l1);
    *(__nv_bfloat162*)(g_al + o + 2) = __nv_bfloat162(l2, l3);
}

__global__ void conv_w(const float* __restrict__ wq, const float* __restrict__ wk,
                       const float* __restrict__ wv, const float* __restrict__ wo,
                       const float* __restrict__ bq, const float* __restrict__ bk,
                       const float* __restrict__ bv, const float* __restrict__ bo)
{
    const size_t WSZ = (size_t)EDIM * EDIM;
    size_t i = (size_t)blockIdx.x * blockDim.x + threadIdx.x;
    int sel = (int)(i / WSZ);
    size_t off = i - (size_t)sel * WSZ;
    const float* w = (sel == 0) ? wq : (sel == 1) ? wk : (sel == 2) ? wv : wo;
    __nv_bfloat16 h, l;
    split2(w[off], h, l);
    g_wh[i] = h; g_wl[i] = l;
    if (i < 4 * EDIM) {
        int s = (int)(i / EDIM), r = (int)(i % EDIM);
        const float* b = (s == 0) ? bq : (s == 1) ? bk : (s == 2) ? bv : bo;
        g_bias[i] = b[r];
    }
}

// ---------------- split-bf16 HMMA GEMM (128x128 CTA, warp tile 64x64) ----------------
__global__ __launch_bounds__(128, 2)
void gemm_tc(int n_off, int mode, float* __restrict__ outp)
{
    extern __shared__ char smdyn[];
    const uint32_t smb = smem_to_u32(smdyn);
    const int t = threadIdx.x;
    const int wid = t >> 5, lane = t & 31;
    const int wm = wid & 1, wn = wid >> 1;           // 2x2 warp grid
    const int bm = blockIdx.x * 128;
    const int nb = n_off + blockIdx.y * 128;

    const __nv_bfloat16* srcs[4] = {
        g_ah + (size_t)bm * EDIM, g_al + (size_t)bm * EDIM,
        g_wh + (size_t)nb * EDIM, g_wl + (size_t)nb * EDIM };

    float acc[4][8][4];
#pragma unroll
    for (int mi = 0; mi < 4; ++mi)
#pragma unroll
        for (int ni = 0; ni < 8; ++ni)
#pragma unroll
            for (int e = 0; e < 4; ++e) acc[mi][ni][e] = 0.0f;

    const int lrow8 = (lane & 7) + ((lane >> 3) & 1) * 8;
    const int lkoff = (lane >> 4) * 8;

    // prefetch chunk 0: per matrix 512 x 16B; 128 threads x 4
    {
#pragma unroll
        for (int kk = 0; kk < 4; ++kk) {
            const int id = t + kk * 128;
            const int r = id >> 2, cl = id & 3;
            const uint32_t d = smb + (uint32_t)(r * (GP * 2) + cl * 16);
            const int s = r * EDIM + cl * 8;
#pragma unroll
            for (int m = 0; m < 4; ++m)
                cp16(d + m * MTX, srcs[m] + s);
        }
        cp_commit();
    }

    const int NC = EDIM / BK;  // 24
#pragma unroll 1
    for (int ch = 0; ch < NC; ++ch) {
        cp_wait0();
        __syncthreads();
        if (ch + 1 < NC) {
            const uint32_t bufn = ((ch + 1) & 1) * GBUF;
#pragma unroll
            for (int kk = 0; kk < 4; ++kk) {
                const int id = t + kk * 128;
                const int r = id >> 2, cl = id & 3;
                const uint32_t d = smb + bufn + (uint32_t)(r * (GP * 2) + cl * 16);
                const int s = r * EDIM + (ch + 1) * BK + cl * 8;
#pragma unroll
                for (int m = 0; m < 4; ++m)
                    cp16(d + m * MTX, srcs[m] + s);
            }
            cp_commit();
        }
        const uint32_t buf = smb + (ch & 1) * GBUF;
        const uint32_t aA = buf + (uint32_t)((wm * 64 + lrow8) * (GP * 2));
        const uint32_t aB = buf + 2 * MTX + (uint32_t)((wn * 64 + lrow8) * (GP * 2));
#pragma unroll
        for (int ks = 0; ks < 2; ++ks) {
            const uint32_t kbyte = (uint32_t)((ks * 16 + lkoff) * 2);
            uint32_t ah[4][4], al[4][4];
#pragma unroll
            for (int mi = 0; mi < 4; ++mi) {
                ldmx4(ah[mi], aA + (uint32_t)(mi * 16 * GP * 2) + kbyte);
                ldmx4(al[mi], aA + MTX + (uint32_t)(mi * 16 * GP * 2) + kbyte);
            }
#pragma unroll
            for (int ng = 0; ng < 4; ++ng) {
                uint32_t bh[4], bl[4];
                ldmx4(bh, aB + (uint32_t)(ng * 16 * GP * 2) + kbyte);
                ldmx4(bl, aB + MTX + (uint32_t)(ng * 16 * GP * 2) + kbyte);
#pragma unroll
                for (int mi = 0; mi < 4; ++mi)
#pragma unroll
                    for (int lo = 0; lo < 2; ++lo) {
                        float (&d)[4] = acc[mi][ng * 2 + lo];
                        mma16816(d, ah[mi], bh[lo], bh[lo + 2]);
                        mma16816(d, ah[mi], bl[lo], bl[lo + 2]);
                        mma16816(d, al[mi], bh[lo], bh[lo + 2]);
                    }
            }
        }
    }

    // epilogue
    const int r0 = bm + wm * 64 + (lane >> 2);
    const int cbase = nb + wn * 64 + (lane & 3) * 2;
#pragma unroll
    for (int mi = 0; mi < 4; ++mi) {
#pragma unroll
        for (int half = 0; half < 2; ++half) {
            const int m = r0 + mi * 16 + half * 8;
            const int i_ = m / CDIM, c_ = m % CDIM;
#pragma unroll
            for (int ni = 0; ni < 8; ++ni) {
                const int ng = cbase + ni * 8;
                float ox = acc[mi][ni][half * 2 + 0] + g_bias[ng + 0];
                float oy = acc[mi][ni][half * 2 + 1] + g_bias[ng + 1];
                if (mode == 0) {
                    if (ng < EDIM) { ox *= 0.125f; oy *= 0.125f; }
                    const int sel = ng / EDIM, f = ng % EDIM, h = f >> 6, d = f & 63;
                    __nv_bfloat16* dh = (sel == 0) ? g_qh : (sel == 1) ? g_kh : g_vh;
                    __nv_bfloat16* dl = (sel == 0) ? g_ql : (sel == 1) ? g_kl : g_vl;
                    const size_t off = (((size_t)c_ * HDIM + h) * RDIM + i_) * DDIM + d;
                    __nv_bfloat16 hx, lx, hy, ly;
                    split2(ox, hx, lx); split2(oy, hy, ly);
                    *(__nv_bfloat162*)(dh + off) = __nv_bfloat162(hx, hy);
                    *(__nv_bfloat162*)(dl + off) = __nv_bfloat162(lx, ly);
                } else {
                    float2 o; o.x = ox; o.y = oy;
                    *(float2*)(outp + (size_t)m * EDIM + (ng - 3 * EDIM)) = o;
                }
            }
        }
    }
}

// ---------------- register-flash HMMA attention (2 heads/CTA) ----------------
__global__ __launch_bounds__(512, 1)
void attn_tc(const unsigned char* __restrict__ mask, float* __restrict__ probs)
{
    extern __shared__ char sm[];
    const uint32_t smb = smem_to_u32(sm);
    const int c = blockIdx.x, hp = blockIdx.y;
    const int t = threadIdx.x, wid = t >> 5, lane = t & 31;

    // ---- loads: q/k/v hi+lo for both heads, all [128][64] ----
#pragma unroll
    for (int tl2 = 0; tl2 < 2; ++tl2) {
        const size_t gb = ((size_t)c * HDIM + (hp * 2 + tl2)) * (RDIM * DDIM);
        const __nv_bfloat16* sq[6] = { g_qh + gb, g_ql + gb, g_kh + gb,
                                       g_kl + gb, g_vh + gb, g_vl + gb };
        const uint32_t qo[6] = { AQH, AQL, AKH, AKL, AVH, AVL };
#pragma unroll
        for (int m = 0; m < 6; ++m)
#pragma unroll
            for (int k = 0; k < 2; ++k) {
                const int id = t + k * 512;
                const int r = id >> 3, cl = id & 7;
                cp16(smb + tl2 * ATS + qo[m] + (uint32_t)(r * (PA * 2) + cl * 16),
                     sq[m] + (size_t)r * DDIM + cl * 8);
            }
    }
    cp_commit();

    // mask bitmap
    uint32_t* bmw = (uint32_t*)(sm + ABM);
    if (t < 4) bmw[t] = 0;
    __syncthreads();
    if (t < RDIM && mask[(size_t)t * CDIM + c]) atomicOr(&bmw[t >> 5], 1u << (t & 31));
    cp_wait0();
    __syncthreads();
    const uint32_t mb[4] = { bmw[0], bmw[1], bmw[2], bmw[3] };
    const bool any_mask = (mb[0] | mb[1] | mb[2] | mb[3]) != 0;

    const int tl = wid >> 3, rw = wid & 7;
    const int h = hp * 2 + tl;
    const uint32_t tb = smb + tl * ATS;
    const int lrow8 = (lane & 7) + ((lane >> 3) & 1) * 8;
    const int lkoff = (lane >> 4) * 8;

    // ---- S = Q K^T : warp tile 16(m) x 128(n), k=64 ----
    float sacc[16][4];
#pragma unroll
    for (int ni = 0; ni < 16; ++ni)
#pragma unroll
        for (int e = 0; e < 4; ++e) sacc[ni][e] = 0.0f;

    const uint32_t qb = tb + AQH + (uint32_t)((rw * 16 + lrow8) * (PA * 2));
    const uint32_t kbse = tb + AKH + (uint32_t)(lrow8 * (PA * 2));
#pragma unroll
    for (int ks = 0; ks < 4; ++ks) {
        const uint32_t ko = (uint32_t)((ks * 16 + lkoff) * 2);
        uint32_t qh[4], ql[4];
        ldmx4(qh, qb + ko);
        ldmx4(ql, qb + 18432u + ko);
#pragma unroll
        for (int nh = 0; nh < 2; ++nh) {
            uint32_t kh[4][4], kl[4][4];
#pragma unroll
            for (int nb8 = 0; nb8 < 4; ++nb8) {
                const uint32_t ra = (uint32_t)((nh * 64 + nb8 * 16) * (PA * 2));
                ldmx4(kh[nb8], kbse + ra + ko);
                ldmx4(kl[nb8], kbse + 18432u + ra + ko);
            }
#pragma unroll
            for (int ni = 0; ni < 8; ++ni) {
                const int g = ni >> 1, lo = ni & 1, idx = nh * 8 + ni;
                mma16816(sacc[idx], qh, kh[g][lo], kh[g][lo + 2]);
                mma16816(sacc[idx], qh, kl[g][lo], kl[g][lo + 2]);
                mma16816(sacc[idx], ql, kh[g][lo], kh[g][lo + 2]);
            }
        }
    }

    // ---- mask + warp-local softmax ----
    if (any_mask) {
#pragma unroll
        for (int ni = 0; ni < 16; ++ni) {
            const uint32_t w = mb[ni >> 2];
            const int b0 = (ni & 3) * 8 + (lane & 3) * 2;
            if ((w >> b0) & 1)       { sacc[ni][0] = -10000.0f; sacc[ni][2] = -10000.0f; }
            if ((w >> (b0 + 1)) & 1) { sacc[ni][1] = -10000.0f; sacc[ni][3] = -10000.0f; }
        }
    }
    float mx0 = -3.0e38f, mx1 = -3.0e38f;
#pragma unroll
    for (int ni = 0; ni < 16; ++ni) {
        mx0 = fmaxf(mx0, fmaxf(sacc[ni][0], sacc[ni][1]));
        mx1 = fmaxf(mx1, fmaxf(sacc[ni][2], sacc[ni][3]));
    }
    mx0 = fmaxf(mx0, __shfl_xor_sync(0xffffffffu, mx0, 1));
    mx0 = fmaxf(mx0, __shfl_xor_sync(0xffffffffu, mx0, 2));
    mx1 = fmaxf(mx1, __shfl_xor_sync(0xffffffffu, mx1, 1));
    mx1 = fmaxf(mx1, __shfl_xor_sync(0xffffffffu, mx1, 2));

    float s0 = 0.0f, s1 = 0.0f;
#pragma unroll
    for (int ni = 0; ni < 16; ++ni) {
        sacc[ni][0] = __expf(sacc[ni][0] - mx0);
        sacc[ni][1] = __expf(sacc[ni][1] - mx0);
        sacc[ni][2] = __expf(sacc[ni][2] - mx1);
        sacc[ni][3] = __expf(sacc[ni][3] - mx1);
        s0 += sacc[ni][0] + sacc[ni][1];
        s1 += sacc[ni][2] + sacc[ni][3];
    }
    s0 += __shfl_xor_sync(0xffffffffu, s0, 1);
    s0 += __shfl_xor_sync(0xffffffffu, s0, 2);
    s1 += __shfl_xor_sync(0xffffffffu, s1, 1);
    s1 += __shfl_xor_sync(0xffffffffu, s1, 2);
    const float inv0 = 1.0f / s0, inv1 = 1.0f / s1;

    // ---- probs (normalized fp32) straight from registers ----
    {
        const int r0 = rw * 16 + (lane >> 2);
        float* pb = probs + (((size_t)h * CDIM + c) * RDIM + r0) * RDIM + (lane & 3) * 2;
#pragma unroll
        for (int ni = 0; ni < 16; ++ni) {
            float2 a; a.x = sacc[ni][0] * inv0; a.y = sacc[ni][1] * inv0;
            float2 b; b.x = sacc[ni][2] * inv1; b.y = sacc[ni][3] * inv1;
            *(float2*)(pb + ni * 8) = a;
            *(float2*)(pb + 8 * RDIM + ni * 8) = b;
        }
    }

    // ---- pack unnormalized P -> bf16 hi/lo A-fragments ----
    uint32_t ph0[16], ph1[16], pl0[16], pl1[16];
#pragma unroll
    for (int ni = 0; ni < 16; ++ni) {
        ph0[ni] = packsplit_hi(sacc[ni][0], sacc[ni][1]);
        pl0[ni] = packsplit_lo(sacc[ni][0], sacc[ni][1]);
        ph1[ni] = packsplit_hi(sacc[ni][2], sacc[ni][3]);
        pl1[ni] = packsplit_lo(sacc[ni][2], sacc[ni][3]);
    }

    // ---- transpose V [j][d] -> Vt [d][j] into (now free) Q/K region ----
    __syncthreads();
#pragma unroll
    for (int tl2 = 0; tl2 < 2; ++tl2) {
        const __nv_bfloat16* vh = (const __nv_bfloat16*)(sm + tl2 * ATS + AVH);
        const __nv_bfloat16* vl = (const __nv_bfloat16*)(sm + tl2 * ATS + AVL);
        __nv_bfloat16* vth = (__nv_bfloat16*)(sm + tl2 * ATS + AVTH);
        __nv_bfloat16* vtl = (__nv_bfloat16*)(sm + tl2 * ATS + AVTL);
#pragma unroll
        for (int k = 0; k < 16; ++k) {
            const int idx = t + k * 512;
            const int j = idx >> 6, d = idx & 63;
            vth[d * PVT + j] = vh[j * PA + d];
            vtl[d * PVT + j] = vl[j * PA + d];
        }
    }
    __syncthreads();

    // ---- ctx = P V : warp tile 16(m) x 64(n), k=128, Vt n-major ----
    float cacc[8][4];
#pragma unroll
    for (int ni = 0; ni < 8; ++ni)
#pragma unroll
        for (int e = 0; e < 4; ++e) cacc[ni][e] = 0.0f;

    const uint32_t vb = tb + AVTH + (uint32_t)(lrow8 * (PVT * 2));
#pragma unroll
    for (int kb = 0; kb < 8; ++kb) {
        const uint32_t ko = (uint32_t)((kb * 16 + lkoff) * 2);
        const uint32_t a_h[4] = { ph0[2 * kb], ph1[2 * kb], ph0[2 * kb + 1], ph1[2 * kb + 1] };
        const uint32_t a_l[4] = { pl0[2 * kb], pl1[2 * kb], pl0[2 * kb + 1], pl1[2 * kb + 1] };
#pragma unroll
        for (int vh2 = 0; vh2 < 2; ++vh2) {
            uint32_t vh[2][4], vl[2][4];
#pragma unroll
            for (int nb8 = 0; nb8 < 2; ++nb8) {
                const uint32_t ra = (uint32_t)((vh2 * 32 + nb8 * 16) * (PVT * 2));
                ldmx4(vh[nb8], vb + ra + ko);
                ldmx4(vl[nb8], vb + (uint32_t)AVTL + ra + ko);
            }
#pragma unroll
            for (int nl = 0; nl < 4; ++nl) {
                const int g = nl >> 1, lo = nl & 1, idx = vh2 * 4 + nl;
                mma16816(cacc[idx], a_h, vh[g][lo], vh[g][lo + 2]);
                mma16816(cacc[idx], a_h, vl[g][lo], vl[g][lo + 2]);
                mma16816(cacc[idx], a_l, vh[g][lo], vh[g][lo + 2]);
            }
        }
    }

    // ---- ctx epilogue (normalize, split, feed out-projection) ----
    {
        const int r0 = rw * 16 + (lane >> 2);
#pragma unroll
        for (int ni = 0; ni < 8; ++ni) {
            const int d = ni * 8 + (lane & 3) * 2;
            const size_t ob0 = ((size_t)r0 * CDIM + c) * EDIM + h * DDIM + d;
            const size_t ob1 = ((size_t)(r0 + 8) * CDIM + c) * EDIM + h * DDIM + d;
            __nv_bfloat16 hx, lx, hy, ly;
            split2(cacc[ni][0] * inv0, hx, lx);
            split2(cacc[ni][1] * inv0, hy, ly);
            *(__nv_bfloat162*)(g_ah + ob0) = __nv_bfloat162(hx, hy);
            *(__nv_bfloat162*)(g_al + ob0) = __nv_bfloat162(lx, ly);
            split2(cacc[ni][2] * inv1, hx, lx);
            split2(cacc[ni][3] * inv1, hy, ly);
            *(__nv_bfloat162*)(g_ah + ob1) = __nv_bfloat162(hx, hy);
            *(__nv_bfloat162*)(g_al + ob1) = __nv_bfloat162(lx, ly);
        }
    }
}

// ---------------------------------------------------------------------------
extern "C" void kernel_launch(void* const* d_in, const int* in_sizes, int n_in,
                              void* d_out, int out_size)
{
    const float* x  = (const float*)d_in[0];
    const unsigned char* mask = (const unsigned char*)d_in[2];
    const float* wq = (const float*)d_in[3];
    const float* bq = (const float*)d_in[4];
    const float* wk = (const float*)d_in[5];
    const float* bk = (const float*)d_in[6];
    const float* wv = (const float*)d_in[7];
    const float* bv = (const float*)d_in[8];
    const float* wo = (const float*)d_in[9];
    const float* bo = (const float*)d_in[10];

    float* out   = (float*)d_out;                    // (R, C, 1, E)
    float* probs = out + (size_t)MDIM * EDIM;        // (H, C, 1, R, R)

    const int gemm_smem = 2 * GBUF;                  // 81920
    cudaFuncSetAttribute(gemm_tc, cudaFuncAttributeMaxDynamicSharedMemorySize, gemm_smem);
    cudaFuncSetAttribute(attn_tc, cudaFuncAttributeMaxDynamicSharedMemorySize, ATOT);

    conv_w<<<2304, 1024>>>(wq, wk, wv, wo, bq, bk, bv, bo);
    conv_x<<<9216, 1024>>>(x, MDIM * EDIM / 4);
    gemm_tc<<<dim3(MDIM / 128, 18), 128, gemm_smem>>>(0, 0, out);        // qkv
    attn_tc<<<dim3(CDIM, HDIM / 2), 512, ATOT>>>(mask, probs);
    gemm_tc<<<dim3(MDIM / 128, 6), 128, gemm_smem>>>(3 * EDIM, 1, out);  // out proj
}

// round 7
// speedup vs baseline: 1.2460x; 1.0136x over previous
#include <cuda_runtime.h>
#include <cuda_bf16.h>
#include <cstdint>

#define RDIM 128
#define CDIM 384
#define EDIM 768
#define HDIM 12
#define DDIM 64
#define MDIM (RDIM * CDIM)   // 49152

// GEMM tiling: CTA 128x128, 8 warps (2x4), warp tile 64x32, BK=32
#define BK 32
#define GP 40                              // bf16/row (80B), conflict-free
#define MTX (128 * GP * 2)                 // 10240 B per matrix tile
#define GBUF (4 * MTX)                     // 40960 (Ah, Al, Bh, Bl)

// attention smem map (per-tile, bytes); V stored [i][d] like Q/K
#define PA 72      // q/k/v rows: 144B
#define PVT 136    // vt rows: 272B
#define AQH 0
#define AQL 18432
#define AKH 36864
#define AKL 55296
#define AVH 73728
#define AVL 92160
#define ATS 110592             /* per-tile stride */
#define AVTH 0                 /* Vt aliases Q region after S */
#define AVTL 17408
#define ABM (2 * ATS)          /* mask bitmap (4 x u32) */
#define ATOT (ABM + 16)

// ---------------- device scratch (allocation-free rule) ----------------
__device__ __nv_bfloat16 g_ah[(size_t)MDIM * EDIM];     // A hi (x, then ctx)
__device__ __nv_bfloat16 g_al[(size_t)MDIM * EDIM];     // A lo
__device__ __nv_bfloat16 g_wh[(size_t)4 * EDIM * EDIM]; // packed wq|wk|wv|wo hi
__device__ __nv_bfloat16 g_wl[(size_t)4 * EDIM * EDIM]; // lo
__device__ float g_bias[4 * EDIM];
__device__ __nv_bfloat16 g_qh[(size_t)MDIM * EDIM];     // [c][h][i][d]
__device__ __nv_bfloat16 g_ql[(size_t)MDIM * EDIM];
__device__ __nv_bfloat16 g_kh[(size_t)MDIM * EDIM];
__device__ __nv_bfloat16 g_kl[(size_t)MDIM * EDIM];
__device__ __nv_bfloat16 g_vh[(size_t)MDIM * EDIM];     // [c][h][i][d]
__device__ __nv_bfloat16 g_vl[(size_t)MDIM * EDIM];

// ---------------- helpers ----------------
__device__ __forceinline__ uint32_t smem_to_u32(const void* p) {
    uint32_t a;
    asm("{ .reg .u64 t; cvta.to.shared.u64 t, %1; cvt.u32.u64 %0, t; }"
        : "=r"(a) : "l"(p));
    return a;
}
__device__ __forceinline__ void cp16(uint32_t dst, const void* src) {
    asm volatile("cp.async.cg.shared.global [%0], [%1], 16;"
                 :: "r"(dst), "l"(src) : "memory");
}
__device__ __forceinline__ void cp_commit() {
    asm volatile("cp.async.commit_group;" ::: "memory");
}
__device__ __forceinline__ void cp_wait0() {
    asm volatile("cp.async.wait_group 0;" ::: "memory");
}
__device__ __forceinline__ void ldmx4(uint32_t (&r)[4], uint32_t addr) {
    asm volatile("ldmatrix.sync.aligned.m8n8.x4.shared.b16 {%0,%1,%2,%3}, [%4];"
                 : "=r"(r[0]), "=r"(r[1]), "=r"(r[2]), "=r"(r[3]) : "r"(addr));
}
__device__ __forceinline__ void mma16816(float (&d)[4], const uint32_t (&a)[4],
                                         uint32_t b0, uint32_t b1) {
    asm volatile(
        "mma.sync.aligned.m16n8k16.row.col.f32.bf16.bf16.f32 "
        "{%0,%1,%2,%3}, {%4,%5,%6,%7}, {%8,%9}, {%0,%1,%2,%3};"
        : "+f"(d[0]), "+f"(d[1]), "+f"(d[2]), "+f"(d[3])
        : "r"(a[0]), "r"(a[1]), "r"(a[2]), "r"(a[3]), "r"(b0), "r"(b1));
}
__device__ __forceinline__ void split2(float f, __nv_bfloat16& h, __nv_bfloat16& l) {
    h = __float2bfloat16(f);
    l = __float2bfloat16(f - __bfloat162float(h));
}
__device__ __forceinline__ uint32_t packsplit_hi(float a, float b) {
    __nv_bfloat16 ha = __float2bfloat16(a), hb = __float2bfloat16(b);
    __nv_bfloat162 p(ha, hb);
    return *(uint32_t*)&p;
}
__device__ __forceinline__ uint32_t packsplit_lo(float a, float b) {
    __nv_bfloat16 ha = __float2bfloat16(a), hb = __float2bfloat16(b);
    __nv_bfloat16 la = __float2bfloat16(a - __bfloat162float(ha));
    __nv_bfloat16 lb = __float2bfloat16(b - __bfloat162float(hb));
    __nv_bfloat162 p(la, lb);
    return *(uint32_t*)&p;
}

// ---------------- conversion kernels ----------------
__global__ void conv_x(const float* __restrict__ src, int n4) {
    int i = blockIdx.x * blockDim.x + threadIdx.x;
    if (i >= n4) return;
    float4 v = ((const float4*)src)[i];
    __nv_bfloat16 h0, h1, h2, h3, l0, l1, l2, l3;
    split2(v.x, h0, l0); split2(v.y, h1, l1); split2(v.z, h2, l2); split2(v.w, h3, l3);
    size_t o = (size_t)i * 4;
    *(__nv_bfloat162*)(g_ah + o)     = __nv_bfloat162(h0, h1);
    *(__nv_bfloat162*)(g_ah + o + 2) = __nv_bfloat162(h2, h3);
    *(__nv_bfloat162*)(g_al + o)     = __nv_bfloat162(l0, l1);
    *(__nv_bfloat162*)(g_al + o + 2) = __nv_bfloat162(l2, l3);
}

__global__ void conv_w(const float* __restrict__ wq, const float* __restrict__ wk,
                       const float* __restrict__ wv, const float* __restrict__ wo,
                       const float* __restrict__ bq, const float* __restrict__ bk,
                       const float* __restrict__ bv, const float* __restrict__ bo)
{
    const size_t WSZ = (size_t)EDIM * EDIM;
    size_t i = (size_t)blockIdx.x * blockDim.x + threadIdx.x;
    int sel = (int)(i / WSZ);
    size_t off = i - (size_t)sel * WSZ;
    const float* w = (sel == 0) ? wq : (sel == 1) ? wk : (sel == 2) ? wv : wo;
    __nv_bfloat16 h, l;
    split2(w[off], h, l);
    g_wh[i] = h; g_wl[i] = l;
    if (i < 4 * EDIM) {
        int s = (int)(i / EDIM), r = (int)(i % EDIM);
        const float* b = (s == 0) ? bq : (s == 1) ? bk : (s == 2) ? bv : bo;
        g_bias[i] = b[r];
    }
}

// ---------------- split-bf16 HMMA GEMM (128x128 CTA, 8 warps, warp tile 64x32) ----------------
__global__ __launch_bounds__(256, 2)
void gemm_tc(int n_off, int mode, float* __restrict__ outp)
{
    extern __shared__ char smdyn[];
    const uint32_t smb = smem_to_u32(smdyn);
    const int t = threadIdx.x;
    const int wid = t >> 5, lane = t & 31;
    const int wm = wid & 1, wn = wid >> 1;           // 2x4 warp grid
    const int bm = blockIdx.x * 128;
    const int nb = n_off + blockIdx.y * 128;

    const __nv_bfloat16* srcs[4] = {
        g_ah + (size_t)bm * EDIM, g_al + (size_t)bm * EDIM,
        g_wh + (size_t)nb * EDIM, g_wl + (size_t)nb * EDIM };

    float acc[4][4][4];
#pragma unroll
    for (int mi = 0; mi < 4; ++mi)
#pragma unroll
        for (int ni = 0; ni < 4; ++ni)
#pragma unroll
            for (int e = 0; e < 4; ++e) acc[mi][ni][e] = 0.0f;

    const int lrow8 = (lane & 7) + ((lane >> 3) & 1) * 8;
    const int lkoff = (lane >> 4) * 8;

    // prefetch chunk 0: per matrix 512 x 16B; 256 threads x 2
    {
#pragma unroll
        for (int kk = 0; kk < 2; ++kk) {
            const int id = t + kk * 256;
            const int r = id >> 2, cl = id & 3;
            const uint32_t d = smb + (uint32_t)(r * (GP * 2) + cl * 16);
            const int s = r * EDIM + cl * 8;
#pragma unroll
            for (int m = 0; m < 4; ++m)
                cp16(d + m * MTX, srcs[m] + s);
        }
        cp_commit();
    }

    const int NC = EDIM / BK;  // 24
#pragma unroll 1
    for (int ch = 0; ch < NC; ++ch) {
        cp_wait0();
        __syncthreads();
        if (ch + 1 < NC) {
            const uint32_t bufn = ((ch + 1) & 1) * GBUF;
#pragma unroll
            for (int kk = 0; kk < 2; ++kk) {
                const int id = t + kk * 256;
                const int r = id >> 2, cl = id & 3;
                const uint32_t d = smb + bufn + (uint32_t)(r * (GP * 2) + cl * 16);
                const int s = r * EDIM + (ch + 1) * BK + cl * 8;
#pragma unroll
                for (int m = 0; m < 4; ++m)
                    cp16(d + m * MTX, srcs[m] + s);
            }
            cp_commit();
        }
        const uint32_t buf = smb + (ch & 1) * GBUF;
        const uint32_t aA = buf + (uint32_t)((wm * 64 + lrow8) * (GP * 2));
        const uint32_t aB = buf + 2 * MTX + (uint32_t)((wn * 32 + lrow8) * (GP * 2));
#pragma unroll
        for (int ks = 0; ks < 2; ++ks) {
            const uint32_t kbyte = (uint32_t)((ks * 16 + lkoff) * 2);
            // B fragments: 2 n16-groups (hi/lo)
            uint32_t bh[2][4], bl[2][4];
#pragma unroll
            for (int ng = 0; ng < 2; ++ng) {
                ldmx4(bh[ng], aB + (uint32_t)(ng * 16 * GP * 2) + kbyte);
                ldmx4(bl[ng], aB + MTX + (uint32_t)(ng * 16 * GP * 2) + kbyte);
            }
            // A per m-tile (short live range keeps regs <= 128)
#pragma unroll
            for (int mi = 0; mi < 4; ++mi) {
                uint32_t ah[4], al[4];
                ldmx4(ah, aA + (uint32_t)(mi * 16 * GP * 2) + kbyte);
                ldmx4(al, aA + MTX + (uint32_t)(mi * 16 * GP * 2) + kbyte);
#pragma unroll
                for (int ni = 0; ni < 4; ++ni) {
                    const int ng = ni >> 1, lo = ni & 1;
                    float (&d)[4] = acc[mi][ni];
                    mma16816(d, ah, bh[ng][lo], bh[ng][lo + 2]);
                    mma16816(d, ah, bl[ng][lo], bl[ng][lo + 2]);
                    mma16816(d, al, bh[ng][lo], bh[ng][lo + 2]);
                }
            }
        }
    }

    // epilogue
    const int r0 = bm + wm * 64 + (lane >> 2);
    const int cbase = nb + wn * 32 + (lane & 3) * 2;
#pragma unroll
    for (int mi = 0; mi < 4; ++mi) {
#pragma unroll
        for (int half = 0; half < 2; ++half) {
            const int m = r0 + mi * 16 + half * 8;
            const int i_ = m / CDIM, c_ = m % CDIM;
#pragma unroll
            for (int ni = 0; ni < 4; ++ni) {
                const int ng = cbase + ni * 8;
                float ox = acc[mi][ni][half * 2 + 0] + g_bias[ng + 0];
                float oy = acc[mi][ni][half * 2 + 1] + g_bias[ng + 1];
                if (mode == 0) {
                    if (ng < EDIM) { ox *= 0.125f; oy *= 0.125f; }
                    const int sel = ng / EDIM, f = ng % EDIM, h = f >> 6, d = f & 63;
                    __nv_bfloat16* dh = (sel == 0) ? g_qh : (sel == 1) ? g_kh : g_vh;
                    __nv_bfloat16* dl = (sel == 0) ? g_ql : (sel == 1) ? g_kl : g_vl;
                    const size_t off = (((size_t)c_ * HDIM + h) * RDIM + i_) * DDIM + d;
                    __nv_bfloat16 hx, lx, hy, ly;
                    split2(ox, hx, lx); split2(oy, hy, ly);
                    *(__nv_bfloat162*)(dh + off) = __nv_bfloat162(hx, hy);
                    *(__nv_bfloat162*)(dl + off) = __nv_bfloat162(lx, ly);
                } else {
                    float2 o; o.x = ox; o.y = oy;
                    *(float2*)(outp + (size_t)m * EDIM + (ng - 3 * EDIM)) = o;
                }
            }
        }
    }
}

// ---------------- register-flash HMMA attention (2 heads/CTA) ----------------
__global__ __launch_bounds__(512, 1)
void attn_tc(const unsigned char* __restrict__ mask, float* __restrict__ probs)
{
    extern __shared__ char sm[];
    const uint32_t smb = smem_to_u32(sm);
    const int c = blockIdx.x, hp = blockIdx.y;
    const int t = threadIdx.x, wid = t >> 5, lane = t & 31;

    // ---- loads: q/k/v hi+lo for both heads, all [128][64] ----
#pragma unroll
    for (int tl2 = 0; tl2 < 2; ++tl2) {
        const size_t gb = ((size_t)c * HDIM + (hp * 2 + tl2)) * (RDIM * DDIM);
        const __nv_bfloat16* sq[6] = { g_qh + gb, g_ql + gb, g_kh + gb,
                                       g_kl + gb, g_vh + gb, g_vl + gb };
        const uint32_t qo[6] = { AQH, AQL, AKH, AKL, AVH, AVL };
#pragma unroll
        for (int m = 0; m < 6; ++m)
#pragma unroll
            for (int k = 0; k < 2; ++k) {
                const int id = t + k * 512;
                const int r = id >> 3, cl = id & 7;
                cp16(smb + tl2 * ATS + qo[m] + (uint32_t)(r * (PA * 2) + cl * 16),
                     sq[m] + (size_t)r * DDIM + cl * 8);
            }
    }
    cp_commit();

    // mask bitmap
    uint32_t* bmw = (uint32_t*)(sm + ABM);
    if (t < 4) bmw[t] = 0;
    __syncthreads();
    if (t < RDIM && mask[(size_t)t * CDIM + c]) atomicOr(&bmw[t >> 5], 1u << (t & 31));
    cp_wait0();
    __syncthreads();
    const uint32_t mb[4] = { bmw[0], bmw[1], bmw[2], bmw[3] };
    const bool any_mask = (mb[0] | mb[1] | mb[2] | mb[3]) != 0;

    const int tl = wid >> 3, rw = wid & 7;
    const int h = hp * 2 + tl;
    const uint32_t tb = smb + tl * ATS;
    const int lrow8 = (lane & 7) + ((lane >> 3) & 1) * 8;
    const int lkoff = (lane >> 4) * 8;

    // ---- S = Q K^T : warp tile 16(m) x 128(n), k=64 ----
    float sacc[16][4];
#pragma unroll
    for (int ni = 0; ni < 16; ++ni)
#pragma unroll
        for (int e = 0; e < 4; ++e) sacc[ni][e] = 0.0f;

    const uint32_t qb = tb + AQH + (uint32_t)((rw * 16 + lrow8) * (PA * 2));
    const uint32_t kbse = tb + AKH + (uint32_t)(lrow8 * (PA * 2));
#pragma unroll
    for (int ks = 0; ks < 4; ++ks) {
        const uint32_t ko = (uint32_t)((ks * 16 + lkoff) * 2);
        uint32_t qh[4], ql[4];
        ldmx4(qh, qb + ko);
        ldmx4(ql, qb + 18432u + ko);
#pragma unroll
        for (int nh = 0; nh < 2; ++nh) {
            uint32_t kh[4][4], kl[4][4];
#pragma unroll
            for (int nb8 = 0; nb8 < 4; ++nb8) {
                const uint32_t ra = (uint32_t)((nh * 64 + nb8 * 16) * (PA * 2));
                ldmx4(kh[nb8], kbse + ra + ko);
                ldmx4(kl[nb8], kbse + 18432u + ra + ko);
            }
#pragma unroll
            for (int ni = 0; ni < 8; ++ni) {
                const int g = ni >> 1, lo = ni & 1, idx = nh * 8 + ni;
                mma16816(sacc[idx], qh, kh[g][lo], kh[g][lo + 2]);
                mma16816(sacc[idx], qh, kl[g][lo], kl[g][lo + 2]);
                mma16816(sacc[idx], ql, kh[g][lo], kh[g][lo + 2]);
            }
        }
    }

    // ---- mask + warp-local softmax ----
    if (any_mask) {
#pragma unroll
        for (int ni = 0; ni < 16; ++ni) {
            const uint32_t w = mb[ni >> 2];
            const int b0 = (ni & 3) * 8 + (lane & 3) * 2;
            if ((w >> b0) & 1)       { sacc[ni][0] = -10000.0f; sacc[ni][2] = -10000.0f; }
            if ((w >> (b0 + 1)) & 1) { sacc[ni][1] = -10000.0f; sacc[ni][3] = -10000.0f; }
        }
    }
    float mx0 = -3.0e38f, mx1 = -3.0e38f;
#pragma unroll
    for (int ni = 0; ni < 16; ++ni) {
        mx0 = fmaxf(mx0, fmaxf(sacc[ni][0], sacc[ni][1]));
        mx1 = fmaxf(mx1, fmaxf(sacc[ni][2], sacc[ni][3]));
    }
    mx0 = fmaxf(mx0, __shfl_xor_sync(0xffffffffu, mx0, 1));
    mx0 = fmaxf(mx0, __shfl_xor_sync(0xffffffffu, mx0, 2));
    mx1 = fmaxf(mx1, __shfl_xor_sync(0xffffffffu, mx1, 1));
    mx1 = fmaxf(mx1, __shfl_xor_sync(0xffffffffu, mx1, 2));

    float s0 = 0.0f, s1 = 0.0f;
#pragma unroll
    for (int ni = 0; ni < 16; ++ni) {
        sacc[ni][0] = __expf(sacc[ni][0] - mx0);
        sacc[ni][1] = __expf(sacc[ni][1] - mx0);
        sacc[ni][2] = __expf(sacc[ni][2] - mx1);
        sacc[ni][3] = __expf(sacc[ni][3] - mx1);
        s0 += sacc[ni][0] + sacc[ni][1];
        s1 += sacc[ni][2] + sacc[ni][3];
    }
    s0 += __shfl_xor_sync(0xffffffffu, s0, 1);
    s0 += __shfl_xor_sync(0xffffffffu, s0, 2);
    s1 += __shfl_xor_sync(0xffffffffu, s1, 1);
    s1 += __shfl_xor_sync(0xffffffffu, s1, 2);
    const float inv0 = 1.0f / s0, inv1 = 1.0f / s1;

    // ---- probs (normalized fp32) straight from registers ----
    {
        const int r0 = rw * 16 + (lane >> 2);
        float* pb = probs + (((size_t)h * CDIM + c) * RDIM + r0) * RDIM + (lane & 3) * 2;
#pragma unroll
        for (int ni = 0; ni < 16; ++ni) {
            float2 a; a.x = sacc[ni][0] * inv0; a.y = sacc[ni][1] * inv0;
            float2 b; b.x = sacc[ni][2] * inv1; b.y = sacc[ni][3] * inv1;
            *(float2*)(pb + ni * 8) = a;
            *(float2*)(pb + 8 * RDIM + ni * 8) = b;
        }
    }

    // ---- pack unnormalized P -> bf16 hi/lo A-fragments ----
    uint32_t ph0[16], ph1[16], pl0[16], pl1[16];
#pragma unroll
    for (int ni = 0; ni < 16; ++ni) {
        ph0[ni] = packsplit_hi(sacc[ni][0], sacc[ni][1]);
        pl0[ni] = packsplit_lo(sacc[ni][0], sacc[ni][1]);
        ph1[ni] = packsplit_hi(sacc[ni][2], sacc[ni][3]);
        pl1[ni] = packsplit_lo(sacc[ni][2], sacc[ni][3]);
    }

    // ---- transpose V [j][d] -> Vt [d][j] into (now free) Q/K region ----
    __syncthreads();
#pragma unroll
    for (int tl2 = 0; tl2 < 2; ++tl2) {
        const __nv_bfloat16* vh = (const __nv_bfloat16*)(sm + tl2 * ATS + AVH);
        const __nv_bfloat16* vl = (const __nv_bfloat16*)(sm + tl2 * ATS + AVL);
        __nv_bfloat16* vth = (__nv_bfloat16*)(sm + tl2 * ATS + AVTH);
        __nv_bfloat16* vtl = (__nv_bfloat16*)(sm + tl2 * ATS + AVTL);
#pragma unroll
        for (int k = 0; k < 16; ++k) {
            const int idx = t + k * 512;
            const int j = idx >> 6, d = idx & 63;
            vth[d * PVT + j] = vh[j * PA + d];
            vtl[d * PVT + j] = vl[j * PA + d];
        }
    }
    __syncthreads();

    // ---- ctx = P V : warp tile 16(m) x 64(n), k=128, Vt n-major ----
    float cacc[8][4];
#pragma unroll
    for (int ni = 0; ni < 8; ++ni)
#pragma unroll
        for (int e = 0; e < 4; ++e) cacc[ni][e] = 0.0f;

    const uint32_t vb = tb + AVTH + (uint32_t)(lrow8 * (PVT * 2));
#pragma unroll
    for (int kb = 0; kb < 8; ++kb) {
        const uint32_t ko = (uint32_t)((kb * 16 + lkoff) * 2);
        const uint32_t a_h[4] = { ph0[2 * kb], ph1[2 * kb], ph0[2 * kb + 1], ph1[2 * kb + 1] };
        const uint32_t a_l[4] = { pl0[2 * kb], pl1[2 * kb], pl0[2 * kb + 1], pl1[2 * kb + 1] };
#pragma unroll
        for (int vh2 = 0; vh2 < 2; ++vh2) {
            uint32_t vh[2][4], vl[2][4];
#pragma unroll
            for (int nb8 = 0; nb8 < 2; ++nb8) {
                const uint32_t ra = (uint32_t)((vh2 * 32 + nb8 * 16) * (PVT * 2));
                ldmx4(vh[nb8], vb + ra + ko);
                ldmx4(vl[nb8], vb + (uint32_t)AVTL + ra + ko);
            }
#pragma unroll
            for (int nl = 0; nl < 4; ++nl) {
                const int g = nl >> 1, lo = nl & 1, idx = vh2 * 4 + nl;
                mma16816(cacc[idx], a_h, vh[g][lo], vh[g][lo + 2]);
                mma16816(cacc[idx], a_h, vl[g][lo], vl[g][lo + 2]);
                mma16816(cacc[idx], a_l, vh[g][lo], vh[g][lo + 2]);
            }
        }
    }

    // ---- ctx epilogue (normalize, split, feed out-projection) ----
    {
        const int r0 = rw * 16 + (lane >> 2);
#pragma unroll
        for (int ni = 0; ni < 8; ++ni) {
            const int d = ni * 8 + (lane & 3) * 2;
            const size_t ob0 = ((size_t)r0 * CDIM + c) * EDIM + h * DDIM + d;
            const size_t ob1 = ((size_t)(r0 + 8) * CDIM + c) * EDIM + h * DDIM + d;
            __nv_bfloat16 hx, lx, hy, ly;
            split2(cacc[ni][0] * inv0, hx, lx);
            split2(cacc[ni][1] * inv0, hy, ly);
            *(__nv_bfloat162*)(g_ah + ob0) = __nv_bfloat162(hx, hy);
            *(__nv_bfloat162*)(g_al + ob0) = __nv_bfloat162(lx, ly);
            split2(cacc[ni][2] * inv1, hx, lx);
            split2(cacc[ni][3] * inv1, hy, ly);
            *(__nv_bfloat162*)(g_ah + ob1) = __nv_bfloat162(hx, hy);
            *(__nv_bfloat162*)(g_al + ob1) = __nv_bfloat162(lx, ly);
        }
    }
}

// ---------------------------------------------------------------------------
extern "C" void kernel_launch(void* const* d_in, const int* in_sizes, int n_in,
                              void* d_out, int out_size)
{
    const float* x  = (const float*)d_in[0];
    const unsigned char* mask = (const unsigned char*)d_in[2];
    const float* wq = (const float*)d_in[3];
    const float* bq = (const float*)d_in[4];
    const float* wk = (const float*)d_in[5];
    const float* bk = (const float*)d_in[6];
    const float* wv = (const float*)d_in[7];
    const float* bv = (const float*)d_in[8];
    const float* wo = (const float*)d_in[9];
    const float* bo = (const float*)d_in[10];

    float* out   = (float*)d_out;                    // (R, C, 1, E)
    float* probs = out + (size_t)MDIM * EDIM;        // (H, C, 1, R, R)

    const int gemm_smem = 2 * GBUF;                  // 81920
    cudaFuncSetAttribute(gemm_tc, cudaFuncAttributeMaxDynamicSharedMemorySize, gemm_smem);
    cudaFuncSetAttribute(attn_tc, cudaFuncAttributeMaxDynamicSharedMemorySize, ATOT);

    conv_w<<<2304, 1024>>>(wq, wk, wv, wo, bq, bk, bv, bo);
    conv_x<<<9216, 1024>>>(x, MDIM * EDIM / 4);
    gemm_tc<<<dim3(MDIM / 128, 18), 256, gemm_smem>>>(0, 0, out);        // qkv
    attn_tc<<<dim3(CDIM, HDIM / 2), 512, ATOT>>>(mask, probs);
    gemm_tc<<<dim3(MDIM / 128, 6), 256, gemm_smem>>>(3 * EDIM, 1, out);  // out proj
}

// round 8
// speedup vs baseline: 1.7467x; 1.4018x over previous
#include <cuda_runtime.h>
#include <cuda_fp16.h>
#include <cstdint>

#define RDIM 128
#define CDIM 384
#define EDIM 768
#define HDIM 12
#define DDIM 64
#define MDIM (RDIM * CDIM)   // 49152

// GEMM tiling: CTA 128x128, 8 warps (2x4), warp tile 64x32, BK=32
#define BK 32
#define GP 40                              // fp16/row (80B), conflict-free
#define MTX (128 * GP * 2)                 // 10240 B per matrix tile
#define GBUF (3 * MTX)                     // 30720 (Ah, Al, B)

// attention smem map (per-tile, bytes): qh, ql, k, v each 128x64 fp16 @ pitch PA
#define PA 72      // rows: 144B
#define PVT 136    // vt rows: 272B
#define AQH 0
#define AQL 18432
#define AK  36864
#define AV  55296
#define ATS 73728              /* per-tile stride */
#define AVT 0                  /* Vt (64 x PVT = 34816 B) aliases QH/QL after S */
#define ABM (2 * ATS)          /* mask bitmap (4 x u32) */
#define ATOT (ABM + 16)

// ---------------- device scratch (allocation-free rule) ----------------
__device__ __half g_ah[(size_t)MDIM * EDIM];     // A hi (x, then ctx)
__device__ __half g_al[(size_t)MDIM * EDIM];     // A lo
__device__ __half g_w[(size_t)4 * EDIM * EDIM];  // packed wq|wk|wv|wo (single fp16)
__device__ float g_bias[4 * EDIM];
__device__ __half g_qh[(size_t)MDIM * EDIM];     // [c][h][i][d] q hi
__device__ __half g_ql[(size_t)MDIM * EDIM];     // q lo
__device__ __half g_k[(size_t)MDIM * EDIM];      // k single
__device__ __half g_v[(size_t)MDIM * EDIM];      // v single

// ---------------- helpers ----------------
__device__ __forceinline__ uint32_t smem_to_u32(const void* p) {
    uint32_t a;
    asm("{ .reg .u64 t; cvta.to.shared.u64 t, %1; cvt.u32.u64 %0, t; }"
        : "=r"(a) : "l"(p));
    return a;
}
__device__ __forceinline__ void cp16(uint32_t dst, const void* src) {
    asm volatile("cp.async.cg.shared.global [%0], [%1], 16;"
                 :: "r"(dst), "l"(src) : "memory");
}
__device__ __forceinline__ void cp_commit() {
    asm volatile("cp.async.commit_group;" ::: "memory");
}
__device__ __forceinline__ void cp_wait0() {
    asm volatile("cp.async.wait_group 0;" ::: "memory");
}
__device__ __forceinline__ void ldmx4(uint32_t (&r)[4], uint32_t addr) {
    asm volatile("ldmatrix.sync.aligned.m8n8.x4.shared.b16 {%0,%1,%2,%3}, [%4];"
                 : "=r"(r[0]), "=r"(r[1]), "=r"(r[2]), "=r"(r[3]) : "r"(addr));
}
__device__ __forceinline__ void mma16816(float (&d)[4], const uint32_t (&a)[4],
                                         uint32_t b0, uint32_t b1) {
    asm volatile(
        "mma.sync.aligned.m16n8k16.row.col.f32.f16.f16.f32 "
        "{%0,%1,%2,%3}, {%4,%5,%6,%7}, {%8,%9}, {%0,%1,%2,%3};"
        : "+f"(d[0]), "+f"(d[1]), "+f"(d[2]), "+f"(d[3])
        : "r"(a[0]), "r"(a[1]), "r"(a[2]), "r"(a[3]), "r"(b0), "r"(b1));
}
__device__ __forceinline__ void split2h(float f, __half& h, __half& l) {
    h = __float2half_rn(f);
    l = __float2half_rn(f - __half2float(h));
}
__device__ __forceinline__ uint32_t packh(float a, float b) {
    __half2 p(__float2half_rn(a), __float2half_rn(b));
    return *(uint32_t*)&p;
}
__device__ __forceinline__ uint32_t packl(float a, float b) {
    __half ha = __float2half_rn(a), hb = __float2half_rn(b);
    __half2 p(__float2half_rn(a - __half2float(ha)),
              __float2half_rn(b - __half2float(hb)));
    return *(uint32_t*)&p;
}

// ---------------- conversion kernels ----------------
__global__ void conv_x(const float* __restrict__ src, int n4) {
    int i = blockIdx.x * blockDim.x + threadIdx.x;
    if (i >= n4) return;
    float4 v = ((const float4*)src)[i];
    __half h0, h1, h2, h3, l0, l1, l2, l3;
    split2h(v.x, h0, l0); split2h(v.y, h1, l1);
    split2h(v.z, h2, l2); split2h(v.w, h3, l3);
    size_t o = (size_t)i * 4;
    *(__half2*)(g_ah + o)     = __half2(h0, h1);
    *(__half2*)(g_ah + o + 2) = __half2(h2, h3);
    *(__half2*)(g_al + o)     = __half2(l0, l1);
    *(__half2*)(g_al + o + 2) = __half2(l2, l3);
}

__global__ void conv_w(const float* __restrict__ wq, const float* __restrict__ wk,
                       const float* __restrict__ wv, const float* __restrict__ wo,
                       const float* __restrict__ bq, const float* __restrict__ bk,
                       const float* __restrict__ bv, const float* __restrict__ bo)
{
    const size_t WSZ = (size_t)EDIM * EDIM;
    size_t i = (size_t)blockIdx.x * blockDim.x + threadIdx.x;
    int sel = (int)(i / WSZ);
    size_t off = i - (size_t)sel * WSZ;
    const float* w = (sel == 0) ? wq : (sel == 1) ? wk : (sel == 2) ? wv : wo;
    g_w[i] = __float2half_rn(w[off]);
    if (i < 4 * EDIM) {
        int s = (int)(i / EDIM), r = (int)(i % EDIM);
        const float* b = (s == 0) ? bq : (s == 1) ? bk : (s == 2) ? bv : bo;
        g_bias[i] = b[r];
    }
}

// ---------------- 2-product fp16 HMMA GEMM ----------------
// C[128x128] = (Ah + Al)[128,768] * W[nb..nb+128, 768]^T (+bias)
__global__ __launch_bounds__(256, 2)
void gemm_tc(int n_off, int mode, float* __restrict__ outp)
{
    extern __shared__ char smdyn[];
    const uint32_t smb = smem_to_u32(smdyn);
    const int t = threadIdx.x;
    const int wid = t >> 5, lane = t & 31;
    const int wm = wid & 1, wn = wid >> 1;           // 2x4 warp grid
    const int bm = blockIdx.x * 128;
    const int nb = n_off + blockIdx.y * 128;

    const __half* srcs[3] = {
        g_ah + (size_t)bm * EDIM, g_al + (size_t)bm * EDIM,
        g_w + (size_t)nb * EDIM };

    float acc[4][4][4];
#pragma unroll
    for (int mi = 0; mi < 4; ++mi)
#pragma unroll
        for (int ni = 0; ni < 4; ++ni)
#pragma unroll
            for (int e = 0; e < 4; ++e) acc[mi][ni][e] = 0.0f;

    const int lrow8 = (lane & 7) + ((lane >> 3) & 1) * 8;
    const int lkoff = (lane >> 4) * 8;

    // prefetch chunk 0: per matrix 512 x 16B; 256 threads x 2
    {
#pragma unroll
        for (int kk = 0; kk < 2; ++kk) {
            const int id = t + kk * 256;
            const int r = id >> 2, cl = id & 3;
            const uint32_t d = smb + (uint32_t)(r * (GP * 2) + cl * 16);
            const int s = r * EDIM + cl * 8;
#pragma unroll
            for (int m = 0; m < 3; ++m)
                cp16(d + m * MTX, srcs[m] + s);
        }
        cp_commit();
    }

    const int NC = EDIM / BK;  // 24
#pragma unroll 1
    for (int ch = 0; ch < NC; ++ch) {
        cp_wait0();
        __syncthreads();
        if (ch + 1 < NC) {
            const uint32_t bufn = ((ch + 1) & 1) * GBUF;
#pragma unroll
            for (int kk = 0; kk < 2; ++kk) {
                const int id = t + kk * 256;
                const int r = id >> 2, cl = id & 3;
                const uint32_t d = smb + bufn + (uint32_t)(r * (GP * 2) + cl * 16);
                const int s = r * EDIM + (ch + 1) * BK + cl * 8;
#pragma unroll
                for (int m = 0; m < 3; ++m)
                    cp16(d + m * MTX, srcs[m] + s);
            }
            cp_commit();
        }
        const uint32_t buf = smb + (ch & 1) * GBUF;
        const uint32_t aA = buf + (uint32_t)((wm * 64 + lrow8) * (GP * 2));
        const uint32_t aB = buf + 2 * MTX + (uint32_t)((wn * 32 + lrow8) * (GP * 2));
#pragma unroll
        for (int ks = 0; ks < 2; ++ks) {
            const uint32_t kbyte = (uint32_t)((ks * 16 + lkoff) * 2);
            uint32_t bfr[2][4];
#pragma unroll
            for (int ng = 0; ng < 2; ++ng)
                ldmx4(bfr[ng], aB + (uint32_t)(ng * 16 * GP * 2) + kbyte);
#pragma unroll
            for (int mi = 0; mi < 4; ++mi) {
                uint32_t ah[4], al[4];
                ldmx4(ah, aA + (uint32_t)(mi * 16 * GP * 2) + kbyte);
                ldmx4(al, aA + MTX + (uint32_t)(mi * 16 * GP * 2) + kbyte);
#pragma unroll
                for (int ni = 0; ni < 4; ++ni) {
                    const int ng = ni >> 1, lo = ni & 1;
                    float (&d)[4] = acc[mi][ni];
                    mma16816(d, ah, bfr[ng][lo], bfr[ng][lo + 2]);
                    mma16816(d, al, bfr[ng][lo], bfr[ng][lo + 2]);
                }
            }
        }
    }

    // epilogue
    const int r0 = bm + wm * 64 + (lane >> 2);
    const int cbase = nb + wn * 32 + (lane & 3) * 2;
#pragma unroll
    for (int mi = 0; mi < 4; ++mi) {
#pragma unroll
        for (int half = 0; half < 2; ++half) {
            const int m = r0 + mi * 16 + half * 8;
            const int i_ = m / CDIM, c_ = m % CDIM;
#pragma unroll
            for (int ni = 0; ni < 4; ++ni) {
                const int ng = cbase + ni * 8;
                float ox = acc[mi][ni][half * 2 + 0] + g_bias[ng + 0];
                float oy = acc[mi][ni][half * 2 + 1] + g_bias[ng + 1];
                if (mode == 0) {
                    const int sel = ng / EDIM, f = ng % EDIM, h = f >> 6, d = f & 63;
                    const size_t off = (((size_t)c_ * HDIM + h) * RDIM + i_) * DDIM + d;
                    if (sel == 0) {          // q: scaled, split hi/lo
                        ox *= 0.125f; oy *= 0.125f;
                        __half hx, lx, hy, ly;
                        split2h(ox, hx, lx); split2h(oy, hy, ly);
                        *(__half2*)(g_qh + off) = __half2(hx, hy);
                        *(__half2*)(g_ql + off) = __half2(lx, ly);
                    } else {                 // k, v: single fp16
                        __half* dst = (sel == 1) ? g_k : g_v;
                        *(__half2*)(dst + off) =
                            __half2(__float2half_rn(ox), __float2half_rn(oy));
                    }
                } else {
                    float2 o; o.x = ox; o.y = oy;
                    *(float2*)(outp + (size_t)m * EDIM + (ng - 3 * EDIM)) = o;
                }
            }
        }
    }
}

// ---------------- register-flash fp16 HMMA attention (2 heads/CTA) ----------------
__global__ __launch_bounds__(512, 1)
void attn_tc(const unsigned char* __restrict__ mask, float* __restrict__ probs)
{
    extern __shared__ char sm[];
    const uint32_t smb = smem_to_u32(sm);
    const int c = blockIdx.x, hp = blockIdx.y;
    const int t = threadIdx.x, wid = t >> 5, lane = t & 31;

    // ---- loads: qh, ql, k, v for both heads, all [128][64] fp16 ----
#pragma unroll
    for (int tl2 = 0; tl2 < 2; ++tl2) {
        const size_t gb = ((size_t)c * HDIM + (hp * 2 + tl2)) * (RDIM * DDIM);
        const __half* sq[4] = { g_qh + gb, g_ql + gb, g_k + gb, g_v + gb };
        const uint32_t qo[4] = { AQH, AQL, AK, AV };
#pragma unroll
        for (int m = 0; m < 4; ++m)
#pragma unroll
            for (int k = 0; k < 2; ++k) {
                const int id = t + k * 512;
                const int r = id >> 3, cl = id & 7;
                cp16(smb + tl2 * ATS + qo[m] + (uint32_t)(r * (PA * 2) + cl * 16),
                     sq[m] + (size_t)r * DDIM + cl * 8);
            }
    }
    cp_commit();

    // mask bitmap
    uint32_t* bmw = (uint32_t*)(sm + ABM);
    if (t < 4) bmw[t] = 0;
    __syncthreads();
    if (t < RDIM && mask[(size_t)t * CDIM + c]) atomicOr(&bmw[t >> 5], 1u << (t & 31));
    cp_wait0();
    __syncthreads();
    const uint32_t mb[4] = { bmw[0], bmw[1], bmw[2], bmw[3] };
    const bool any_mask = (mb[0] | mb[1] | mb[2] | mb[3]) != 0;

    const int tl = wid >> 3, rw = wid & 7;
    const int h = hp * 2 + tl;
    const uint32_t tb = smb + tl * ATS;
    const int lrow8 = (lane & 7) + ((lane >> 3) & 1) * 8;
    const int lkoff = (lane >> 4) * 8;

    // ---- S = (Qh+Ql) K^T : warp tile 16(m) x 128(n), k=64 ----
    float sacc[16][4];
#pragma unroll
    for (int ni = 0; ni < 16; ++ni)
#pragma unroll
        for (int e = 0; e < 4; ++e) sacc[ni][e] = 0.0f;

    const uint32_t qb = tb + AQH + (uint32_t)((rw * 16 + lrow8) * (PA * 2));
    const uint32_t kbse = tb + AK + (uint32_t)(lrow8 * (PA * 2));
#pragma unroll
    for (int ks = 0; ks < 4; ++ks) {
        const uint32_t ko = (uint32_t)((ks * 16 + lkoff) * 2);
        uint32_t qh[4], ql[4];
        ldmx4(qh, qb + ko);
        ldmx4(ql, qb + 18432u + ko);
#pragma unroll
        for (int nh = 0; nh < 2; ++nh) {
            uint32_t kf[4][4];
#pragma unroll
            for (int nb8 = 0; nb8 < 4; ++nb8)
                ldmx4(kf[nb8], kbse + (uint32_t)((nh * 64 + nb8 * 16) * (PA * 2)) + ko);
#pragma unroll
            for (int ni = 0; ni < 8; ++ni) {
                const int g = ni >> 1, lo = ni & 1, idx = nh * 8 + ni;
                mma16816(sacc[idx], qh, kf[g][lo], kf[g][lo + 2]);
                mma16816(sacc[idx], ql, kf[g][lo], kf[g][lo + 2]);
            }
        }
    }

    // ---- mask + warp-local softmax ----
    if (any_mask) {
#pragma unroll
        for (int ni = 0; ni < 16; ++ni) {
            const uint32_t w = mb[ni >> 2];
            const int b0 = (ni & 3) * 8 + (lane & 3) * 2;
            if ((w >> b0) & 1)       { sacc[ni][0] = -10000.0f; sacc[ni][2] = -10000.0f; }
            if ((w >> (b0 + 1)) & 1) { sacc[ni][1] = -10000.0f; sacc[ni][3] = -10000.0f; }
        }
    }
    float mx0 = -3.0e38f, mx1 = -3.0e38f;
#pragma unroll
    for (int ni = 0; ni < 16; ++ni) {
        mx0 = fmaxf(mx0, fmaxf(sacc[ni][0], sacc[ni][1]));
        mx1 = fmaxf(mx1, fmaxf(sacc[ni][2], sacc[ni][3]));
    }
    mx0 = fmaxf(mx0, __shfl_xor_sync(0xffffffffu, mx0, 1));
    mx0 = fmaxf(mx0, __shfl_xor_sync(0xffffffffu, mx0, 2));
    mx1 = fmaxf(mx1, __shfl_xor_sync(0xffffffffu, mx1, 1));
    mx1 = fmaxf(mx1, __shfl_xor_sync(0xffffffffu, mx1, 2));

    float s0 = 0.0f, s1 = 0.0f;
#pragma unroll
    for (int ni = 0; ni < 16; ++ni) {
        sacc[ni][0] = __expf(sacc[ni][0] - mx0);
        sacc[ni][1] = __expf(sacc[ni][1] - mx0);
        sacc[ni][2] = __expf(sacc[ni][2] - mx1);
        sacc[ni][3] = __expf(sacc[ni][3] - mx1);
        s0 += sacc[ni][0] + sacc[ni][1];
        s1 += sacc[ni][2] + sacc[ni][3];
    }
    s0 += __shfl_xor_sync(0xffffffffu, s0, 1);
    s0 += __shfl_xor_sync(0xffffffffu, s0, 2);
    s1 += __shfl_xor_sync(0xffffffffu, s1, 1);
    s1 += __shfl_xor_sync(0xffffffffu, s1, 2);
    const float inv0 = 1.0f / s0, inv1 = 1.0f / s1;

    // ---- probs (normalized fp32) straight from registers ----
    {
        const int r0 = rw * 16 + (lane >> 2);
        float* pb = probs + (((size_t)h * CDIM + c) * RDIM + r0) * RDIM + (lane & 3) * 2;
#pragma unroll
        for (int ni = 0; ni < 16; ++ni) {
            float2 a; a.x = sacc[ni][0] * inv0; a.y = sacc[ni][1] * inv0;
            float2 b; b.x = sacc[ni][2] * inv1; b.y = sacc[ni][3] * inv1;
            *(float2*)(pb + ni * 8) = a;
            *(float2*)(pb + 8 * RDIM + ni * 8) = b;
        }
    }

    // ---- pack unnormalized P -> fp16 hi/lo A-fragments ----
    uint32_t ph0[16], ph1[16], pl0[16], pl1[16];
#pragma unroll
    for (int ni = 0; ni < 16; ++ni) {
        ph0[ni] = packh(sacc[ni][0], sacc[ni][1]);
        pl0[ni] = packl(sacc[ni][0], sacc[ni][1]);
        ph1[ni] = packh(sacc[ni][2], sacc[ni][3]);
        pl1[ni] = packl(sacc[ni][2], sacc[ni][3]);
    }

    // ---- transpose V [j][d] -> Vt [d][j] into (now free) Q region ----
    __syncthreads();
#pragma unroll
    for (int tl2 = 0; tl2 < 2; ++tl2) {
        const __half* vsrc = (const __half*)(sm + tl2 * ATS + AV);
        __half* vt = (__half*)(sm + tl2 * ATS + AVT);
#pragma unroll
        for (int k = 0; k < 16; ++k) {
            const int idx = t + k * 512;
            const int j = idx >> 6, d = idx & 63;
            vt[d * PVT + j] = vsrc[j * PA + d];
        }
    }
    __syncthreads();

    // ---- ctx = (Ph+Pl) V : warp tile 16(m) x 64(n), k=128, Vt n-major ----
    float cacc[8][4];
#pragma unroll
    for (int ni = 0; ni < 8; ++ni)
#pragma unroll
        for (int e = 0; e < 4; ++e) cacc[ni][e] = 0.0f;

    const uint32_t vb = tb + AVT + (uint32_t)(lrow8 * (PVT * 2));
#pragma unroll
    for (int kb = 0; kb < 8; ++kb) {
        const uint32_t ko = (uint32_t)((kb * 16 + lkoff) * 2);
        const uint32_t a_h[4] = { ph0[2 * kb], ph1[2 * kb], ph0[2 * kb + 1], ph1[2 * kb + 1] };
        const uint32_t a_l[4] = { pl0[2 * kb], pl1[2 * kb], pl0[2 * kb + 1], pl1[2 * kb + 1] };
#pragma unroll
        for (int vh2 = 0; vh2 < 2; ++vh2) {
            uint32_t vf[2][4];
#pragma unroll
            for (int nb8 = 0; nb8 < 2; ++nb8)
                ldmx4(vf[nb8], vb + (uint32_t)((vh2 * 32 + nb8 * 16) * (PVT * 2)) + ko);
#pragma unroll
            for (int nl = 0; nl < 4; ++nl) {
                const int g = nl >> 1, lo = nl & 1, idx = vh2 * 4 + nl;
                mma16816(cacc[idx], a_h, vf[g][lo], vf[g][lo + 2]);
                mma16816(cacc[idx], a_l, vf[g][lo], vf[g][lo + 2]);
            }
        }
    }

    // ---- ctx epilogue (normalize, split, feed out-projection) ----
    {
        const int r0 = rw * 16 + (lane >> 2);
#pragma unroll
        for (int ni = 0; ni < 8; ++ni) {
            const int d = ni * 8 + (lane & 3) * 2;
            const size_t ob0 = ((size_t)r0 * CDIM + c) * EDIM + h * DDIM + d;
            const size_t ob1 = ((size_t)(r0 + 8) * CDIM + c) * EDIM + h * DDIM + d;
            __half hx, lx, hy, ly;
            split2h(cacc[ni][0] * inv0, hx, lx);
            split2h(cacc[ni][1] * inv0, hy, ly);
            *(__half2*)(g_ah + ob0) = __half2(hx, hy);
            *(__half2*)(g_al + ob0) = __half2(lx, ly);
            split2h(cacc[ni][2] * inv1, hx, lx);
            split2h(cacc[ni][3] * inv1, hy, ly);
            *(__half2*)(g_ah + ob1) = __half2(hx, hy);
            *(__half2*)(g_al + ob1) = __half2(lx, ly);
        }
    }
}

// ---------------------------------------------------------------------------
extern "C" void kernel_launch(void* const* d_in, const int* in_sizes, int n_in,
                              void* d_out, int out_size)
{
    const float* x  = (const float*)d_in[0];
    const unsigned char* mask = (const unsigned char*)d_in[2];
    const float* wq = (const float*)d_in[3];
    const float* bq = (const float*)d_in[4];
    const float* wk = (const float*)d_in[5];
    const float* bk = (const float*)d_in[6];
    const float* wv = (const float*)d_in[7];
    const float* bv = (const float*)d_in[8];
    const float* wo = (const float*)d_in[9];
    const float* bo = (const float*)d_in[10];

    float* out   = (float*)d_out;                    // (R, C, 1, E)
    float* probs = out + (size_t)MDIM * EDIM;        // (H, C, 1, R, R)

    const int gemm_smem = 2 * GBUF;                  // 61440
    cudaFuncSetAttribute(gemm_tc, cudaFuncAttributeMaxDynamicSharedMemorySize, gemm_smem);
    cudaFuncSetAttribute(attn_tc, cudaFuncAttributeMaxDynamicSharedMemorySize, ATOT);

    conv_w<<<2304, 1024>>>(wq, wk, wv, wo, bq, bk, bv, bo);
    conv_x<<<9216, 1024>>>(x, MDIM * EDIM / 4);
    gemm_tc<<<dim3(MDIM / 128, 18), 256, gemm_smem>>>(0, 0, out);        // qkv
    attn_tc<<<dim3(CDIM, HDIM / 2), 512, ATOT>>>(mask, probs);
    gemm_tc<<<dim3(MDIM / 128, 6), 256, gemm_smem>>>(3 * EDIM, 1, out);  // out proj
}

// round 9
// speedup vs baseline: 1.8842x; 1.0787x over previous
#include <cuda_runtime.h>
#include <cuda_fp16.h>
#include <cstdint>

#define RDIM 128
#define CDIM 384
#define EDIM 768
#define HDIM 12
#define DDIM 64
#define MDIM (RDIM * CDIM)   // 49152

// GEMM tiling: CTA 128x128, 8 warps (2x4), warp tile 64x32, BK=32
#define BK 32
#define GP 40                              // fp16/row (80B), conflict-free
#define MTX (128 * GP * 2)                 // 10240 B per matrix tile
#define GBUF (3 * MTX)                     // 30720 (Ah, Al, B)

// attention smem map (per-tile, bytes): qh, ql, k, v each 128x64 fp16 @ pitch PA
#define PA 72      // rows: 144B
#define PVT 136    // vt rows: 272B
#define AQH 0
#define AQL 18432
#define AK  36864
#define AV  55296
#define ATS 73728              /* per-tile stride */
#define AVT 0                  /* Vt (64 x PVT = 34816 B) aliases QH/QL after S */
#define ABM (2 * ATS)          /* mask bitmap (4 x u32) */
#define ATOT (ABM + 16)

// ---------------- device scratch (allocation-free rule) ----------------
__device__ __half g_ah[(size_t)MDIM * EDIM];     // A hi (x, then ctx)
__device__ __half g_al[(size_t)MDIM * EDIM];     // A lo
__device__ __half g_w[(size_t)4 * EDIM * EDIM];  // packed wq|wk|wv|wo (single fp16)
__device__ float g_bias[4 * EDIM];
__device__ __half g_qh[(size_t)MDIM * EDIM];     // [c][h][i][d] q hi
__device__ __half g_ql[(size_t)MDIM * EDIM];     // q lo
__device__ __half g_k[(size_t)MDIM * EDIM];      // k single
__device__ __half g_v[(size_t)MDIM * EDIM];      // v single

// ---------------- helpers ----------------
__device__ __forceinline__ uint32_t smem_to_u32(const void* p) {
    uint32_t a;
    asm("{ .reg .u64 t; cvta.to.shared.u64 t, %1; cvt.u32.u64 %0, t; }"
        : "=r"(a) : "l"(p));
    return a;
}
__device__ __forceinline__ void cp16(uint32_t dst, const void* src) {
    asm volatile("cp.async.cg.shared.global [%0], [%1], 16;"
                 :: "r"(dst), "l"(src) : "memory");
}
__device__ __forceinline__ void cp_commit() {
    asm volatile("cp.async.commit_group;" ::: "memory");
}
__device__ __forceinline__ void cp_wait0() {
    asm volatile("cp.async.wait_group 0;" ::: "memory");
}
__device__ __forceinline__ void ldmx4(uint32_t (&r)[4], uint32_t addr) {
    asm volatile("ldmatrix.sync.aligned.m8n8.x4.shared.b16 {%0,%1,%2,%3}, [%4];"
                 : "=r"(r[0]), "=r"(r[1]), "=r"(r[2]), "=r"(r[3]) : "r"(addr));
}
__device__ __forceinline__ void mma16816(float (&d)[4], const uint32_t (&a)[4],
                                         uint32_t b0, uint32_t b1) {
    asm volatile(
        "mma.sync.aligned.m16n8k16.row.col.f32.f16.f16.f32 "
        "{%0,%1,%2,%3}, {%4,%5,%6,%7}, {%8,%9}, {%0,%1,%2,%3};"
        : "+f"(d[0]), "+f"(d[1]), "+f"(d[2]), "+f"(d[3])
        : "r"(a[0]), "r"(a[1]), "r"(a[2]), "r"(a[3]), "r"(b0), "r"(b1));
}
__device__ __forceinline__ void split2h(float f, __half& h, __half& l) {
    h = __float2half_rn(f);
    l = __float2half_rn(f - __half2float(h));
}
__device__ __forceinline__ uint32_t packh(float a, float b) {
    __half2 p(__float2half_rn(a), __float2half_rn(b));
    return *(uint32_t*)&p;
}
__device__ __forceinline__ uint32_t packl(float a, float b) {
    __half ha = __float2half_rn(a), hb = __float2half_rn(b);
    __half2 p(__float2half_rn(a - __half2float(ha)),
              __float2half_rn(b - __half2float(hb)));
    return *(uint32_t*)&p;
}

// ---------------- conversion kernels ----------------
__global__ void conv_x(const float* __restrict__ src, int n4) {
    int i = blockIdx.x * blockDim.x + threadIdx.x;
    if (i >= n4) return;
    float4 v = ((const float4*)src)[i];
    __half h0, h1, h2, h3, l0, l1, l2, l3;
    split2h(v.x, h0, l0); split2h(v.y, h1, l1);
    split2h(v.z, h2, l2); split2h(v.w, h3, l3);
    size_t o = (size_t)i * 4;
    *(__half2*)(g_ah + o)     = __half2(h0, h1);
    *(__half2*)(g_ah + o + 2) = __half2(h2, h3);
    *(__half2*)(g_al + o)     = __half2(l0, l1);
    *(__half2*)(g_al + o + 2) = __half2(l2, l3);
}

__global__ void conv_w(const float* __restrict__ wq, const float* __restrict__ wk,
                       const float* __restrict__ wv, const float* __restrict__ wo,
                       const float* __restrict__ bq, const float* __restrict__ bk,
                       const float* __restrict__ bv, const float* __restrict__ bo)
{
    const size_t WSZ = (size_t)EDIM * EDIM;
    size_t i = (size_t)blockIdx.x * blockDim.x + threadIdx.x;
    int sel = (int)(i / WSZ);
    size_t off = i - (size_t)sel * WSZ;
    const float* w = (sel == 0) ? wq : (sel == 1) ? wk : (sel == 2) ? wv : wo;
    g_w[i] = __float2half_rn(w[off]);
    if (i < 4 * EDIM) {
        int s = (int)(i / EDIM), r = (int)(i % EDIM);
        const float* b = (s == 0) ? bq : (s == 1) ? bk : (s == 2) ? bv : bo;
        g_bias[i] = b[r];
    }
}

// ---------------- fp16 HMMA GEMM (ntile-fastest grid; K/V single-product) ----------------
// grid = (n_tiles, m_tiles): blockIdx.x = ntile (fastest -> W + A-slice L2 resident)
__global__ __launch_bounds__(256, 2)
void gemm_tc(int n_off, int mode, float* __restrict__ outp)
{
    extern __shared__ char smdyn[];
    const uint32_t smb = smem_to_u32(smdyn);
    const int t = threadIdx.x;
    const int wid = t >> 5, lane = t & 31;
    const int wm = wid & 1, wn = wid >> 1;           // 2x4 warp grid
    const int bm = blockIdx.y * 128;
    const int nb = n_off + blockIdx.x * 128;
    // split A only where the extra precision survives: q columns + out-proj
    const bool dosplit = (mode != 0) || ((int)blockIdx.x < 6);

    const __half* srcs[3] = {
        g_ah + (size_t)bm * EDIM, g_al + (size_t)bm * EDIM,
        g_w + (size_t)nb * EDIM };

    float acc[4][4][4];
#pragma unroll
    for (int mi = 0; mi < 4; ++mi)
#pragma unroll
        for (int ni = 0; ni < 4; ++ni)
#pragma unroll
            for (int e = 0; e < 4; ++e) acc[mi][ni][e] = 0.0f;

    const int lrow8 = (lane & 7) + ((lane >> 3) & 1) * 8;
    const int lkoff = (lane >> 4) * 8;

    // prefetch chunk 0: per matrix 512 x 16B; 256 threads x 2
    {
#pragma unroll
        for (int kk = 0; kk < 2; ++kk) {
            const int id = t + kk * 256;
            const int r = id >> 2, cl = id & 3;
            const uint32_t d = smb + (uint32_t)(r * (GP * 2) + cl * 16);
            const int s = r * EDIM + cl * 8;
            cp16(d, srcs[0] + s);
            if (dosplit) cp16(d + MTX, srcs[1] + s);
            cp16(d + 2 * MTX, srcs[2] + s);
        }
        cp_commit();
    }

    const int NC = EDIM / BK;  // 24
#pragma unroll 1
    for (int ch = 0; ch < NC; ++ch) {
        cp_wait0();
        __syncthreads();
        if (ch + 1 < NC) {
            const uint32_t bufn = ((ch + 1) & 1) * GBUF;
#pragma unroll
            for (int kk = 0; kk < 2; ++kk) {
                const int id = t + kk * 256;
                const int r = id >> 2, cl = id & 3;
                const uint32_t d = smb + bufn + (uint32_t)(r * (GP * 2) + cl * 16);
                const int s = r * EDIM + (ch + 1) * BK + cl * 8;
                cp16(d, srcs[0] + s);
                if (dosplit) cp16(d + MTX, srcs[1] + s);
                cp16(d + 2 * MTX, srcs[2] + s);
            }
            cp_commit();
        }
        const uint32_t buf = smb + (ch & 1) * GBUF;
        const uint32_t aA = buf + (uint32_t)((wm * 64 + lrow8) * (GP * 2));
        const uint32_t aB = buf + 2 * MTX + (uint32_t)((wn * 32 + lrow8) * (GP * 2));
#pragma unroll
        for (int ks = 0; ks < 2; ++ks) {
            const uint32_t kbyte = (uint32_t)((ks * 16 + lkoff) * 2);
            uint32_t bfr[2][4];
#pragma unroll
            for (int ng = 0; ng < 2; ++ng)
                ldmx4(bfr[ng], aB + (uint32_t)(ng * 16 * GP * 2) + kbyte);
#pragma unroll
            for (int mi = 0; mi < 4; ++mi) {
                uint32_t ah[4];
                ldmx4(ah, aA + (uint32_t)(mi * 16 * GP * 2) + kbyte);
#pragma unroll
                for (int ni = 0; ni < 4; ++ni) {
                    const int ng = ni >> 1, lo = ni & 1;
                    mma16816(acc[mi][ni], ah, bfr[ng][lo], bfr[ng][lo + 2]);
                }
                if (dosplit) {
                    uint32_t al[4];
                    ldmx4(al, aA + MTX + (uint32_t)(mi * 16 * GP * 2) + kbyte);
#pragma unroll
                    for (int ni = 0; ni < 4; ++ni) {
                        const int ng = ni >> 1, lo = ni & 1;
                        mma16816(acc[mi][ni], al, bfr[ng][lo], bfr[ng][lo + 2]);
                    }
                }
            }
        }
    }

    // epilogue
    const int r0 = bm + wm * 64 + (lane >> 2);
    const int cbase = nb + wn * 32 + (lane & 3) * 2;
#pragma unroll
    for (int mi = 0; mi < 4; ++mi) {
#pragma unroll
        for (int half = 0; half < 2; ++half) {
            const int m = r0 + mi * 16 + half * 8;
            const int i_ = m / CDIM, c_ = m % CDIM;
#pragma unroll
            for (int ni = 0; ni < 4; ++ni) {
                const int ng = cbase + ni * 8;
                float ox = acc[mi][ni][half * 2 + 0] + g_bias[ng + 0];
                float oy = acc[mi][ni][half * 2 + 1] + g_bias[ng + 1];
                if (mode == 0) {
                    const int sel = ng / EDIM, f = ng % EDIM, h = f >> 6, d = f & 63;
                    const size_t off = (((size_t)c_ * HDIM + h) * RDIM + i_) * DDIM + d;
                    if (sel == 0) {          // q: scaled, split hi/lo
                        ox *= 0.125f; oy *= 0.125f;
                        __half hx, lx, hy, ly;
                        split2h(ox, hx, lx); split2h(oy, hy, ly);
                        *(__half2*)(g_qh + off) = __half2(hx, hy);
                        *(__half2*)(g_ql + off) = __half2(lx, ly);
                    } else {                 // k, v: single fp16
                        __half* dst = (sel == 1) ? g_k : g_v;
                        *(__half2*)(dst + off) =
                            __half2(__float2half_rn(ox), __float2half_rn(oy));
                    }
                } else {
                    float2 o; o.x = ox; o.y = oy;
                    *(float2*)(outp + (size_t)m * EDIM + (ng - 3 * EDIM)) = o;
                }
            }
        }
    }
}

// ---------------- register-flash fp16 HMMA attention (2 heads/CTA) ----------------
__global__ __launch_bounds__(512, 1)
void attn_tc(const unsigned char* __restrict__ mask, float* __restrict__ probs)
{
    extern __shared__ char sm[];
    const uint32_t smb = smem_to_u32(sm);
    const int c = blockIdx.x, hp = blockIdx.y;
    const int t = threadIdx.x, wid = t >> 5, lane = t & 31;

    // ---- loads: qh, ql, k, v for both heads, all [128][64] fp16 ----
#pragma unroll
    for (int tl2 = 0; tl2 < 2; ++tl2) {
        const size_t gb = ((size_t)c * HDIM + (hp * 2 + tl2)) * (RDIM * DDIM);
        const __half* sq[4] = { g_qh + gb, g_ql + gb, g_k + gb, g_v + gb };
        const uint32_t qo[4] = { AQH, AQL, AK, AV };
#pragma unroll
        for (int m = 0; m < 4; ++m)
#pragma unroll
            for (int k = 0; k < 2; ++k) {
                const int id = t + k * 512;
                const int r = id >> 3, cl = id & 7;
                cp16(smb + tl2 * ATS + qo[m] + (uint32_t)(r * (PA * 2) + cl * 16),
                     sq[m] + (size_t)r * DDIM + cl * 8);
            }
    }
    cp_commit();

    // mask bitmap
    uint32_t* bmw = (uint32_t*)(sm + ABM);
    if (t < 4) bmw[t] = 0;
    __syncthreads();
    if (t < RDIM && mask[(size_t)t * CDIM + c]) atomicOr(&bmw[t >> 5], 1u << (t & 31));
    cp_wait0();
    __syncthreads();
    const uint32_t mb[4] = { bmw[0], bmw[1], bmw[2], bmw[3] };
    const bool any_mask = (mb[0] | mb[1] | mb[2] | mb[3]) != 0;

    const int tl = wid >> 3, rw = wid & 7;
    const int h = hp * 2 + tl;
    const uint32_t tb = smb + tl * ATS;
    const int lrow8 = (lane & 7) + ((lane >> 3) & 1) * 8;
    const int lkoff = (lane >> 4) * 8;

    // ---- S = (Qh+Ql) K^T : warp tile 16(m) x 128(n), k=64 ----
    float sacc[16][4];
#pragma unroll
    for (int ni = 0; ni < 16; ++ni)
#pragma unroll
        for (int e = 0; e < 4; ++e) sacc[ni][e] = 0.0f;

    const uint32_t qb = tb + AQH + (uint32_t)((rw * 16 + lrow8) * (PA * 2));
    const uint32_t kbse = tb + AK + (uint32_t)(lrow8 * (PA * 2));
#pragma unroll
    for (int ks = 0; ks < 4; ++ks) {
        const uint32_t ko = (uint32_t)((ks * 16 + lkoff) * 2);
        uint32_t qh[4], ql[4];
        ldmx4(qh, qb + ko);
        ldmx4(ql, qb + 18432u + ko);
#pragma unroll
        for (int nh = 0; nh < 2; ++nh) {
            uint32_t kf[4][4];
#pragma unroll
            for (int nb8 = 0; nb8 < 4; ++nb8)
                ldmx4(kf[nb8], kbse + (uint32_t)((nh * 64 + nb8 * 16) * (PA * 2)) + ko);
#pragma unroll
            for (int ni = 0; ni < 8; ++ni) {
                const int g = ni >> 1, lo = ni & 1, idx = nh * 8 + ni;
                mma16816(sacc[idx], qh, kf[g][lo], kf[g][lo + 2]);
                mma16816(sacc[idx], ql, kf[g][lo], kf[g][lo + 2]);
            }
        }
    }

    // ---- mask + warp-local softmax ----
    if (any_mask) {
#pragma unroll
        for (int ni = 0; ni < 16; ++ni) {
            const uint32_t w = mb[ni >> 2];
            const int b0 = (ni & 3) * 8 + (lane & 3) * 2;
            if ((w >> b0) & 1)       { sacc[ni][0] = -10000.0f; sacc[ni][2] = -10000.0f; }
            if ((w >> (b0 + 1)) & 1) { sacc[ni][1] = -10000.0f; sacc[ni][3] = -10000.0f; }
        }
    }
    float mx0 = -3.0e38f, mx1 = -3.0e38f;
#pragma unroll
    for (int ni = 0; ni < 16; ++ni) {
        mx0 = fmaxf(mx0, fmaxf(sacc[ni][0], sacc[ni][1]));
        mx1 = fmaxf(mx1, fmaxf(sacc[ni][2], sacc[ni][3]));
    }
    mx0 = fmaxf(mx0, __shfl_xor_sync(0xffffffffu, mx0, 1));
    mx0 = fmaxf(mx0, __shfl_xor_sync(0xffffffffu, mx0, 2));
    mx1 = fmaxf(mx1, __shfl_xor_sync(0xffffffffu, mx1, 1));
    mx1 = fmaxf(mx1, __shfl_xor_sync(0xffffffffu, mx1, 2));

    float s0 = 0.0f, s1 = 0.0f;
#pragma unroll
    for (int ni = 0; ni < 16; ++ni) {
        sacc[ni][0] = __expf(sacc[ni][0] - mx0);
        sacc[ni][1] = __expf(sacc[ni][1] - mx0);
        sacc[ni][2] = __expf(sacc[ni][2] - mx1);
        sacc[ni][3] = __expf(sacc[ni][3] - mx1);
        s0 += sacc[ni][0] + sacc[ni][1];
        s1 += sacc[ni][2] + sacc[ni][3];
    }
    s0 += __shfl_xor_sync(0xffffffffu, s0, 1);
    s0 += __shfl_xor_sync(0xffffffffu, s0, 2);
    s1 += __shfl_xor_sync(0xffffffffu, s1, 1);
    s1 += __shfl_xor_sync(0xffffffffu, s1, 2);
    const float inv0 = 1.0f / s0, inv1 = 1.0f / s1;

    // ---- probs (normalized fp32) straight from registers ----
    {
        const int r0 = rw * 16 + (lane >> 2);
        float* pb = probs + (((size_t)h * CDIM + c) * RDIM + r0) * RDIM + (lane & 3) * 2;
#pragma unroll
        for (int ni = 0; ni < 16; ++ni) {
            float2 a; a.x = sacc[ni][0] * inv0; a.y = sacc[ni][1] * inv0;
            float2 b; b.x = sacc[ni][2] * inv1; b.y = sacc[ni][3] * inv1;
            *(float2*)(pb + ni * 8) = a;
            *(float2*)(pb + 8 * RDIM + ni * 8) = b;
        }
    }

    // ---- pack unnormalized P -> fp16 hi/lo A-fragments ----
    uint32_t ph0[16], ph1[16], pl0[16], pl1[16];
#pragma unroll
    for (int ni = 0; ni < 16; ++ni) {
        ph0[ni] = packh(sacc[ni][0], sacc[ni][1]);
        pl0[ni] = packl(sacc[ni][0], sacc[ni][1]);
        ph1[ni] = packh(sacc[ni][2], sacc[ni][3]);
        pl1[ni] = packl(sacc[ni][2], sacc[ni][3]);
    }

    // ---- transpose V [j][d] -> Vt [d][j] into (now free) Q region ----
    __syncthreads();
#pragma unroll
    for (int tl2 = 0; tl2 < 2; ++tl2) {
        const __half* vsrc = (const __half*)(sm + tl2 * ATS + AV);
        __half* vt = (__half*)(sm + tl2 * ATS + AVT);
#pragma unroll
        for (int k = 0; k < 16; ++k) {
            const int idx = t + k * 512;
            const int j = idx >> 6, d = idx & 63;
            vt[d * PVT + j] = vsrc[j * PA + d];
        }
    }
    __syncthreads();

    // ---- ctx = (Ph+Pl) V : warp tile 16(m) x 64(n), k=128, Vt n-major ----
    float cacc[8][4];
#pragma unroll
    for (int ni = 0; ni < 8; ++ni)
#pragma unroll
        for (int e = 0; e < 4; ++e) cacc[ni][e] = 0.0f;

    const uint32_t vb = tb + AVT + (uint32_t)(lrow8 * (PVT * 2));
#pragma unroll
    for (int kb = 0; kb < 8; ++kb) {
        const uint32_t ko = (uint32_t)((kb * 16 + lkoff) * 2);
        const uint32_t a_h[4] = { ph0[2 * kb], ph1[2 * kb], ph0[2 * kb + 1], ph1[2 * kb + 1] };
        const uint32_t a_l[4] = { pl0[2 * kb], pl1[2 * kb], pl0[2 * kb + 1], pl1[2 * kb + 1] };
#pragma unroll
        for (int vh2 = 0; vh2 < 2; ++vh2) {
            uint32_t vf[2][4];
#pragma unroll
            for (int nb8 = 0; nb8 < 2; ++nb8)
                ldmx4(vf[nb8], vb + (uint32_t)((vh2 * 32 + nb8 * 16) * (PVT * 2)) + ko);
#pragma unroll
            for (int nl = 0; nl < 4; ++nl) {
                const int g = nl >> 1, lo = nl & 1, idx = vh2 * 4 + nl;
                mma16816(cacc[idx], a_h, vf[g][lo], vf[g][lo + 2]);
                mma16816(cacc[idx], a_l, vf[g][lo], vf[g][lo + 2]);
            }
        }
    }

    // ---- ctx epilogue (normalize, split, feed out-projection) ----
    {
        const int r0 = rw * 16 + (lane >> 2);
#pragma unroll
        for (int ni = 0; ni < 8; ++ni) {
            const int d = ni * 8 + (lane & 3) * 2;
            const size_t ob0 = ((size_t)r0 * CDIM + c) * EDIM + h * DDIM + d;
            const size_t ob1 = ((size_t)(r0 + 8) * CDIM + c) * EDIM + h * DDIM + d;
            __half hx, lx, hy, ly;
            split2h(cacc[ni][0] * inv0, hx, lx);
            split2h(cacc[ni][1] * inv0, hy, ly);
            *(__half2*)(g_ah + ob0) = __half2(hx, hy);
            *(__half2*)(g_al + ob0) = __half2(lx, ly);
            split2h(cacc[ni][2] * inv1, hx, lx);
            split2h(cacc[ni][3] * inv1, hy, ly);
            *(__half2*)(g_ah + ob1) = __half2(hx, hy);
            *(__half2*)(g_al + ob1) = __half2(lx, ly);
        }
    }
}

// ---------------------------------------------------------------------------
extern "C" void kernel_launch(void* const* d_in, const int* in_sizes, int n_in,
                              void* d_out, int out_size)
{
    const float* x  = (const float*)d_in[0];
    const unsigned char* mask = (const unsigned char*)d_in[2];
    const float* wq = (const float*)d_in[3];
    const float* bq = (const float*)d_in[4];
    const float* wk = (const float*)d_in[5];
    const float* bk = (const float*)d_in[6];
    const float* wv = (const float*)d_in[7];
    const float* bv = (const float*)d_in[8];
    const float* wo = (const float*)d_in[9];
    const float* bo = (const float*)d_in[10];

    float* out   = (float*)d_out;                    // (R, C, 1, E)
    float* probs = out + (size_t)MDIM * EDIM;        // (H, C, 1, R, R)

    const int gemm_smem = 2 * GBUF;                  // 61440
    cudaFuncSetAttribute(gemm_tc, cudaFuncAttributeMaxDynamicSharedMemorySize, gemm_smem);
    cudaFuncSetAttribute(attn_tc, cudaFuncAttributeMaxDynamicSharedMemorySize, ATOT);

    conv_w<<<2304, 1024>>>(wq, wk, wv, wo, bq, bk, bv, bo);
    conv_x<<<9216, 1024>>>(x, MDIM * EDIM / 4);
    gemm_tc<<<dim3(18, MDIM / 128), 256, gemm_smem>>>(0, 0, out);        // qkv
    attn_tc<<<dim3(CDIM, HDIM / 2), 512, ATOT>>>(mask, probs);
    gemm_tc<<<dim3(6, MDIM / 128), 256, gemm_smem>>>(3 * EDIM, 1, out);  // out proj
}

// round 10
// speedup vs baseline: 2.0420x; 1.0838x over previous
#include <cuda_runtime.h>
#include <cuda_fp16.h>
#include <cstdint>

#define RDIM 128
#define CDIM 384
#define EDIM 768
#define HDIM 12
#define DDIM 64
#define MDIM (RDIM * CDIM)   // 49152

// GEMM tiling: CTA 128x128, 8 warps (2x4), warp tile 64x32, BK=32
#define BK 32
#define GP 40                              // fp16/row (80B), conflict-free
#define MTX (128 * GP * 2)                 // 10240 B per matrix tile
#define GBUF (3 * MTX)                     // 30720 (Ah, Al, B)

// attention smem map (per-tile, bytes): qh, ql, k, v each 128x64 fp16 @ pitch PA
#define PA 72      // rows: 144B
#define PVT 136    // vt rows: 272B
#define AQH 0
#define AQL 18432
#define AK  36864
#define AV  55296
#define ATS 73728              /* per-tile stride */
#define AVT 0                  /* Vt (64 x PVT = 34816 B) aliases QH/QL after S */
#define ABM (2 * ATS)          /* mask bitmap (4 x u32) */
#define ATOT (ABM + 16)

// ---------------- device scratch (allocation-free rule) ----------------
__device__ __half g_ah[(size_t)MDIM * EDIM];     // A hi (x, then ctx single-fp16)
__device__ __half g_al[(size_t)MDIM * EDIM];     // A lo (x only)
__device__ __half g_w[(size_t)4 * EDIM * EDIM];  // packed wq|wk|wv|wo (single fp16)
__device__ float g_bias[4 * EDIM];
__device__ __half g_qh[(size_t)MDIM * EDIM];     // [c][h][i][d] q hi
__device__ __half g_ql[(size_t)MDIM * EDIM];     // q lo
__device__ __half g_k[(size_t)MDIM * EDIM];      // k single
__device__ __half g_v[(size_t)MDIM * EDIM];      // v single

// ---------------- helpers ----------------
__device__ __forceinline__ uint32_t smem_to_u32(const void* p) {
    uint32_t a;
    asm("{ .reg .u64 t; cvta.to.shared.u64 t, %1; cvt.u32.u64 %0, t; }"
        : "=r"(a) : "l"(p));
    return a;
}
__device__ __forceinline__ void cp16(uint32_t dst, const void* src) {
    asm volatile("cp.async.cg.shared.global [%0], [%1], 16;"
                 :: "r"(dst), "l"(src) : "memory");
}
__device__ __forceinline__ void cp_commit() {
    asm volatile("cp.async.commit_group;" ::: "memory");
}
__device__ __forceinline__ void cp_wait0() {
    asm volatile("cp.async.wait_group 0;" ::: "memory");
}
__device__ __forceinline__ void ldmx4(uint32_t (&r)[4], uint32_t addr) {
    asm volatile("ldmatrix.sync.aligned.m8n8.x4.shared.b16 {%0,%1,%2,%3}, [%4];"
                 : "=r"(r[0]), "=r"(r[1]), "=r"(r[2]), "=r"(r[3]) : "r"(addr));
}
__device__ __forceinline__ void mma16816(float (&d)[4], const uint32_t (&a)[4],
                                         uint32_t b0, uint32_t b1) {
    asm volatile(
        "mma.sync.aligned.m16n8k16.row.col.f32.f16.f16.f32 "
        "{%0,%1,%2,%3}, {%4,%5,%6,%7}, {%8,%9}, {%0,%1,%2,%3};"
        : "+f"(d[0]), "+f"(d[1]), "+f"(d[2]), "+f"(d[3])
        : "r"(a[0]), "r"(a[1]), "r"(a[2]), "r"(a[3]), "r"(b0), "r"(b1));
}
__device__ __forceinline__ void split2h(float f, __half& h, __half& l) {
    h = __float2half_rn(f);
    l = __float2half_rn(f - __half2float(h));
}
__device__ __forceinline__ uint32_t packh(float a, float b) {
    __half2 p(__float2half_rn(a), __float2half_rn(b));
    return *(uint32_t*)&p;
}
__device__ __forceinline__ uint32_t packl(float a, float b) {
    __half ha = __float2half_rn(a), hb = __float2half_rn(b);
    __half2 p(__float2half_rn(a - __half2float(ha)),
              __float2half_rn(b - __half2float(hb)));
    return *(uint32_t*)&p;
}

// ---------------- conversion kernels ----------------
__global__ void conv_x(const float* __restrict__ src, int n4) {
    int i = blockIdx.x * blockDim.x + threadIdx.x;
    if (i >= n4) return;
    float4 v = ((const float4*)src)[i];
    __half h0, h1, h2, h3, l0, l1, l2, l3;
    split2h(v.x, h0, l0); split2h(v.y, h1, l1);
    split2h(v.z, h2, l2); split2h(v.w, h3, l3);
    size_t o = (size_t)i * 4;
    *(__half2*)(g_ah + o)     = __half2(h0, h1);
    *(__half2*)(g_ah + o + 2) = __half2(h2, h3);
    *(__half2*)(g_al + o)     = __half2(l0, l1);
    *(__half2*)(g_al + o + 2) = __half2(l2, l3);
}

__global__ void conv_w(const float* __restrict__ wq, const float* __restrict__ wk,
                       const float* __restrict__ wv, const float* __restrict__ wo,
                       const float* __restrict__ bq, const float* __restrict__ bk,
                       const float* __restrict__ bv, const float* __restrict__ bo)
{
    const size_t WSZ = (size_t)EDIM * EDIM;
    size_t i = (size_t)blockIdx.x * blockDim.x + threadIdx.x;
    int sel = (int)(i / WSZ);
    size_t off = i - (size_t)sel * WSZ;
    const float* w = (sel == 0) ? wq : (sel == 1) ? wk : (sel == 2) ? wv : wo;
    g_w[i] = __float2half_rn(w[off]);
    if (i < 4 * EDIM) {
        int s = (int)(i / EDIM), r = (int)(i % EDIM);
        const float* b = (s == 0) ? bq : (s == 1) ? bk : (s == 2) ? bv : bo;
        g_bias[i] = b[r];
    }
}

// ---------------- fp16 HMMA GEMM (ntile-fastest grid) ----------------
// grid = (n_tiles, m_tiles). A-split only for q columns (qkv mode, ntile<6).
__global__ __launch_bounds__(256, 2)
void gemm_tc(int n_off, int mode, float* __restrict__ outp)
{
    extern __shared__ char smdyn[];
    const uint32_t smb = smem_to_u32(smdyn);
    const int t = threadIdx.x;
    const int wid = t >> 5, lane = t & 31;
    const int wm = wid & 1, wn = wid >> 1;           // 2x4 warp grid
    const int bm = blockIdx.y * 128;
    const int nb = n_off + blockIdx.x * 128;
    // split A only where the extra precision survives: q columns (qkv mode)
    const bool dosplit = (mode == 0) && ((int)blockIdx.x < 6);

    const __half* srcs[3] = {
        g_ah + (size_t)bm * EDIM, g_al + (size_t)bm * EDIM,
        g_w + (size_t)nb * EDIM };

    float acc[4][4][4];
#pragma unroll
    for (int mi = 0; mi < 4; ++mi)
#pragma unroll
        for (int ni = 0; ni < 4; ++ni)
#pragma unroll
            for (int e = 0; e < 4; ++e) acc[mi][ni][e] = 0.0f;

    const int lrow8 = (lane & 7) + ((lane >> 3) & 1) * 8;
    const int lkoff = (lane >> 4) * 8;

    // prefetch chunk 0: per matrix 512 x 16B; 256 threads x 2
    {
#pragma unroll
        for (int kk = 0; kk < 2; ++kk) {
            const int id = t + kk * 256;
            const int r = id >> 2, cl = id & 3;
            const uint32_t d = smb + (uint32_t)(r * (GP * 2) + cl * 16);
            const int s = r * EDIM + cl * 8;
            cp16(d, srcs[0] + s);
            if (dosplit) cp16(d + MTX, srcs[1] + s);
            cp16(d + 2 * MTX, srcs[2] + s);
        }
        cp_commit();
    }

    const int NC = EDIM / BK;  // 24
#pragma unroll 1
    for (int ch = 0; ch < NC; ++ch) {
        cp_wait0();
        __syncthreads();
        if (ch + 1 < NC) {
            const uint32_t bufn = ((ch + 1) & 1) * GBUF;
#pragma unroll
            for (int kk = 0; kk < 2; ++kk) {
                const int id = t + kk * 256;
                const int r = id >> 2, cl = id & 3;
                const uint32_t d = smb + bufn + (uint32_t)(r * (GP * 2) + cl * 16);
                const int s = r * EDIM + (ch + 1) * BK + cl * 8;
                cp16(d, srcs[0] + s);
                if (dosplit) cp16(d + MTX, srcs[1] + s);
                cp16(d + 2 * MTX, srcs[2] + s);
            }
            cp_commit();
        }
        const uint32_t buf = smb + (ch & 1) * GBUF;
        const uint32_t aA = buf + (uint32_t)((wm * 64 + lrow8) * (GP * 2));
        const uint32_t aB = buf + 2 * MTX + (uint32_t)((wn * 32 + lrow8) * (GP * 2));
#pragma unroll
        for (int ks = 0; ks < 2; ++ks) {
            const uint32_t kbyte = (uint32_t)((ks * 16 + lkoff) * 2);
            uint32_t bfr[2][4];
#pragma unroll
            for (int ng = 0; ng < 2; ++ng)
                ldmx4(bfr[ng], aB + (uint32_t)(ng * 16 * GP * 2) + kbyte);
#pragma unroll
            for (int mi = 0; mi < 4; ++mi) {
                uint32_t ah[4];
                ldmx4(ah, aA + (uint32_t)(mi * 16 * GP * 2) + kbyte);
#pragma unroll
                for (int ni = 0; ni < 4; ++ni) {
                    const int ng = ni >> 1, lo = ni & 1;
                    mma16816(acc[mi][ni], ah, bfr[ng][lo], bfr[ng][lo + 2]);
                }
                if (dosplit) {
                    uint32_t al[4];
                    ldmx4(al, aA + MTX + (uint32_t)(mi * 16 * GP * 2) + kbyte);
#pragma unroll
                    for (int ni = 0; ni < 4; ++ni) {
                        const int ng = ni >> 1, lo = ni & 1;
                        mma16816(acc[mi][ni], al, bfr[ng][lo], bfr[ng][lo + 2]);
                    }
                }
            }
        }
    }

    // epilogue
    const int r0 = bm + wm * 64 + (lane >> 2);
    const int cbase = nb + wn * 32 + (lane & 3) * 2;
#pragma unroll
    for (int mi = 0; mi < 4; ++mi) {
#pragma unroll
        for (int half = 0; half < 2; ++half) {
            const int m = r0 + mi * 16 + half * 8;
            const int i_ = m / CDIM, c_ = m % CDIM;
#pragma unroll
            for (int ni = 0; ni < 4; ++ni) {
                const int ng = cbase + ni * 8;
                float ox = acc[mi][ni][half * 2 + 0] + g_bias[ng + 0];
                float oy = acc[mi][ni][half * 2 + 1] + g_bias[ng + 1];
                if (mode == 0) {
                    const int sel = ng / EDIM, f = ng % EDIM, h = f >> 6, d = f & 63;
                    const size_t off = (((size_t)c_ * HDIM + h) * RDIM + i_) * DDIM + d;
                    if (sel == 0) {          // q: scaled, split hi/lo
                        ox *= 0.125f; oy *= 0.125f;
                        __half hx, lx, hy, ly;
                        split2h(ox, hx, lx); split2h(oy, hy, ly);
                        *(__half2*)(g_qh + off) = __half2(hx, hy);
                        *(__half2*)(g_ql + off) = __half2(lx, ly);
                    } else {                 // k, v: single fp16
                        __half* dst = (sel == 1) ? g_k : g_v;
                        *(__half2*)(dst + off) =
                            __half2(__float2half_rn(ox), __float2half_rn(oy));
                    }
                } else {
                    float2 o; o.x = ox; o.y = oy;
                    *(float2*)(outp + (size_t)m * EDIM + (ng - 3 * EDIM)) = o;
                }
            }
        }
    }
}

// ---------------- register-flash fp16 HMMA attention (2 heads/CTA) ----------------
__global__ __launch_bounds__(512, 1)
void attn_tc(const unsigned char* __restrict__ mask, float* __restrict__ probs)
{
    extern __shared__ char sm[];
    const uint32_t smb = smem_to_u32(sm);
    const int c = blockIdx.x, hp = blockIdx.y;
    const int t = threadIdx.x, wid = t >> 5, lane = t & 31;

    // ---- loads: qh, ql, k, v for both heads, all [128][64] fp16 ----
#pragma unroll
    for (int tl2 = 0; tl2 < 2; ++tl2) {
        const size_t gb = ((size_t)c * HDIM + (hp * 2 + tl2)) * (RDIM * DDIM);
        const __half* sq[4] = { g_qh + gb, g_ql + gb, g_k + gb, g_v + gb };
        const uint32_t qo[4] = { AQH, AQL, AK, AV };
#pragma unroll
        for (int m = 0; m < 4; ++m)
#pragma unroll
            for (int k = 0; k < 2; ++k) {
                const int id = t + k * 512;
                const int r = id >> 3, cl = id & 7;
                cp16(smb + tl2 * ATS + qo[m] + (uint32_t)(r * (PA * 2) + cl * 16),
                     sq[m] + (size_t)r * DDIM + cl * 8);
            }
    }
    cp_commit();

    // mask bitmap
    uint32_t* bmw = (uint32_t*)(sm + ABM);
    if (t < 4) bmw[t] = 0;
    __syncthreads();
    if (t < RDIM && mask[(size_t)t * CDIM + c]) atomicOr(&bmw[t >> 5], 1u << (t & 31));
    cp_wait0();
    __syncthreads();
    const uint32_t mb[4] = { bmw[0], bmw[1], bmw[2], bmw[3] };
    const bool any_mask = (mb[0] | mb[1] | mb[2] | mb[3]) != 0;

    const int tl = wid >> 3, rw = wid & 7;
    const int h = hp * 2 + tl;
    const uint32_t tb = smb + tl * ATS;
    const int lrow8 = (lane & 7) + ((lane >> 3) & 1) * 8;
    const int lkoff = (lane >> 4) * 8;

    // ---- S = (Qh+Ql) K^T : warp tile 16(m) x 128(n), k=64 ----
    float sacc[16][4];
#pragma unroll
    for (int ni = 0; ni < 16; ++ni)
#pragma unroll
        for (int e = 0; e < 4; ++e) sacc[ni][e] = 0.0f;

    const uint32_t qb = tb + AQH + (uint32_t)((rw * 16 + lrow8) * (PA * 2));
    const uint32_t kbse = tb + AK + (uint32_t)(lrow8 * (PA * 2));
#pragma unroll
    for (int ks = 0; ks < 4; ++ks) {
        const uint32_t ko = (uint32_t)((ks * 16 + lkoff) * 2);
        uint32_t qh[4], ql[4];
        ldmx4(qh, qb + ko);
        ldmx4(ql, qb + 18432u + ko);
#pragma unroll
        for (int nh = 0; nh < 2; ++nh) {
            uint32_t kf[4][4];
#pragma unroll
            for (int nb8 = 0; nb8 < 4; ++nb8)
                ldmx4(kf[nb8], kbse + (uint32_t)((nh * 64 + nb8 * 16) * (PA * 2)) + ko);
#pragma unroll
            for (int ni = 0; ni < 8; ++ni) {
                const int g = ni >> 1, lo = ni & 1, idx = nh * 8 + ni;
                mma16816(sacc[idx], qh, kf[g][lo], kf[g][lo + 2]);
                mma16816(sacc[idx], ql, kf[g][lo], kf[g][lo + 2]);
            }
        }
    }

    // ---- mask + warp-local softmax ----
    if (any_mask) {
#pragma unroll
        for (int ni = 0; ni < 16; ++ni) {
            const uint32_t w = mb[ni >> 2];
            const int b0 = (ni & 3) * 8 + (lane & 3) * 2;
            if ((w >> b0) & 1)       { sacc[ni][0] = -10000.0f; sacc[ni][2] = -10000.0f; }
            if ((w >> (b0 + 1)) & 1) { sacc[ni][1] = -10000.0f; sacc[ni][3] = -10000.0f; }
        }
    }
    float mx0 = -3.0e38f, mx1 = -3.0e38f;
#pragma unroll
    for (int ni = 0; ni < 16; ++ni) {
        mx0 = fmaxf(mx0, fmaxf(sacc[ni][0], sacc[ni][1]));
        mx1 = fmaxf(mx1, fmaxf(sacc[ni][2], sacc[ni][3]));
    }
    mx0 = fmaxf(mx0, __shfl_xor_sync(0xffffffffu, mx0, 1));
    mx0 = fmaxf(mx0, __shfl_xor_sync(0xffffffffu, mx0, 2));
    mx1 = fmaxf(mx1, __shfl_xor_sync(0xffffffffu, mx1, 1));
    mx1 = fmaxf(mx1, __shfl_xor_sync(0xffffffffu, mx1, 2));

    float s0 = 0.0f, s1 = 0.0f;
#pragma unroll
    for (int ni = 0; ni < 16; ++ni) {
        sacc[ni][0] = __expf(sacc[ni][0] - mx0);
        sacc[ni][1] = __expf(sacc[ni][1] - mx0);
        sacc[ni][2] = __expf(sacc[ni][2] - mx1);
        sacc[ni][3] = __expf(sacc[ni][3] - mx1);
        s0 += sacc[ni][0] + sacc[ni][1];
        s1 += sacc[ni][2] + sacc[ni][3];
    }
    s0 += __shfl_xor_sync(0xffffffffu, s0, 1);
    s0 += __shfl_xor_sync(0xffffffffu, s0, 2);
    s1 += __shfl_xor_sync(0xffffffffu, s1, 1);
    s1 += __shfl_xor_sync(0xffffffffu, s1, 2);
    const float inv0 = 1.0f / s0, inv1 = 1.0f / s1;

    // ---- probs (normalized fp32) straight from registers ----
    {
        const int r0 = rw * 16 + (lane >> 2);
        float* pb = probs + (((size_t)h * CDIM + c) * RDIM + r0) * RDIM + (lane & 3) * 2;
#pragma unroll
        for (int ni = 0; ni < 16; ++ni) {
            float2 a; a.x = sacc[ni][0] * inv0; a.y = sacc[ni][1] * inv0;
            float2 b; b.x = sacc[ni][2] * inv1; b.y = sacc[ni][3] * inv1;
            *(float2*)(pb + ni * 8) = a;
            *(float2*)(pb + 8 * RDIM + ni * 8) = b;
        }
    }

    // ---- pack unnormalized P -> fp16 hi/lo A-fragments ----
    uint32_t ph0[16], ph1[16], pl0[16], pl1[16];
#pragma unroll
    for (int ni = 0; ni < 16; ++ni) {
        ph0[ni] = packh(sacc[ni][0], sacc[ni][1]);
        pl0[ni] = packl(sacc[ni][0], sacc[ni][1]);
        ph1[ni] = packh(sacc[ni][2], sacc[ni][3]);
        pl1[ni] = packl(sacc[ni][2], sacc[ni][3]);
    }

    // ---- transpose V [j][d] -> Vt [d][j] into (now free) Q region ----
    __syncthreads();
#pragma unroll
    for (int tl2 = 0; tl2 < 2; ++tl2) {
        const __half* vsrc = (const __half*)(sm + tl2 * ATS + AV);
        __half* vt = (__half*)(sm + tl2 * ATS + AVT);
#pragma unroll
        for (int k = 0; k < 16; ++k) {
            const int idx = t + k * 512;
            const int j = idx >> 6, d = idx & 63;
            vt[d * PVT + j] = vsrc[j * PA + d];
        }
    }
    __syncthreads();

    // ---- ctx = (Ph+Pl) V : warp tile 16(m) x 64(n), k=128, Vt n-major ----
    float cacc[8][4];
#pragma unroll
    for (int ni = 0; ni < 8; ++ni)
#pragma unroll
        for (int e = 0; e < 4; ++e) cacc[ni][e] = 0.0f;

    const uint32_t vb = tb + AVT + (uint32_t)(lrow8 * (PVT * 2));
#pragma unroll
    for (int kb = 0; kb < 8; ++kb) {
        const uint32_t ko = (uint32_t)((kb * 16 + lkoff) * 2);
        const uint32_t a_h[4] = { ph0[2 * kb], ph1[2 * kb], ph0[2 * kb + 1], ph1[2 * kb + 1] };
        const uint32_t a_l[4] = { pl0[2 * kb], pl1[2 * kb], pl0[2 * kb + 1], pl1[2 * kb + 1] };
#pragma unroll
        for (int vh2 = 0; vh2 < 2; ++vh2) {
            uint32_t vf[2][4];
#pragma unroll
            for (int nb8 = 0; nb8 < 2; ++nb8)
                ldmx4(vf[nb8], vb + (uint32_t)((vh2 * 32 + nb8 * 16) * (PVT * 2)) + ko);
#pragma unroll
            for (int nl = 0; nl < 4; ++nl) {
                const int g = nl >> 1, lo = nl & 1, idx = vh2 * 4 + nl;
                mma16816(cacc[idx], a_h, vf[g][lo], vf[g][lo + 2]);
                mma16816(cacc[idx], a_l, vf[g][lo], vf[g][lo + 2]);
            }
        }
    }

    // ---- ctx epilogue (normalize, single fp16, feed out-projection) ----
    {
        const int r0 = rw * 16 + (lane >> 2);
#pragma unroll
        for (int ni = 0; ni < 8; ++ni) {
            const int d = ni * 8 + (lane & 3) * 2;
            const size_t ob0 = ((size_t)r0 * CDIM + c) * EDIM + h * DDIM + d;
            const size_t ob1 = ((size_t)(r0 + 8) * CDIM + c) * EDIM + h * DDIM + d;
            *(__half2*)(g_ah + ob0) = __half2(__float2half_rn(cacc[ni][0] * inv0),
                                              __float2half_rn(cacc[ni][1] * inv0));
            *(__half2*)(g_ah + ob1) = __half2(__float2half_rn(cacc[ni][2] * inv1),
                                              __float2half_rn(cacc[ni][3] * inv1));
        }
    }
}

// ---------------------------------------------------------------------------
extern "C" void kernel_launch(void* const* d_in, const int* in_sizes, int n_in,
                              void* d_out, int out_size)
{
    const float* x  = (const float*)d_in[0];
    const unsigned char* mask = (const unsigned char*)d_in[2];
    const float* wq = (const float*)d_in[3];
    const float* bq = (const float*)d_in[4];
    const float* wk = (const float*)d_in[5];
    const float* bk = (const float*)d_in[6];
    const float* wv = (const float*)d_in[7];
    const float* bv = (const float*)d_in[8];
    const float* wo = (const float*)d_in[9];
    const float* bo = (const float*)d_in[10];

    float* out   = (float*)d_out;                    // (R, C, 1, E)
    float* probs = out + (size_t)MDIM * EDIM;        // (H, C, 1, R, R)

    const int gemm_smem = 2 * GBUF;                  // 61440
    cudaFuncSetAttribute(gemm_tc, cudaFuncAttributeMaxDynamicSharedMemorySize, gemm_smem);
    cudaFuncSetAttribute(attn_tc, cudaFuncAttributeMaxDynamicSharedMemorySize, ATOT);

    conv_w<<<2304, 1024>>>(wq, wk, wv, wo, bq, bk, bv, bo);
    conv_x<<<9216, 1024>>>(x, MDIM * EDIM / 4);
    gemm_tc<<<dim3(18, MDIM / 128), 256, gemm_smem>>>(0, 0, out);        // qkv
    attn_tc<<<dim3(CDIM, HDIM / 2), 512, ATOT>>>(mask, probs);
    gemm_tc<<<dim3(6, MDIM / 128), 256, gemm_smem>>>(3 * EDIM, 1, out);  // out proj
}

// round 11
// speedup vs baseline: 2.8046x; 1.3734x over previous
#include <cuda_runtime.h>
#include <cuda_fp16.h>
#include <cstdint>

#define RDIM 128
#define CDIM 384
#define EDIM 768
#define HDIM 12
#define DDIM 64
#define MDIM (RDIM * CDIM)   // 49152

// GEMM tiling: CTA 128x128, 8 warps (2x4), warp tile 64x32, BK=32, single product
#define BK 32
#define GP 40                              // fp16/row (80B), conflict-free
#define MTX (128 * GP * 2)                 // 10240 B per matrix tile
#define GBUF (2 * MTX)                     // 20480 (A, B)

// attention smem map (per-tile, bytes): q, k, v each 128x64 fp16 @ pitch PA
#define PA 72      // rows: 144B
#define PVT 136    // vt rows: 272B
#define AQ  0
#define AK  18432
#define AV  36864
#define ATS 55296              /* per-tile stride */
#define AVT 0                  /* Vt (64 x PVT x 2 = 17408 B) aliases Q after S */
#define ABM (2 * ATS)          /* mask bitmap (4 x u32) */
#define ATOT (ABM + 16)

// ---------------- device scratch (allocation-free rule) ----------------
__device__ __half g_a[(size_t)MDIM * EDIM];      // A (x, then ctx), single fp16
__device__ __half g_w[(size_t)4 * EDIM * EDIM];  // packed wq|wk|wv|wo
__device__ float g_bias[4 * EDIM];
__device__ __half g_q[(size_t)MDIM * EDIM];      // [c][h][i][d]
__device__ __half g_k[(size_t)MDIM * EDIM];
__device__ __half g_v[(size_t)MDIM * EDIM];

// ---------------- helpers ----------------
__device__ __forceinline__ uint32_t smem_to_u32(const void* p) {
    uint32_t a;
    asm("{ .reg .u64 t; cvta.to.shared.u64 t, %1; cvt.u32.u64 %0, t; }"
        : "=r"(a) : "l"(p));
    return a;
}
__device__ __forceinline__ void cp16(uint32_t dst, const void* src) {
    asm volatile("cp.async.cg.shared.global [%0], [%1], 16;"
                 :: "r"(dst), "l"(src) : "memory");
}
__device__ __forceinline__ void cp_commit() {
    asm volatile("cp.async.commit_group;" ::: "memory");
}
__device__ __forceinline__ void cp_wait0() {
    asm volatile("cp.async.wait_group 0;" ::: "memory");
}
__device__ __forceinline__ void ldmx4(uint32_t (&r)[4], uint32_t addr) {
    asm volatile("ldmatrix.sync.aligned.m8n8.x4.shared.b16 {%0,%1,%2,%3}, [%4];"
                 : "=r"(r[0]), "=r"(r[1]), "=r"(r[2]), "=r"(r[3]) : "r"(addr));
}
__device__ __forceinline__ void mma16816(float (&d)[4], const uint32_t (&a)[4],
                                         uint32_t b0, uint32_t b1) {
    asm volatile(
        "mma.sync.aligned.m16n8k16.row.col.f32.f16.f16.f32 "
        "{%0,%1,%2,%3}, {%4,%5,%6,%7}, {%8,%9}, {%0,%1,%2,%3};"
        : "+f"(d[0]), "+f"(d[1]), "+f"(d[2]), "+f"(d[3])
        : "r"(a[0]), "r"(a[1]), "r"(a[2]), "r"(a[3]), "r"(b0), "r"(b1));
}
__device__ __forceinline__ uint32_t packh(float a, float b) {
    __half2 p(__float2half_rn(a), __float2half_rn(b));
    return *(uint32_t*)&p;
}

// ---------------- conversion kernels ----------------
__global__ void conv_x(const float* __restrict__ src, int n4) {
    int i = blockIdx.x * blockDim.x + threadIdx.x;
    if (i >= n4) return;
    float4 v = ((const float4*)src)[i];
    size_t o = (size_t)i * 4;
    *(__half2*)(g_a + o)     = __half2(__float2half_rn(v.x), __float2half_rn(v.y));
    *(__half2*)(g_a + o + 2) = __half2(__float2half_rn(v.z), __float2half_rn(v.w));
}

__global__ void conv_w(const float* __restrict__ wq, const float* __restrict__ wk,
                       const float* __restrict__ wv, const float* __restrict__ wo,
                       const float* __restrict__ bq, const float* __restrict__ bk,
                       const float* __restrict__ bv, const float* __restrict__ bo)
{
    const size_t WSZ = (size_t)EDIM * EDIM;
    size_t i = (size_t)blockIdx.x * blockDim.x + threadIdx.x;
    int sel = (int)(i / WSZ);
    size_t off = i - (size_t)sel * WSZ;
    const float* w = (sel == 0) ? wq : (sel == 1) ? wk : (sel == 2) ? wv : wo;
    g_w[i] = __float2half_rn(w[off]);
    if (i < 4 * EDIM) {
        int s = (int)(i / EDIM), r = (int)(i % EDIM);
        const float* b = (s == 0) ? bq : (s == 1) ? bk : (s == 2) ? bv : bo;
        g_bias[i] = b[r];
    }
}

// ---------------- fp16 HMMA GEMM (single product, ntile-fastest grid) ----------------
__global__ __launch_bounds__(256, 2)
void gemm_tc(int n_off, int mode, float* __restrict__ outp)
{
    extern __shared__ char smdyn[];
    const uint32_t smb = smem_to_u32(smdyn);
    const int t = threadIdx.x;
    const int wid = t >> 5, lane = t & 31;
    const int wm = wid & 1, wn = wid >> 1;           // 2x4 warp grid
    const int bm = blockIdx.y * 128;
    const int nb = n_off + blockIdx.x * 128;

    const __half* srcA = g_a + (size_t)bm * EDIM;
    const __half* srcB = g_w + (size_t)nb * EDIM;

    float acc[4][4][4];
#pragma unroll
    for (int mi = 0; mi < 4; ++mi)
#pragma unroll
        for (int ni = 0; ni < 4; ++ni)
#pragma unroll
            for (int e = 0; e < 4; ++e) acc[mi][ni][e] = 0.0f;

    const int lrow8 = (lane & 7) + ((lane >> 3) & 1) * 8;
    const int lkoff = (lane >> 4) * 8;

    // prefetch chunk 0: per matrix 512 x 16B; 256 threads x 2
    {
#pragma unroll
        for (int kk = 0; kk < 2; ++kk) {
            const int id = t + kk * 256;
            const int r = id >> 2, cl = id & 3;
            const uint32_t d = smb + (uint32_t)(r * (GP * 2) + cl * 16);
            const int s = r * EDIM + cl * 8;
            cp16(d, srcA + s);
            cp16(d + MTX, srcB + s);
        }
        cp_commit();
    }

    const int NC = EDIM / BK;  // 24
#pragma unroll 1
    for (int ch = 0; ch < NC; ++ch) {
        cp_wait0();
        __syncthreads();
        if (ch + 1 < NC) {
            const uint32_t bufn = ((ch + 1) & 1) * GBUF;
#pragma unroll
            for (int kk = 0; kk < 2; ++kk) {
                const int id = t + kk * 256;
                const int r = id >> 2, cl = id & 3;
                const uint32_t d = smb + bufn + (uint32_t)(r * (GP * 2) + cl * 16);
                const int s = r * EDIM + (ch + 1) * BK + cl * 8;
                cp16(d, srcA + s);
                cp16(d + MTX, srcB + s);
            }
            cp_commit();
        }
        const uint32_t buf = smb + (ch & 1) * GBUF;
        const uint32_t aA = buf + (uint32_t)((wm * 64 + lrow8) * (GP * 2));
        const uint32_t aB = buf + MTX + (uint32_t)((wn * 32 + lrow8) * (GP * 2));
#pragma unroll
        for (int ks = 0; ks < 2; ++ks) {
            const uint32_t kbyte = (uint32_t)((ks * 16 + lkoff) * 2);
            uint32_t bfr[2][4];
#pragma unroll
            for (int ng = 0; ng < 2; ++ng)
                ldmx4(bfr[ng], aB + (uint32_t)(ng * 16 * GP * 2) + kbyte);
#pragma unroll
            for (int mi = 0; mi < 4; ++mi) {
                uint32_t af[4];
                ldmx4(af, aA + (uint32_t)(mi * 16 * GP * 2) + kbyte);
#pragma unroll
                for (int ni = 0; ni < 4; ++ni) {
                    const int ng = ni >> 1, lo = ni & 1;
                    mma16816(acc[mi][ni], af, bfr[ng][lo], bfr[ng][lo + 2]);
                }
            }
        }
    }

    // epilogue
    const int r0 = bm + wm * 64 + (lane >> 2);
    const int cbase = nb + wn * 32 + (lane & 3) * 2;
#pragma unroll
    for (int mi = 0; mi < 4; ++mi) {
#pragma unroll
        for (int half = 0; half < 2; ++half) {
            const int m = r0 + mi * 16 + half * 8;
            const int i_ = m / CDIM, c_ = m % CDIM;
#pragma unroll
            for (int ni = 0; ni < 4; ++ni) {
                const int ng = cbase + ni * 8;
                float ox = acc[mi][ni][half * 2 + 0] + g_bias[ng + 0];
                float oy = acc[mi][ni][half * 2 + 1] + g_bias[ng + 1];
                if (mode == 0) {
                    const int sel = ng / EDIM, f = ng % EDIM, h = f >> 6, d = f & 63;
                    if (sel == 0) { ox *= 0.125f; oy *= 0.125f; }
                    __half* dst = (sel == 0) ? g_q : (sel == 1) ? g_k : g_v;
                    const size_t off = (((size_t)c_ * HDIM + h) * RDIM + i_) * DDIM + d;
                    *(__half2*)(dst + off) =
                        __half2(__float2half_rn(ox), __float2half_rn(oy));
                } else {
                    float2 o; o.x = ox; o.y = oy;
                    *(float2*)(outp + (size_t)m * EDIM + (ng - 3 * EDIM)) = o;
                }
            }
        }
    }
}

// ---------------- register-flash fp16 HMMA attention (2 heads/CTA, single product) ----------------
__global__ __launch_bounds__(512, 1)
void attn_tc(const unsigned char* __restrict__ mask, float* __restrict__ probs)
{
    extern __shared__ char sm[];
    const uint32_t smb = smem_to_u32(sm);
    const int c = blockIdx.x, hp = blockIdx.y;
    const int t = threadIdx.x, wid = t >> 5, lane = t & 31;

    // ---- loads: q, k, v for both heads, all [128][64] fp16 ----
#pragma unroll
    for (int tl2 = 0; tl2 < 2; ++tl2) {
        const size_t gb = ((size_t)c * HDIM + (hp * 2 + tl2)) * (RDIM * DDIM);
        const __half* sq[3] = { g_q + gb, g_k + gb, g_v + gb };
        const uint32_t qo[3] = { AQ, AK, AV };
#pragma unroll
        for (int m = 0; m < 3; ++m)
#pragma unroll
            for (int k = 0; k < 2; ++k) {
                const int id = t + k * 512;
                const int r = id >> 3, cl = id & 7;
                cp16(smb + tl2 * ATS + qo[m] + (uint32_t)(r * (PA * 2) + cl * 16),
                     sq[m] + (size_t)r * DDIM + cl * 8);
            }
    }
    cp_commit();

    // mask bitmap
    uint32_t* bmw = (uint32_t*)(sm + ABM);
    if (t < 4) bmw[t] = 0;
    __syncthreads();
    if (t < RDIM && mask[(size_t)t * CDIM + c]) atomicOr(&bmw[t >> 5], 1u << (t & 31));
    cp_wait0();
    __syncthreads();
    const uint32_t mb[4] = { bmw[0], bmw[1], bmw[2], bmw[3] };
    const bool any_mask = (mb[0] | mb[1] | mb[2] | mb[3]) != 0;

    const int tl = wid >> 3, rw = wid & 7;
    const int h = hp * 2 + tl;
    const uint32_t tb = smb + tl * ATS;
    const int lrow8 = (lane & 7) + ((lane >> 3) & 1) * 8;
    const int lkoff = (lane >> 4) * 8;

    // ---- S = Q K^T : warp tile 16(m) x 128(n), k=64, single product ----
    float sacc[16][4];
#pragma unroll
    for (int ni = 0; ni < 16; ++ni)
#pragma unroll
        for (int e = 0; e < 4; ++e) sacc[ni][e] = 0.0f;

    const uint32_t qb = tb + AQ + (uint32_t)((rw * 16 + lrow8) * (PA * 2));
    const uint32_t kbse = tb + AK + (uint32_t)(lrow8 * (PA * 2));
#pragma unroll
    for (int ks = 0; ks < 4; ++ks) {
        const uint32_t ko = (uint32_t)((ks * 16 + lkoff) * 2);
        uint32_t qf[4];
        ldmx4(qf, qb + ko);
#pragma unroll
        for (int nh = 0; nh < 2; ++nh) {
            uint32_t kf[4][4];
#pragma unroll
            for (int nb8 = 0; nb8 < 4; ++nb8)
                ldmx4(kf[nb8], kbse + (uint32_t)((nh * 64 + nb8 * 16) * (PA * 2)) + ko);
#pragma unroll
            for (int ni = 0; ni < 8; ++ni) {
                const int g = ni >> 1, lo = ni & 1, idx = nh * 8 + ni;
                mma16816(sacc[idx], qf, kf[g][lo], kf[g][lo + 2]);
            }
        }
    }

    // ---- mask + warp-local softmax ----
    if (any_mask) {
#pragma unroll
        for (int ni = 0; ni < 16; ++ni) {
            const uint32_t w = mb[ni >> 2];
            const int b0 = (ni & 3) * 8 + (lane & 3) * 2;
            if ((w >> b0) & 1)       { sacc[ni][0] = -10000.0f; sacc[ni][2] = -10000.0f; }
            if ((w >> (b0 + 1)) & 1) { sacc[ni][1] = -10000.0f; sacc[ni][3] = -10000.0f; }
        }
    }
    float mx0 = -3.0e38f, mx1 = -3.0e38f;
#pragma unroll
    for (int ni = 0; ni < 16; ++ni) {
        mx0 = fmaxf(mx0, fmaxf(sacc[ni][0], sacc[ni][1]));
        mx1 = fmaxf(mx1, fmaxf(sacc[ni][2], sacc[ni][3]));
    }
    mx0 = fmaxf(mx0, __shfl_xor_sync(0xffffffffu, mx0, 1));
    mx0 = fmaxf(mx0, __shfl_xor_sync(0xffffffffu, mx0, 2));
    mx1 = fmaxf(mx1, __shfl_xor_sync(0xffffffffu, mx1, 1));
    mx1 = fmaxf(mx1, __shfl_xor_sync(0xffffffffu, mx1, 2));

    float s0 = 0.0f, s1 = 0.0f;
#pragma unroll
    for (int ni = 0; ni < 16; ++ni) {
        sacc[ni][0] = __expf(sacc[ni][0] - mx0);
        sacc[ni][1] = __expf(sacc[ni][1] - mx0);
        sacc[ni][2] = __expf(sacc[ni][2] - mx1);
        sacc[ni][3] = __expf(sacc[ni][3] - mx1);
        s0 += sacc[ni][0] + sacc[ni][1];
        s1 += sacc[ni][2] + sacc[ni][3];
    }
    s0 += __shfl_xor_sync(0xffffffffu, s0, 1);
    s0 += __shfl_xor_sync(0xffffffffu, s0, 2);
    s1 += __shfl_xor_sync(0xffffffffu, s1, 1);
    s1 += __shfl_xor_sync(0xffffffffu, s1, 2);
    const float inv0 = 1.0f / s0, inv1 = 1.0f / s1;

    // ---- probs (normalized fp32) straight from registers ----
    {
        const int r0 = rw * 16 + (lane >> 2);
        float* pb = probs + (((size_t)h * CDIM + c) * RDIM + r0) * RDIM + (lane & 3) * 2;
#pragma unroll
        for (int ni = 0; ni < 16; ++ni) {
            float2 a; a.x = sacc[ni][0] * inv0; a.y = sacc[ni][1] * inv0;
            float2 b; b.x = sacc[ni][2] * inv1; b.y = sacc[ni][3] * inv1;
            *(float2*)(pb + ni * 8) = a;
            *(float2*)(pb + 8 * RDIM + ni * 8) = b;
        }
    }

    // ---- pack unnormalized P -> fp16 A-fragments (single) ----
    uint32_t ph0[16], ph1[16];
#pragma unroll
    for (int ni = 0; ni < 16; ++ni) {
        ph0[ni] = packh(sacc[ni][0], sacc[ni][1]);
        ph1[ni] = packh(sacc[ni][2], sacc[ni][3]);
    }

    // ---- transpose V [j][d] -> Vt [d][j] into (now free) Q region ----
    __syncthreads();
#pragma unroll
    for (int tl2 = 0; tl2 < 2; ++tl2) {
        const __half* vsrc = (const __half*)(sm + tl2 * ATS + AV);
        __half* vt = (__half*)(sm + tl2 * ATS + AVT);
#pragma unroll
        for (int k = 0; k < 16; ++k) {
            const int idx = t + k * 512;
            const int j = idx >> 6, d = idx & 63;
            vt[d * PVT + j] = vsrc[j * PA + d];
        }
    }
    __syncthreads();

    // ---- ctx = P V : warp tile 16(m) x 64(n), k=128, single product ----
    float cacc[8][4];
#pragma unroll
    for (int ni = 0; ni < 8; ++ni)
#pragma unroll
        for (int e = 0; e < 4; ++e) cacc[ni][e] = 0.0f;

    const uint32_t vb = tb + AVT + (uint32_t)(lrow8 * (PVT * 2));
#pragma unroll
    for (int kb = 0; kb < 8; ++kb) {
        const uint32_t ko = (uint32_t)((kb * 16 + lkoff) * 2);
        const uint32_t a_h[4] = { ph0[2 * kb], ph1[2 * kb], ph0[2 * kb + 1], ph1[2 * kb + 1] };
#pragma unroll
        for (int vh2 = 0; vh2 < 2; ++vh2) {
            uint32_t vf[2][4];
#pragma unroll
            for (int nb8 = 0; nb8 < 2; ++nb8)
                ldmx4(vf[nb8], vb + (uint32_t)((vh2 * 32 + nb8 * 16) * (PVT * 2)) + ko);
#pragma unroll
            for (int nl = 0; nl < 4; ++nl) {
                const int g = nl >> 1, lo = nl & 1, idx = vh2 * 4 + nl;
                mma16816(cacc[idx], a_h, vf[g][lo], vf[g][lo + 2]);
            }
        }
    }

    // ---- ctx epilogue (normalize, single fp16, feed out-projection) ----
    {
        const int r0 = rw * 16 + (lane >> 2);
#pragma unroll
        for (int ni = 0; ni < 8; ++ni) {
            const int d = ni * 8 + (lane & 3) * 2;
            const size_t ob0 = ((size_t)r0 * CDIM + c) * EDIM + h * DDIM + d;
            const size_t ob1 = ((size_t)(r0 + 8) * CDIM + c) * EDIM + h * DDIM + d;
            *(__half2*)(g_a + ob0) = __half2(__float2half_rn(cacc[ni][0] * inv0),
                                             __float2half_rn(cacc[ni][1] * inv0));
            *(__half2*)(g_a + ob1) = __half2(__float2half_rn(cacc[ni][2] * inv1),
                                             __float2half_rn(cacc[ni][3] * inv1));
        }
    }
}

// ---------------------------------------------------------------------------
extern "C" void kernel_launch(void* const* d_in, const int* in_sizes, int n_in,
                              void* d_out, int out_size)
{
    const float* x  = (const float*)d_in[0];
    const unsigned char* mask = (const unsigned char*)d_in[2];
    const float* wq = (const float*)d_in[3];
    const float* bq = (const float*)d_in[4];
    const float* wk = (const float*)d_in[5];
    const float* bk = (const float*)d_in[6];
    const float* wv = (const float*)d_in[7];
    const float* bv = (const float*)d_in[8];
    const float* wo = (const float*)d_in[9];
    const float* bo = (const float*)d_in[10];

    float* out   = (float*)d_out;                    // (R, C, 1, E)
    float* probs = out + (size_t)MDIM * EDIM;        // (H, C, 1, R, R)

    const int gemm_smem = 2 * GBUF;                  // 40960
    cudaFuncSetAttribute(gemm_tc, cudaFuncAttributeMaxDynamicSharedMemorySize, gemm_smem);
    cudaFuncSetAttribute(attn_tc, cudaFuncAttributeMaxDynamicSharedMemorySize, ATOT);

    conv_w<<<2304, 1024>>>(wq, wk, wv, wo, bq, bk, bv, bo);
    conv_x<<<9216, 1024>>>(x, MDIM * EDIM / 4);
    gemm_tc<<<dim3(18, MDIM / 128), 256, gemm_smem>>>(0, 0, out);        // qkv
    attn_tc<<<dim3(CDIM, HDIM / 2), 512, ATOT>>>(mask, probs);
    gemm_tc<<<dim3(6, MDIM / 128), 256, gemm_smem>>>(3 * EDIM, 1, out);  // out proj
}

// round 12
// speedup vs baseline: 3.1039x; 1.1067x over previous
#include <cuda_runtime.h>
#include <cuda_fp16.h>
#include <cstdint>

#define RDIM 128
#define CDIM 384
#define EDIM 768
#define HDIM 12
#define DDIM 64
#define MDIM (RDIM * CDIM)   // 49152

// GEMM tiling: CTA 128x128, 8 warps (2x4), warp tile 64x32, BK=64, single product
#define BK 64
#define GP 72                              // fp16/row (144B), conflict-free
#define MTX (128 * GP * 2)                 // 18432 B per matrix tile
#define GBUF (2 * MTX)                     // 36864 (A, B)

// attention smem map (per-tile, bytes): q, k, v each 128x64 fp16 @ pitch PA
#define PA 72      // rows: 144B
#define PVT 136    // vt rows: 272B
#define AQ  0
#define AK  18432
#define AV  36864
#define ATS 55296              /* per-tile stride */
#define AVT 0                  /* Vt (64 x PVT x 2 = 17408 B) aliases Q after S */
#define ABM (2 * ATS)          /* mask bitmap (4 x u32) */
#define ATOT (ABM + 16)

// ---------------- device scratch (allocation-free rule) ----------------
__device__ __half g_a[(size_t)MDIM * EDIM];      // A (x, then ctx), single fp16
__device__ __half g_w[(size_t)4 * EDIM * EDIM];  // packed wq|wk|wv|wo
__device__ float g_bias[4 * EDIM];
__device__ __half g_q[(size_t)MDIM * EDIM];      // [c][h][i][d]
__device__ __half g_k[(size_t)MDIM * EDIM];
__device__ __half g_v[(size_t)MDIM * EDIM];

// ---------------- helpers ----------------
__device__ __forceinline__ uint32_t smem_to_u32(const void* p) {
    uint32_t a;
    asm("{ .reg .u64 t; cvta.to.shared.u64 t, %1; cvt.u32.u64 %0, t; }"
        : "=r"(a) : "l"(p));
    return a;
}
__device__ __forceinline__ void cp16(uint32_t dst, const void* src) {
    asm volatile("cp.async.cg.shared.global [%0], [%1], 16;"
                 :: "r"(dst), "l"(src) : "memory");
}
__device__ __forceinline__ void cp_commit() {
    asm volatile("cp.async.commit_group;" ::: "memory");
}
__device__ __forceinline__ void cp_wait0() {
    asm volatile("cp.async.wait_group 0;" ::: "memory");
}
__device__ __forceinline__ void ldmx4(uint32_t (&r)[4], uint32_t addr) {
    asm volatile("ldmatrix.sync.aligned.m8n8.x4.shared.b16 {%0,%1,%2,%3}, [%4];"
                 : "=r"(r[0]), "=r"(r[1]), "=r"(r[2]), "=r"(r[3]) : "r"(addr));
}
__device__ __forceinline__ void mma16816(float (&d)[4], const uint32_t (&a)[4],
                                         uint32_t b0, uint32_t b1) {
    asm volatile(
        "mma.sync.aligned.m16n8k16.row.col.f32.f16.f16.f32 "
        "{%0,%1,%2,%3}, {%4,%5,%6,%7}, {%8,%9}, {%0,%1,%2,%3};"
        : "+f"(d[0]), "+f"(d[1]), "+f"(d[2]), "+f"(d[3])
        : "r"(a[0]), "r"(a[1]), "r"(a[2]), "r"(a[3]), "r"(b0), "r"(b1));
}
__device__ __forceinline__ uint32_t packh(float a, float b) {
    __half2 p(__float2half_rn(a), __float2half_rn(b));
    return *(uint32_t*)&p;
}

// ---------------- conversion kernels ----------------
__global__ void conv_x(const float* __restrict__ src, int n4) {
    int i = blockIdx.x * blockDim.x + threadIdx.x;
    if (i >= n4) return;
    float4 v = ((const float4*)src)[i];
    size_t o = (size_t)i * 4;
    *(__half2*)(g_a + o)     = __half2(__float2half_rn(v.x), __float2half_rn(v.y));
    *(__half2*)(g_a + o + 2) = __half2(__float2half_rn(v.z), __float2half_rn(v.w));
}

__global__ void conv_w(const float* __restrict__ wq, const float* __restrict__ wk,
                       const float* __restrict__ wv, const float* __restrict__ wo,
                       const float* __restrict__ bq, const float* __restrict__ bk,
                       const float* __restrict__ bv, const float* __restrict__ bo)
{
    const size_t WSZ = (size_t)EDIM * EDIM;
    size_t i = (size_t)blockIdx.x * blockDim.x + threadIdx.x;
    int sel = (int)(i / WSZ);
    size_t off = i - (size_t)sel * WSZ;
    const float* w = (sel == 0) ? wq : (sel == 1) ? wk : (sel == 2) ? wv : wo;
    g_w[i] = __float2half_rn(w[off]);
    if (i < 4 * EDIM) {
        int s = (int)(i / EDIM), r = (int)(i % EDIM);
        const float* b = (s == 0) ? bq : (s == 1) ? bk : (s == 2) ? bv : bo;
        g_bias[i] = b[r];
    }
}

// ---------------- fp16 HMMA GEMM (single product, BK=64, ntile-fastest grid) ----------------
__global__ __launch_bounds__(256, 2)
void gemm_tc(int n_off, int mode, float* __restrict__ outp)
{
    extern __shared__ char smdyn[];
    const uint32_t smb = smem_to_u32(smdyn);
    const int t = threadIdx.x;
    const int wid = t >> 5, lane = t & 31;
    const int wm = wid & 1, wn = wid >> 1;           // 2x4 warp grid
    const int bm = blockIdx.y * 128;
    const int nb = n_off + blockIdx.x * 128;

    const __half* srcA = g_a + (size_t)bm * EDIM;
    const __half* srcB = g_w + (size_t)nb * EDIM;

    float acc[4][4][4];
#pragma unroll
    for (int mi = 0; mi < 4; ++mi)
#pragma unroll
        for (int ni = 0; ni < 4; ++ni)
#pragma unroll
            for (int e = 0; e < 4; ++e) acc[mi][ni][e] = 0.0f;

    const int lrow8 = (lane & 7) + ((lane >> 3) & 1) * 8;
    const int lkoff = (lane >> 4) * 8;

    // prefetch chunk 0: per matrix 1024 x 16B; 256 threads x 4
    {
#pragma unroll
        for (int kk = 0; kk < 4; ++kk) {
            const int id = t + kk * 256;
            const int r = id >> 3, cl = id & 7;
            const uint32_t d = smb + (uint32_t)(r * (GP * 2) + cl * 16);
            const int s = r * EDIM + cl * 8;
            cp16(d, srcA + s);
            cp16(d + MTX, srcB + s);
        }
        cp_commit();
    }

    const int NC = EDIM / BK;  // 12
#pragma unroll 1
    for (int ch = 0; ch < NC; ++ch) {
        cp_wait0();
        __syncthreads();
        if (ch + 1 < NC) {
            const uint32_t bufn = ((ch + 1) & 1) * GBUF;
#pragma unroll
            for (int kk = 0; kk < 4; ++kk) {
                const int id = t + kk * 256;
                const int r = id >> 3, cl = id & 7;
                const uint32_t d = smb + bufn + (uint32_t)(r * (GP * 2) + cl * 16);
                const int s = r * EDIM + (ch + 1) * BK + cl * 8;
                cp16(d, srcA + s);
                cp16(d + MTX, srcB + s);
            }
            cp_commit();
        }
        const uint32_t buf = smb + (ch & 1) * GBUF;
        const uint32_t aA = buf + (uint32_t)((wm * 64 + lrow8) * (GP * 2));
        const uint32_t aB = buf + MTX + (uint32_t)((wn * 32 + lrow8) * (GP * 2));
#pragma unroll
        for (int ks = 0; ks < 4; ++ks) {
            const uint32_t kbyte = (uint32_t)((ks * 16 + lkoff) * 2);
            uint32_t bfr[2][4];
#pragma unroll
            for (int ng = 0; ng < 2; ++ng)
                ldmx4(bfr[ng], aB + (uint32_t)(ng * 16 * GP * 2) + kbyte);
#pragma unroll
            for (int mi = 0; mi < 4; ++mi) {
                uint32_t af[4];
                ldmx4(af, aA + (uint32_t)(mi * 16 * GP * 2) + kbyte);
#pragma unroll
                for (int ni = 0; ni < 4; ++ni) {
                    const int ng = ni >> 1, lo = ni & 1;
                    mma16816(acc[mi][ni], af, bfr[ng][lo], bfr[ng][lo + 2]);
                }
            }
        }
    }

    // epilogue
    const int r0 = bm + wm * 64 + (lane >> 2);
    const int cbase = nb + wn * 32 + (lane & 3) * 2;
#pragma unroll
    for (int mi = 0; mi < 4; ++mi) {
#pragma unroll
        for (int half = 0; half < 2; ++half) {
            const int m = r0 + mi * 16 + half * 8;
            const int i_ = m / CDIM, c_ = m % CDIM;
#pragma unroll
            for (int ni = 0; ni < 4; ++ni) {
                const int ng = cbase + ni * 8;
                float ox = acc[mi][ni][half * 2 + 0] + g_bias[ng + 0];
                float oy = acc[mi][ni][half * 2 + 1] + g_bias[ng + 1];
                if (mode == 0) {
                    const int sel = ng / EDIM, f = ng % EDIM, h = f >> 6, d = f & 63;
                    if (sel == 0) { ox *= 0.125f; oy *= 0.125f; }
                    __half* dst = (sel == 0) ? g_q : (sel == 1) ? g_k : g_v;
                    const size_t off = (((size_t)c_ * HDIM + h) * RDIM + i_) * DDIM + d;
                    *(__half2*)(dst + off) =
                        __half2(__float2half_rn(ox), __float2half_rn(oy));
                } else {
                    float2 o; o.x = ox; o.y = oy;
                    *(float2*)(outp + (size_t)m * EDIM + (ng - 3 * EDIM)) = o;
                }
            }
        }
    }
}

// ---------------- register-flash fp16 HMMA attention (2 heads/CTA, single product) ----------------
__global__ __launch_bounds__(512, 1)
void attn_tc(const unsigned char* __restrict__ mask, float* __restrict__ probs)
{
    extern __shared__ char sm[];
    const uint32_t smb = smem_to_u32(sm);
    const int c = blockIdx.x, hp = blockIdx.y;
    const int t = threadIdx.x, wid = t >> 5, lane = t & 31;

    // ---- loads: q, k, v for both heads, all [128][64] fp16 ----
#pragma unroll
    for (int tl2 = 0; tl2 < 2; ++tl2) {
        const size_t gb = ((size_t)c * HDIM + (hp * 2 + tl2)) * (RDIM * DDIM);
        const __half* sq[3] = { g_q + gb, g_k + gb, g_v + gb };
        const uint32_t qo[3] = { AQ, AK, AV };
#pragma unroll
        for (int m = 0; m < 3; ++m)
#pragma unroll
            for (int k = 0; k < 2; ++k) {
                const int id = t + k * 512;
                const int r = id >> 3, cl = id & 7;
                cp16(smb + tl2 * ATS + qo[m] + (uint32_t)(r * (PA * 2) + cl * 16),
                     sq[m] + (size_t)r * DDIM + cl * 8);
            }
    }
    cp_commit();

    // mask bitmap
    uint32_t* bmw = (uint32_t*)(sm + ABM);
    if (t < 4) bmw[t] = 0;
    __syncthreads();
    if (t < RDIM && mask[(size_t)t * CDIM + c]) atomicOr(&bmw[t >> 5], 1u << (t & 31));
    cp_wait0();
    __syncthreads();
    const uint32_t mb[4] = { bmw[0], bmw[1], bmw[2], bmw[3] };
    const bool any_mask = (mb[0] | mb[1] | mb[2] | mb[3]) != 0;

    const int tl = wid >> 3, rw = wid & 7;
    const int h = hp * 2 + tl;
    const uint32_t tb = smb + tl * ATS;
    const int lrow8 = (lane & 7) + ((lane >> 3) & 1) * 8;
    const int lkoff = (lane >> 4) * 8;

    // ---- S = Q K^T : warp tile 16(m) x 128(n), k=64, single product ----
    float sacc[16][4];
#pragma unroll
    for (int ni = 0; ni < 16; ++ni)
#pragma unroll
        for (int e = 0; e < 4; ++e) sacc[ni][e] = 0.0f;

    const uint32_t qb = tb + AQ + (uint32_t)((rw * 16 + lrow8) * (PA * 2));
    const uint32_t kbse = tb + AK + (uint32_t)(lrow8 * (PA * 2));
#pragma unroll
    for (int ks = 0; ks < 4; ++ks) {
        const uint32_t ko = (uint32_t)((ks * 16 + lkoff) * 2);
        uint32_t qf[4];
        ldmx4(qf, qb + ko);
#pragma unroll
        for (int nh = 0; nh < 2; ++nh) {
            uint32_t kf[4][4];
#pragma unroll
            for (int nb8 = 0; nb8 < 4; ++nb8)
                ldmx4(kf[nb8], kbse + (uint32_t)((nh * 64 + nb8 * 16) * (PA * 2)) + ko);
#pragma unroll
            for (int ni = 0; ni < 8; ++ni) {
                const int g = ni >> 1, lo = ni & 1, idx = nh * 8 + ni;
                mma16816(sacc[idx], qf, kf[g][lo], kf[g][lo + 2]);
            }
        }
    }

    // ---- mask + warp-local softmax ----
    if (any_mask) {
#pragma unroll
        for (int ni = 0; ni < 16; ++ni) {
            const uint32_t w = mb[ni >> 2];
            const int b0 = (ni & 3) * 8 + (lane & 3) * 2;
            if ((w >> b0) & 1)       { sacc[ni][0] = -10000.0f; sacc[ni][2] = -10000.0f; }
            if ((w >> (b0 + 1)) & 1) { sacc[ni][1] = -10000.0f; sacc[ni][3] = -10000.0f; }
        }
    }
    float mx0 = -3.0e38f, mx1 = -3.0e38f;
#pragma unroll
    for (int ni = 0; ni < 16; ++ni) {
        mx0 = fmaxf(mx0, fmaxf(sacc[ni][0], sacc[ni][1]));
        mx1 = fmaxf(mx1, fmaxf(sacc[ni][2], sacc[ni][3]));
    }
    mx0 = fmaxf(mx0, __shfl_xor_sync(0xffffffffu, mx0, 1));
    mx0 = fmaxf(mx0, __shfl_xor_sync(0xffffffffu, mx0, 2));
    mx1 = fmaxf(mx1, __shfl_xor_sync(0xffffffffu, mx1, 1));
    mx1 = fmaxf(mx1, __shfl_xor_sync(0xffffffffu, mx1, 2));

    float s0 = 0.0f, s1 = 0.0f;
#pragma unroll
    for (int ni = 0; ni < 16; ++ni) {
        sacc[ni][0] = __expf(sacc[ni][0] - mx0);
        sacc[ni][1] = __expf(sacc[ni][1] - mx0);
        sacc[ni][2] = __expf(sacc[ni][2] - mx1);
        sacc[ni][3] = __expf(sacc[ni][3] - mx1);
        s0 += sacc[ni][0] + sacc[ni][1];
        s1 += sacc[ni][2] + sacc[ni][3];
    }
    s0 += __shfl_xor_sync(0xffffffffu, s0, 1);
    s0 += __shfl_xor_sync(0xffffffffu, s0, 2);
    s1 += __shfl_xor_sync(0xffffffffu, s1, 1);
    s1 += __shfl_xor_sync(0xffffffffu, s1, 2);
    const float inv0 = 1.0f / s0, inv1 = 1.0f / s1;

    // ---- probs (normalized fp32) straight from registers ----
    {
        const int r0 = rw * 16 + (lane >> 2);
        float* pb = probs + (((size_t)h * CDIM + c) * RDIM + r0) * RDIM + (lane & 3) * 2;
#pragma unroll
        for (int ni = 0; ni < 16; ++ni) {
            float2 a; a.x = sacc[ni][0] * inv0; a.y = sacc[ni][1] * inv0;
            float2 b; b.x = sacc[ni][2] * inv1; b.y = sacc[ni][3] * inv1;
            *(float2*)(pb + ni * 8) = a;
            *(float2*)(pb + 8 * RDIM + ni * 8) = b;
        }
    }

    // ---- pack unnormalized P -> fp16 A-fragments (single) ----
    uint32_t ph0[16], ph1[16];
#pragma unroll
    for (int ni = 0; ni < 16; ++ni) {
        ph0[ni] = packh(sacc[ni][0], sacc[ni][1]);
        ph1[ni] = packh(sacc[ni][2], sacc[ni][3]);
    }

    // ---- transpose V [j][d] -> Vt [d][j] into (now free) Q region ----
    __syncthreads();
#pragma unroll
    for (int tl2 = 0; tl2 < 2; ++tl2) {
        const __half* vsrc = (const __half*)(sm + tl2 * ATS + AV);
        __half* vt = (__half*)(sm + tl2 * ATS + AVT);
#pragma unroll
        for (int k = 0; k < 16; ++k) {
            const int idx = t + k * 512;
            const int j = idx >> 6, d = idx & 63;
            vt[d * PVT + j] = vsrc[j * PA + d];
        }
    }
    __syncthreads();

    // ---- ctx = P V : warp tile 16(m) x 64(n), k=128, single product ----
    float cacc[8][4];
#pragma unroll
    for (int ni = 0; ni < 8; ++ni)
#pragma unroll
        for (int e = 0; e < 4; ++e) cacc[ni][e] = 0.0f;

    const uint32_t vb = tb + AVT + (uint32_t)(lrow8 * (PVT * 2));
#pragma unroll
    for (int kb = 0; kb < 8; ++kb) {
        const uint32_t ko = (uint32_t)((kb * 16 + lkoff) * 2);
        const uint32_t a_h[4] = { ph0[2 * kb], ph1[2 * kb], ph0[2 * kb + 1], ph1[2 * kb + 1] };
#pragma unroll
        for (int vh2 = 0; vh2 < 2; ++vh2) {
            uint32_t vf[2][4];
#pragma unroll
            for (int nb8 = 0; nb8 < 2; ++nb8)
                ldmx4(vf[nb8], vb + (uint32_t)((vh2 * 32 + nb8 * 16) * (PVT * 2)) + ko);
#pragma unroll
            for (int nl = 0; nl < 4; ++nl) {
                const int g = nl >> 1, lo = nl & 1, idx = vh2 * 4 + nl;
                mma16816(cacc[idx], a_h, vf[g][lo], vf[g][lo + 2]);
            }
        }
    }

    // ---- ctx epilogue (normalize, single fp16, feed out-projection) ----
    {
        const int r0 = rw * 16 + (lane >> 2);
#pragma unroll
        for (int ni = 0; ni < 8; ++ni) {
            const int d = ni * 8 + (lane & 3) * 2;
            const size_t ob0 = ((size_t)r0 * CDIM + c) * EDIM + h * DDIM + d;
            const size_t ob1 = ((size_t)(r0 + 8) * CDIM + c) * EDIM + h * DDIM + d;
            *(__half2*)(g_a + ob0) = __half2(__float2half_rn(cacc[ni][0] * inv0),
                                             __float2half_rn(cacc[ni][1] * inv0));
            *(__half2*)(g_a + ob1) = __half2(__float2half_rn(cacc[ni][2] * inv1),
                                             __float2half_rn(cacc[ni][3] * inv1));
        }
    }
}

// ---------------------------------------------------------------------------
extern "C" void kernel_launch(void* const* d_in, const int* in_sizes, int n_in,
                              void* d_out, int out_size)
{
    const float* x  = (const float*)d_in[0];
    const unsigned char* mask = (const unsigned char*)d_in[2];
    const float* wq = (const float*)d_in[3];
    const float* bq = (const float*)d_in[4];
    const float* wk = (const float*)d_in[5];
    const float* bk = (const float*)d_in[6];
    const float* wv = (const float*)d_in[7];
    const float* bv = (const float*)d_in[8];
    const float* wo = (const float*)d_in[9];
    const float* bo = (const float*)d_in[10];

    float* out   = (float*)d_out;                    // (R, C, 1, E)
    float* probs = out + (size_t)MDIM * EDIM;        // (H, C, 1, R, R)

    const int gemm_smem = 2 * GBUF;                  // 73728
    cudaFuncSetAttribute(gemm_tc, cudaFuncAttributeMaxDynamicSharedMemorySize, gemm_smem);
    cudaFuncSetAttribute(attn_tc, cudaFuncAttributeMaxDynamicSharedMemorySize, ATOT);

    conv_w<<<2304, 1024>>>(wq, wk, wv, wo, bq, bk, bv, bo);
    conv_x<<<9216, 1024>>>(x, MDIM * EDIM / 4);
    gemm_tc<<<dim3(18, MDIM / 128), 256, gemm_smem>>>(0, 0, out);        // qkv
    attn_tc<<<dim3(CDIM, HDIM / 2), 512, ATOT>>>(mask, probs);
    gemm_tc<<<dim3(6, MDIM / 128), 256, gemm_smem>>>(3 * EDIM, 1, out);  // out proj
}

// round 13
// speedup vs baseline: 3.2224x; 1.0382x over previous
#include <cuda_runtime.h>
#include <cuda_fp16.h>
#include <cstdint>

#define RDIM 128
#define CDIM 384
#define EDIM 768
#define HDIM 12
#define DDIM 64
#define MDIM (RDIM * CDIM)   // 49152

// GEMM tiling: CTA 128x128, 8 warps (2x4), warp tile 64x32, BK=64, single product
#define BK 64
#define GP 72                              // fp16/row (144B), conflict-free
#define MTX (128 * GP * 2)                 // 18432 B per matrix tile
#define GBUF (2 * MTX)                     // 36864 (A, B)

// attention smem map (bytes): q, k, v each 128x64 fp16 @ pitch PA
#define PA 72      // rows: 144B
#define PVT 136    // vt rows: 272B
#define AQ  0
#define AK  18432
#define AV  36864
#define AVT 0                  /* Vt (64 x PVT x 2 = 17408 B) aliases Q after S */
#define ABM 55296              /* mask bitmap (4 x u32) */
#define ATOT (ABM + 16)

// ---------------- device scratch (allocation-free rule) ----------------
__device__ __half g_a[(size_t)MDIM * EDIM];      // A (x, then ctx), single fp16
__device__ __half g_w[(size_t)4 * EDIM * EDIM];  // packed wq|wk|wv|wo
__device__ float g_bias[4 * EDIM];
__device__ __half g_q[(size_t)MDIM * EDIM];      // [c][h][i][d]
__device__ __half g_k[(size_t)MDIM * EDIM];
__device__ __half g_v[(size_t)MDIM * EDIM];

// ---------------- helpers ----------------
__device__ __forceinline__ uint32_t smem_to_u32(const void* p) {
    uint32_t a;
    asm("{ .reg .u64 t; cvta.to.shared.u64 t, %1; cvt.u32.u64 %0, t; }"
        : "=r"(a) : "l"(p));
    return a;
}
__device__ __forceinline__ void cp16(uint32_t dst, const void* src) {
    asm volatile("cp.async.cg.shared.global [%0], [%1], 16;"
                 :: "r"(dst), "l"(src) : "memory");
}
__device__ __forceinline__ void cp_commit() {
    asm volatile("cp.async.commit_group;" ::: "memory");
}
__device__ __forceinline__ void cp_wait0() {
    asm volatile("cp.async.wait_group 0;" ::: "memory");
}
__device__ __forceinline__ void ldmx4(uint32_t (&r)[4], uint32_t addr) {
    asm volatile("ldmatrix.sync.aligned.m8n8.x4.shared.b16 {%0,%1,%2,%3}, [%4];"
                 : "=r"(r[0]), "=r"(r[1]), "=r"(r[2]), "=r"(r[3]) : "r"(addr));
}
__device__ __forceinline__ void mma16816(float (&d)[4], const uint32_t (&a)[4],
                                         uint32_t b0, uint32_t b1) {
    asm volatile(
        "mma.sync.aligned.m16n8k16.row.col.f32.f16.f16.f32 "
        "{%0,%1,%2,%3}, {%4,%5,%6,%7}, {%8,%9}, {%0,%1,%2,%3};"
        : "+f"(d[0]), "+f"(d[1]), "+f"(d[2]), "+f"(d[3])
        : "r"(a[0]), "r"(a[1]), "r"(a[2]), "r"(a[3]), "r"(b0), "r"(b1));
}
__device__ __forceinline__ uint32_t packh(float a, float b) {
    __half2 p(__float2half_rn(a), __float2half_rn(b));
    return *(uint32_t*)&p;
}

// ---------------- merged conversion kernel ----------------
// blocks [0, 2304): weights+bias; blocks [2304, 11520): x (float4 granules)
__global__ void conv_all(const float* __restrict__ x,
                         const float* __restrict__ wq, const float* __restrict__ wk,
                         const float* __restrict__ wv, const float* __restrict__ wo,
                         const float* __restrict__ bq, const float* __restrict__ bk,
                         const float* __restrict__ bv, const float* __restrict__ bo)
{
    if (blockIdx.x < 2304) {
        const size_t WSZ = (size_t)EDIM * EDIM;
        size_t i = (size_t)blockIdx.x * blockDim.x + threadIdx.x;  // < 4*WSZ exact
        int sel = (int)(i / WSZ);
        size_t off = i - (size_t)sel * WSZ;
        const float* w = (sel == 0) ? wq : (sel == 1) ? wk : (sel == 2) ? wv : wo;
        g_w[i] = __float2half_rn(w[off]);
        if (i < 4 * EDIM) {
            int s = (int)(i / EDIM), r = (int)(i % EDIM);
            const float* b = (s == 0) ? bq : (s == 1) ? bk : (s == 2) ? bv : bo;
            g_bias[i] = b[r];
        }
    } else {
        int i = (blockIdx.x - 2304) * blockDim.x + threadIdx.x;    // < MDIM*EDIM/4 exact
        float4 v = ((const float4*)x)[i];
        size_t o = (size_t)i * 4;
        *(__half2*)(g_a + o)     = __half2(__float2half_rn(v.x), __float2half_rn(v.y));
        *(__half2*)(g_a + o + 2) = __half2(__float2half_rn(v.z), __float2half_rn(v.w));
    }
}

// ---------------- fp16 HMMA GEMM (single product, BK=64, ntile-fastest grid) ----------------
__global__ __launch_bounds__(256, 2)
void gemm_tc(int n_off, int mode, float* __restrict__ outp)
{
    extern __shared__ char smdyn[];
    const uint32_t smb = smem_to_u32(smdyn);
    const int t = threadIdx.x;
    const int wid = t >> 5, lane = t & 31;
    const int wm = wid & 1, wn = wid >> 1;           // 2x4 warp grid
    const int bm = blockIdx.y * 128;
    const int nb = n_off + blockIdx.x * 128;

    const __half* srcA = g_a + (size_t)bm * EDIM;
    const __half* srcB = g_w + (size_t)nb * EDIM;

    float acc[4][4][4];
#pragma unroll
    for (int mi = 0; mi < 4; ++mi)
#pragma unroll
        for (int ni = 0; ni < 4; ++ni)
#pragma unroll
            for (int e = 0; e < 4; ++e) acc[mi][ni][e] = 0.0f;

    const int lrow8 = (lane & 7) + ((lane >> 3) & 1) * 8;
    const int lkoff = (lane >> 4) * 8;

    // prefetch chunk 0: per matrix 1024 x 16B; 256 threads x 4
    {
#pragma unroll
        for (int kk = 0; kk < 4; ++kk) {
            const int id = t + kk * 256;
            const int r = id >> 3, cl = id & 7;
            const uint32_t d = smb + (uint32_t)(r * (GP * 2) + cl * 16);
            const int s = r * EDIM + cl * 8;
            cp16(d, srcA + s);
            cp16(d + MTX, srcB + s);
        }
        cp_commit();
    }

    const int NC = EDIM / BK;  // 12
#pragma unroll 1
    for (int ch = 0; ch < NC; ++ch) {
        cp_wait0();
        __syncthreads();
        if (ch + 1 < NC) {
            const uint32_t bufn = ((ch + 1) & 1) * GBUF;
#pragma unroll
            for (int kk = 0; kk < 4; ++kk) {
                const int id = t + kk * 256;
                const int r = id >> 3, cl = id & 7;
                const uint32_t d = smb + bufn + (uint32_t)(r * (GP * 2) + cl * 16);
                const int s = r * EDIM + (ch + 1) * BK + cl * 8;
                cp16(d, srcA + s);
                cp16(d + MTX, srcB + s);
            }
            cp_commit();
        }
        const uint32_t buf = smb + (ch & 1) * GBUF;
        const uint32_t aA = buf + (uint32_t)((wm * 64 + lrow8) * (GP * 2));
        const uint32_t aB = buf + MTX + (uint32_t)((wn * 32 + lrow8) * (GP * 2));
#pragma unroll
        for (int ks = 0; ks < 4; ++ks) {
            const uint32_t kbyte = (uint32_t)((ks * 16 + lkoff) * 2);
            uint32_t bfr[2][4];
#pragma unroll
            for (int ng = 0; ng < 2; ++ng)
                ldmx4(bfr[ng], aB + (uint32_t)(ng * 16 * GP * 2) + kbyte);
#pragma unroll
            for (int mi = 0; mi < 4; ++mi) {
                uint32_t af[4];
                ldmx4(af, aA + (uint32_t)(mi * 16 * GP * 2) + kbyte);
#pragma unroll
                for (int ni = 0; ni < 4; ++ni) {
                    const int ng = ni >> 1, lo = ni & 1;
                    mma16816(acc[mi][ni], af, bfr[ng][lo], bfr[ng][lo + 2]);
                }
            }
        }
    }

    // epilogue
    const int r0 = bm + wm * 64 + (lane >> 2);
    const int cbase = nb + wn * 32 + (lane & 3) * 2;
#pragma unroll
    for (int mi = 0; mi < 4; ++mi) {
#pragma unroll
        for (int half = 0; half < 2; ++half) {
            const int m = r0 + mi * 16 + half * 8;
            const int i_ = m / CDIM, c_ = m % CDIM;
#pragma unroll
            for (int ni = 0; ni < 4; ++ni) {
                const int ng = cbase + ni * 8;
                float ox = acc[mi][ni][half * 2 + 0] + g_bias[ng + 0];
                float oy = acc[mi][ni][half * 2 + 1] + g_bias[ng + 1];
                if (mode == 0) {
                    const int sel = ng / EDIM, f = ng % EDIM, h = f >> 6, d = f & 63;
                    if (sel == 0) { ox *= 0.125f; oy *= 0.125f; }
                    __half* dst = (sel == 0) ? g_q : (sel == 1) ? g_k : g_v;
                    const size_t off = (((size_t)c_ * HDIM + h) * RDIM + i_) * DDIM + d;
                    *(__half2*)(dst + off) =
                        __half2(__float2half_rn(ox), __float2half_rn(oy));
                } else {
                    float2 o; o.x = ox; o.y = oy;
                    *(float2*)(outp + (size_t)m * EDIM + (ng - 3 * EDIM)) = o;
                }
            }
        }
    }
}

// ---------------- register-flash fp16 HMMA attention (1 head/CTA, 2 CTAs/SM) ----------------
__global__ __launch_bounds__(256, 2)
void attn_tc(const unsigned char* __restrict__ mask, float* __restrict__ probs)
{
    extern __shared__ char sm[];
    const uint32_t smb = smem_to_u32(sm);
    const int c = blockIdx.x, h = blockIdx.y;
    const int t = threadIdx.x, wid = t >> 5, lane = t & 31;

    // ---- loads: q, k, v, all [128][64] fp16 ----
    {
        const size_t gb = ((size_t)c * HDIM + h) * (RDIM * DDIM);
        const __half* sq[3] = { g_q + gb, g_k + gb, g_v + gb };
        const uint32_t qo[3] = { AQ, AK, AV };
#pragma unroll
        for (int m = 0; m < 3; ++m)
#pragma unroll
            for (int k = 0; k < 4; ++k) {
                const int id = t + k * 256;
                const int r = id >> 3, cl = id & 7;
                cp16(smb + qo[m] + (uint32_t)(r * (PA * 2) + cl * 16),
                     sq[m] + (size_t)r * DDIM + cl * 8);
            }
    }
    cp_commit();

    // mask bitmap
    uint32_t* bmw = (uint32_t*)(sm + ABM);
    if (t < 4) bmw[t] = 0;
    __syncthreads();
    if (t < RDIM && mask[(size_t)t * CDIM + c]) atomicOr(&bmw[t >> 5], 1u << (t & 31));
    cp_wait0();
    __syncthreads();
    const uint32_t mb[4] = { bmw[0], bmw[1], bmw[2], bmw[3] };
    const bool any_mask = (mb[0] | mb[1] | mb[2] | mb[3]) != 0;

    const int rw = wid;                       // warp owns rows [16rw, 16rw+16)
    const int lrow8 = (lane & 7) + ((lane >> 3) & 1) * 8;
    const int lkoff = (lane >> 4) * 8;

    // ---- S = Q K^T : warp tile 16(m) x 128(n), k=64, single product ----
    float sacc[16][4];
#pragma unroll
    for (int ni = 0; ni < 16; ++ni)
#pragma unroll
        for (int e = 0; e < 4; ++e) sacc[ni][e] = 0.0f;

    const uint32_t qb = smb + AQ + (uint32_t)((rw * 16 + lrow8) * (PA * 2));
    const uint32_t kbse = smb + AK + (uint32_t)(lrow8 * (PA * 2));
#pragma unroll
    for (int ks = 0; ks < 4; ++ks) {
        const uint32_t ko = (uint32_t)((ks * 16 + lkoff) * 2);
        uint32_t qf[4];
        ldmx4(qf, qb + ko);
#pragma unroll
        for (int nh = 0; nh < 2; ++nh) {
            uint32_t kf[4][4];
#pragma unroll
            for (int nb8 = 0; nb8 < 4; ++nb8)
                ldmx4(kf[nb8], kbse + (uint32_t)((nh * 64 + nb8 * 16) * (PA * 2)) + ko);
#pragma unroll
            for (int ni = 0; ni < 8; ++ni) {
                const int g = ni >> 1, lo = ni & 1, idx = nh * 8 + ni;
                mma16816(sacc[idx], qf, kf[g][lo], kf[g][lo + 2]);
            }
        }
    }

    // ---- mask + warp-local softmax ----
    if (any_mask) {
#pragma unroll
        for (int ni = 0; ni < 16; ++ni) {
            const uint32_t w = mb[ni >> 2];
            const int b0 = (ni & 3) * 8 + (lane & 3) * 2;
            if ((w >> b0) & 1)       { sacc[ni][0] = -10000.0f; sacc[ni][2] = -10000.0f; }
            if ((w >> (b0 + 1)) & 1) { sacc[ni][1] = -10000.0f; sacc[ni][3] = -10000.0f; }
        }
    }
    float mx0 = -3.0e38f, mx1 = -3.0e38f;
#pragma unroll
    for (int ni = 0; ni < 16; ++ni) {
        mx0 = fmaxf(mx0, fmaxf(sacc[ni][0], sacc[ni][1]));
        mx1 = fmaxf(mx1, fmaxf(sacc[ni][2], sacc[ni][3]));
    }
    mx0 = fmaxf(mx0, __shfl_xor_sync(0xffffffffu, mx0, 1));
    mx0 = fmaxf(mx0, __shfl_xor_sync(0xffffffffu, mx0, 2));
    mx1 = fmaxf(mx1, __shfl_xor_sync(0xffffffffu, mx1, 1));
    mx1 = fmaxf(mx1, __shfl_xor_sync(0xffffffffu, mx1, 2));

    float s0 = 0.0f, s1 = 0.0f;
#pragma unroll
    for (int ni = 0; ni < 16; ++ni) {
        sacc[ni][0] = __expf(sacc[ni][0] - mx0);
        sacc[ni][1] = __expf(sacc[ni][1] - mx0);
        sacc[ni][2] = __expf(sacc[ni][2] - mx1);
        sacc[ni][3] = __expf(sacc[ni][3] - mx1);
        s0 += sacc[ni][0] + sacc[ni][1];
        s1 += sacc[ni][2] + sacc[ni][3];
    }
    s0 += __shfl_xor_sync(0xffffffffu, s0, 1);
    s0 += __shfl_xor_sync(0xffffffffu, s0, 2);
    s1 += __shfl_xor_sync(0xffffffffu, s1, 1);
    s1 += __shfl_xor_sync(0xffffffffu, s1, 2);
    const float inv0 = 1.0f / s0, inv1 = 1.0f / s1;

    // ---- probs (normalized fp32) straight from registers ----
    {
        const int r0 = rw * 16 + (lane >> 2);
        float* pb = probs + (((size_t)h * CDIM + c) * RDIM + r0) * RDIM + (lane & 3) * 2;
#pragma unroll
        for (int ni = 0; ni < 16; ++ni) {
            float2 a; a.x = sacc[ni][0] * inv0; a.y = sacc[ni][1] * inv0;
            float2 b; b.x = sacc[ni][2] * inv1; b.y = sacc[ni][3] * inv1;
            *(float2*)(pb + ni * 8) = a;
            *(float2*)(pb + 8 * RDIM + ni * 8) = b;
        }
    }

    // ---- pack unnormalized P -> fp16 A-fragments ----
    uint32_t ph0[16], ph1[16];
#pragma unroll
    for (int ni = 0; ni < 16; ++ni) {
        ph0[ni] = packh(sacc[ni][0], sacc[ni][1]);
        ph1[ni] = packh(sacc[ni][2], sacc[ni][3]);
    }

    // ---- transpose V [j][d] -> Vt [d][j] into (now free) Q region ----
    __syncthreads();
    {
        const __half* vsrc = (const __half*)(sm + AV);
        __half* vt = (__half*)(sm + AVT);
#pragma unroll
        for (int k = 0; k < 32; ++k) {
            const int idx = t + k * 256;
            const int j = idx >> 6, d = idx & 63;
            vt[d * PVT + j] = vsrc[j * PA + d];
        }
    }
    __syncthreads();

    // ---- ctx = P V : warp tile 16(m) x 64(n), k=128, single product ----
    float cacc[8][4];
#pragma unroll
    for (int ni = 0; ni < 8; ++ni)
#pragma unroll
        for (int e = 0; e < 4; ++e) cacc[ni][e] = 0.0f;

    const uint32_t vb = smb + AVT + (uint32_t)(lrow8 * (PVT * 2));
#pragma unroll
    for (int kb = 0; kb < 8; ++kb) {
        const uint32_t ko = (uint32_t)((kb * 16 + lkoff) * 2);
        const uint32_t a_h[4] = { ph0[2 * kb], ph1[2 * kb], ph0[2 * kb + 1], ph1[2 * kb + 1] };
#pragma unroll
        for (int vh2 = 0; vh2 < 2; ++vh2) {
            uint32_t vf[2][4];
#pragma unroll
            for (int nb8 = 0; nb8 < 2; ++nb8)
                ldmx4(vf[nb8], vb + (uint32_t)((vh2 * 32 + nb8 * 16) * (PVT * 2)) + ko);
#pragma unroll
            for (int nl = 0; nl < 4; ++nl) {
                const int g = nl >> 1, lo = nl & 1, idx = vh2 * 4 + nl;
                mma16816(cacc[idx], a_h, vf[g][lo], vf[g][lo + 2]);
            }
        }
    }

    // ---- ctx epilogue (normalize, single fp16, feed out-projection) ----
    {
        const int r0 = rw * 16 + (lane >> 2);
#pragma unroll
        for (int ni = 0; ni < 8; ++ni) {
            const int d = ni * 8 + (lane & 3) * 2;
            const size_t ob0 = ((size_t)r0 * CDIM + c) * EDIM + h * DDIM + d;
            const size_t ob1 = ((size_t)(r0 + 8) * CDIM + c) * EDIM + h * DDIM + d;
            *(__half2*)(g_a + ob0) = __half2(__float2half_rn(cacc[ni][0] * inv0),
                                             __float2half_rn(cacc[ni][1] * inv0));
            *(__half2*)(g_a + ob1) = __half2(__float2half_rn(cacc[ni][2] * inv1),
                                             __float2half_rn(cacc[ni][3] * inv1));
        }
    }
}

// ---------------------------------------------------------------------------
extern "C" void kernel_launch(void* const* d_in, const int* in_sizes, int n_in,
                              void* d_out, int out_size)
{
    const float* x  = (const float*)d_in[0];
    const unsigned char* mask = (const unsigned char*)d_in[2];
    const float* wq = (const float*)d_in[3];
    const float* bq = (const float*)d_in[4];
    const float* wk = (const float*)d_in[5];
    const float* bk = (const float*)d_in[6];
    const float* wv = (const float*)d_in[7];
    const float* bv = (const float*)d_in[8];
    const float* wo = (const float*)d_in[9];
    const float* bo = (const float*)d_in[10];

    float* out   = (float*)d_out;                    // (R, C, 1, E)
    float* probs = out + (size_t)MDIM * EDIM;        // (H, C, 1, R, R)

    const int gemm_smem = 2 * GBUF;                  // 73728
    cudaFuncSetAttribute(gemm_tc, cudaFuncAttributeMaxDynamicSharedMemorySize, gemm_smem);
    cudaFuncSetAttribute(attn_tc, cudaFuncAttributeMaxDynamicSharedMemorySize, ATOT);

    conv_all<<<11520, 1024>>>(x, wq, wk, wv, wo, bq, bk, bv, bo);
    gemm_tc<<<dim3(18, MDIM / 128), 256, gemm_smem>>>(0, 0, out);        // qkv
    attn_tc<<<dim3(CDIM, HDIM), 256, ATOT>>>(mask, probs);
    gemm_tc<<<dim3(6, MDIM / 128), 256, gemm_smem>>>(3 * EDIM, 1, out);  // out proj
}

// round 14
// speedup vs baseline: 3.3035x; 1.0251x over previous
#include <cuda_runtime.h>
#include <cuda_fp16.h>
#include <cstdint>

#define RDIM 128
#define CDIM 384
#define EDIM 768
#define HDIM 12
#define DDIM 64
#define MDIM (RDIM * CDIM)   // 49152

// GEMM tiling: CTA 128x128, 8 warps (2x4), warp tile 64x32, BK=64, single product
#define BK 64
#define GP 72                              // fp16/row (144B), conflict-free
#define MTX (128 * GP * 2)                 // 18432 B per matrix tile
#define GBUF (2 * MTX)                     // 36864 (A, B)

// attention smem map (bytes): q, k, v each 128x64 fp16 @ pitch PA
#define PA 72      // rows: 144B
#define AQ  0
#define AK  18432
#define AV  36864
#define ABM 55296              /* mask bitmap (4 x u32) */
#define ATOT (ABM + 16)

// ---------------- device scratch (allocation-free rule) ----------------
__device__ __half g_a[(size_t)MDIM * EDIM];      // A (x, then ctx), single fp16
__device__ __half g_w[(size_t)4 * EDIM * EDIM];  // packed wq|wk|wv|wo
__device__ float g_bias[4 * EDIM];
__device__ __half g_q[(size_t)MDIM * EDIM];      // [c][h][i][d]
__device__ __half g_k[(size_t)MDIM * EDIM];
__device__ __half g_v[(size_t)MDIM * EDIM];

// ---------------- helpers ----------------
__device__ __forceinline__ uint32_t smem_to_u32(const void* p) {
    uint32_t a;
    asm("{ .reg .u64 t; cvta.to.shared.u64 t, %1; cvt.u32.u64 %0, t; }"
        : "=r"(a) : "l"(p));
    return a;
}
__device__ __forceinline__ void cp16(uint32_t dst, const void* src) {
    asm volatile("cp.async.cg.shared.global [%0], [%1], 16;"
                 :: "r"(dst), "l"(src) : "memory");
}
__device__ __forceinline__ void cp_commit() {
    asm volatile("cp.async.commit_group;" ::: "memory");
}
__device__ __forceinline__ void cp_wait0() {
    asm volatile("cp.async.wait_group 0;" ::: "memory");
}
__device__ __forceinline__ void ldmx4(uint32_t (&r)[4], uint32_t addr) {
    asm volatile("ldmatrix.sync.aligned.m8n8.x4.shared.b16 {%0,%1,%2,%3}, [%4];"
                 : "=r"(r[0]), "=r"(r[1]), "=r"(r[2]), "=r"(r[3]) : "r"(addr));
}
__device__ __forceinline__ void ldmx4t(uint32_t (&r)[4], uint32_t addr) {
    asm volatile("ldmatrix.sync.aligned.m8n8.x4.trans.shared.b16 {%0,%1,%2,%3}, [%4];"
                 : "=r"(r[0]), "=r"(r[1]), "=r"(r[2]), "=r"(r[3]) : "r"(addr));
}
__device__ __forceinline__ void mma16816(float (&d)[4], const uint32_t (&a)[4],
                                         uint32_t b0, uint32_t b1) {
    asm volatile(
        "mma.sync.aligned.m16n8k16.row.col.f32.f16.f16.f32 "
        "{%0,%1,%2,%3}, {%4,%5,%6,%7}, {%8,%9}, {%0,%1,%2,%3};"
        : "+f"(d[0]), "+f"(d[1]), "+f"(d[2]), "+f"(d[3])
        : "r"(a[0]), "r"(a[1]), "r"(a[2]), "r"(a[3]), "r"(b0), "r"(b1));
}
__device__ __forceinline__ uint32_t packh(float a, float b) {
    __half2 p(__float2half_rn(a), __float2half_rn(b));
    return *(uint32_t*)&p;
}

// ---------------- merged conversion kernel ----------------
// blocks [0, 2304): weights+bias; blocks [2304, 11520): x (float4 granules)
__global__ void conv_all(const float* __restrict__ x,
                         const float* __restrict__ wq, const float* __restrict__ wk,
                         const float* __restrict__ wv, const float* __restrict__ wo,
                         const float* __restrict__ bq, const float* __restrict__ bk,
                         const float* __restrict__ bv, const float* __restrict__ bo)
{
    if (blockIdx.x < 2304) {
        const size_t WSZ = (size_t)EDIM * EDIM;
        size_t i = (size_t)blockIdx.x * blockDim.x + threadIdx.x;  // < 4*WSZ exact
        int sel = (int)(i / WSZ);
        size_t off = i - (size_t)sel * WSZ;
        const float* w = (sel == 0) ? wq : (sel == 1) ? wk : (sel == 2) ? wv : wo;
        g_w[i] = __float2half_rn(w[off]);
        if (i < 4 * EDIM) {
            int s = (int)(i / EDIM), r = (int)(i % EDIM);
            const float* b = (s == 0) ? bq : (s == 1) ? bk : (s == 2) ? bv : bo;
            g_bias[i] = b[r];
        }
    } else {
        int i = (blockIdx.x - 2304) * blockDim.x + threadIdx.x;    // < MDIM*EDIM/4 exact
        float4 v = ((const float4*)x)[i];
        size_t o = (size_t)i * 4;
        *(__half2*)(g_a + o)     = __half2(__float2half_rn(v.x), __float2half_rn(v.y));
        *(__half2*)(g_a + o + 2) = __half2(__float2half_rn(v.z), __float2half_rn(v.w));
    }
}

// ---------------- fp16 HMMA GEMM (single product, BK=64, ntile-fastest grid) ----------------
__global__ __launch_bounds__(256, 2)
void gemm_tc(int n_off, int mode, float* __restrict__ outp)
{
    extern __shared__ char smdyn[];
    const uint32_t smb = smem_to_u32(smdyn);
    const int t = threadIdx.x;
    const int wid = t >> 5, lane = t & 31;
    const int wm = wid & 1, wn = wid >> 1;           // 2x4 warp grid
    const int bm = blockIdx.y * 128;
    const int nb = n_off + blockIdx.x * 128;

    const __half* srcA = g_a + (size_t)bm * EDIM;
    const __half* srcB = g_w + (size_t)nb * EDIM;

    float acc[4][4][4];
#pragma unroll
    for (int mi = 0; mi < 4; ++mi)
#pragma unroll
        for (int ni = 0; ni < 4; ++ni)
#pragma unroll
            for (int e = 0; e < 4; ++e) acc[mi][ni][e] = 0.0f;

    const int lrow8 = (lane & 7) + ((lane >> 3) & 1) * 8;
    const int lkoff = (lane >> 4) * 8;

    // prefetch chunk 0: per matrix 1024 x 16B; 256 threads x 4
    {
#pragma unroll
        for (int kk = 0; kk < 4; ++kk) {
            const int id = t + kk * 256;
            const int r = id >> 3, cl = id & 7;
            const uint32_t d = smb + (uint32_t)(r * (GP * 2) + cl * 16);
            const int s = r * EDIM + cl * 8;
            cp16(d, srcA + s);
            cp16(d + MTX, srcB + s);
        }
        cp_commit();
    }

    const int NC = EDIM / BK;  // 12
#pragma unroll 1
    for (int ch = 0; ch < NC; ++ch) {
        cp_wait0();
        __syncthreads();
        if (ch + 1 < NC) {
            const uint32_t bufn = ((ch + 1) & 1) * GBUF;
#pragma unroll
            for (int kk = 0; kk < 4; ++kk) {
                const int id = t + kk * 256;
                const int r = id >> 3, cl = id & 7;
                const uint32_t d = smb + bufn + (uint32_t)(r * (GP * 2) + cl * 16);
                const int s = r * EDIM + (ch + 1) * BK + cl * 8;
                cp16(d, srcA + s);
                cp16(d + MTX, srcB + s);
            }
            cp_commit();
        }
        const uint32_t buf = smb + (ch & 1) * GBUF;
        const uint32_t aA = buf + (uint32_t)((wm * 64 + lrow8) * (GP * 2));
        const uint32_t aB = buf + MTX + (uint32_t)((wn * 32 + lrow8) * (GP * 2));
#pragma unroll
        for (int ks = 0; ks < 4; ++ks) {
            const uint32_t kbyte = (uint32_t)((ks * 16 + lkoff) * 2);
            uint32_t bfr[2][4];
#pragma unroll
            for (int ng = 0; ng < 2; ++ng)
                ldmx4(bfr[ng], aB + (uint32_t)(ng * 16 * GP * 2) + kbyte);
#pragma unroll
            for (int mi = 0; mi < 4; ++mi) {
                uint32_t af[4];
                ldmx4(af, aA + (uint32_t)(mi * 16 * GP * 2) + kbyte);
#pragma unroll
                for (int ni = 0; ni < 4; ++ni) {
                    const int ng = ni >> 1, lo = ni & 1;
                    mma16816(acc[mi][ni], af, bfr[ng][lo], bfr[ng][lo + 2]);
                }
            }
        }
    }

    // epilogue
    const int r0 = bm + wm * 64 + (lane >> 2);
    const int cbase = nb + wn * 32 + (lane & 3) * 2;
#pragma unroll
    for (int mi = 0; mi < 4; ++mi) {
#pragma unroll
        for (int half = 0; half < 2; ++half) {
            const int m = r0 + mi * 16 + half * 8;
            const int i_ = m / CDIM, c_ = m % CDIM;
#pragma unroll
            for (int ni = 0; ni < 4; ++ni) {
                const int ng = cbase + ni * 8;
                float ox = acc[mi][ni][half * 2 + 0] + g_bias[ng + 0];
                float oy = acc[mi][ni][half * 2 + 1] + g_bias[ng + 1];
                if (mode == 0) {
                    const int sel = ng / EDIM, f = ng % EDIM, h = f >> 6, d = f & 63;
                    if (sel == 0) { ox *= 0.125f; oy *= 0.125f; }
                    __half* dst = (sel == 0) ? g_q : (sel == 1) ? g_k : g_v;
                    const size_t off = (((size_t)c_ * HDIM + h) * RDIM + i_) * DDIM + d;
                    *(__half2*)(dst + off) =
                        __half2(__float2half_rn(ox), __float2half_rn(oy));
                } else {
                    float2 o; o.x = ox; o.y = oy;
                    *(float2*)(outp + (size_t)m * EDIM + (ng - 3 * EDIM)) = o;
                }
            }
        }
    }
}

// ---------------- register-flash fp16 HMMA attention (1 head/CTA, 2 CTAs/SM) ----------------
// PV uses ldmatrix.trans directly on V [j][d] — no smem transpose, no extra barriers.
__global__ __launch_bounds__(256, 2)
void attn_tc(const unsigned char* __restrict__ mask, float* __restrict__ probs)
{
    extern __shared__ char sm[];
    const uint32_t smb = smem_to_u32(sm);
    const int c = blockIdx.x, h = blockIdx.y;
    const int t = threadIdx.x, wid = t >> 5, lane = t & 31;

    // ---- loads: q, k, v, all [128][64] fp16 ----
    {
        const size_t gb = ((size_t)c * HDIM + h) * (RDIM * DDIM);
        const __half* sq[3] = { g_q + gb, g_k + gb, g_v + gb };
        const uint32_t qo[3] = { AQ, AK, AV };
#pragma unroll
        for (int m = 0; m < 3; ++m)
#pragma unroll
            for (int k = 0; k < 4; ++k) {
                const int id = t + k * 256;
                const int r = id >> 3, cl = id & 7;
                cp16(smb + qo[m] + (uint32_t)(r * (PA * 2) + cl * 16),
                     sq[m] + (size_t)r * DDIM + cl * 8);
            }
    }
    cp_commit();

    // mask bitmap
    uint32_t* bmw = (uint32_t*)(sm + ABM);
    if (t < 4) bmw[t] = 0;
    __syncthreads();
    if (t < RDIM && mask[(size_t)t * CDIM + c]) atomicOr(&bmw[t >> 5], 1u << (t & 31));
    cp_wait0();
    __syncthreads();
    const uint32_t mb[4] = { bmw[0], bmw[1], bmw[2], bmw[3] };
    const bool any_mask = (mb[0] | mb[1] | mb[2] | mb[3]) != 0;

    const int rw = wid;                       // warp owns rows [16rw, 16rw+16)
    const int lrow8 = (lane & 7) + ((lane >> 3) & 1) * 8;
    const int lkoff = (lane >> 4) * 8;

    // ---- S = Q K^T : warp tile 16(m) x 128(n), k=64, single product ----
    float sacc[16][4];
#pragma unroll
    for (int ni = 0; ni < 16; ++ni)
#pragma unroll
        for (int e = 0; e < 4; ++e) sacc[ni][e] = 0.0f;

    const uint32_t qb = smb + AQ + (uint32_t)((rw * 16 + lrow8) * (PA * 2));
    const uint32_t kbse = smb + AK + (uint32_t)(lrow8 * (PA * 2));
#pragma unroll
    for (int ks = 0; ks < 4; ++ks) {
        const uint32_t ko = (uint32_t)((ks * 16 + lkoff) * 2);
        uint32_t qf[4];
        ldmx4(qf, qb + ko);
#pragma unroll
        for (int nh = 0; nh < 2; ++nh) {
            uint32_t kf[4][4];
#pragma unroll
            for (int nb8 = 0; nb8 < 4; ++nb8)
                ldmx4(kf[nb8], kbse + (uint32_t)((nh * 64 + nb8 * 16) * (PA * 2)) + ko);
#pragma unroll
            for (int ni = 0; ni < 8; ++ni) {
                const int g = ni >> 1, lo = ni & 1, idx = nh * 8 + ni;
                mma16816(sacc[idx], qf, kf[g][lo], kf[g][lo + 2]);
            }
        }
    }

    // ---- mask + warp-local softmax ----
    if (any_mask) {
#pragma unroll
        for (int ni = 0; ni < 16; ++ni) {
            const uint32_t w = mb[ni >> 2];
            const int b0 = (ni & 3) * 8 + (lane & 3) * 2;
            if ((w >> b0) & 1)       { sacc[ni][0] = -10000.0f; sacc[ni][2] = -10000.0f; }
            if ((w >> (b0 + 1)) & 1) { sacc[ni][1] = -10000.0f; sacc[ni][3] = -10000.0f; }
        }
    }
    float mx0 = -3.0e38f, mx1 = -3.0e38f;
#pragma unroll
    for (int ni = 0; ni < 16; ++ni) {
        mx0 = fmaxf(mx0, fmaxf(sacc[ni][0], sacc[ni][1]));
        mx1 = fmaxf(mx1, fmaxf(sacc[ni][2], sacc[ni][3]));
    }
    mx0 = fmaxf(mx0, __shfl_xor_sync(0xffffffffu, mx0, 1));
    mx0 = fmaxf(mx0, __shfl_xor_sync(0xffffffffu, mx0, 2));
    mx1 = fmaxf(mx1, __shfl_xor_sync(0xffffffffu, mx1, 1));
    mx1 = fmaxf(mx1, __shfl_xor_sync(0xffffffffu, mx1, 2));

    float s0 = 0.0f, s1 = 0.0f;
#pragma unroll
    for (int ni = 0; ni < 16; ++ni) {
        sacc[ni][0] = __expf(sacc[ni][0] - mx0);
        sacc[ni][1] = __expf(sacc[ni][1] - mx0);
        sacc[ni][2] = __expf(sacc[ni][2] - mx1);
        sacc[ni][3] = __expf(sacc[ni][3] - mx1);
        s0 += sacc[ni][0] + sacc[ni][1];
        s1 += sacc[ni][2] + sacc[ni][3];
    }
    s0 += __shfl_xor_sync(0xffffffffu, s0, 1);
    s0 += __shfl_xor_sync(0xffffffffu, s0, 2);
    s1 += __shfl_xor_sync(0xffffffffu, s1, 1);
    s1 += __shfl_xor_sync(0xffffffffu, s1, 2);
    const float inv0 = 1.0f / s0, inv1 = 1.0f / s1;

    // ---- probs (normalized fp32) straight from registers ----
    {
        const int r0 = rw * 16 + (lane >> 2);
        float* pb = probs + (((size_t)h * CDIM + c) * RDIM + r0) * RDIM + (lane & 3) * 2;
#pragma unroll
        for (int ni = 0; ni < 16; ++ni) {
            float2 a; a.x = sacc[ni][0] * inv0; a.y = sacc[ni][1] * inv0;
            float2 b; b.x = sacc[ni][2] * inv1; b.y = sacc[ni][3] * inv1;
            *(float2*)(pb + ni * 8) = a;
            *(float2*)(pb + 8 * RDIM + ni * 8) = b;
        }
    }

    // ---- pack unnormalized P -> fp16 A-fragments ----
    uint32_t ph0[16], ph1[16];
#pragma unroll
    for (int ni = 0; ni < 16; ++ni) {
        ph0[ni] = packh(sacc[ni][0], sacc[ni][1]);
        ph1[ni] = packh(sacc[ni][2], sacc[ni][3]);
    }

    // ---- ctx = P V : warp tile 16(m) x 64(n), k=128, V via ldmatrix.trans ----
    // trans lane mapping: bit4 -> k-row half, bit3 -> n-col half
    const int trow = (lane & 7) + ((lane >> 4) << 3);
    const int tcol = ((lane >> 3) & 1) * 8;
    const uint32_t vb = smb + AV + (uint32_t)(trow * (PA * 2) + tcol * 2);

    float cacc[8][4];
#pragma unroll
    for (int ni = 0; ni < 8; ++ni)
#pragma unroll
        for (int e = 0; e < 4; ++e) cacc[ni][e] = 0.0f;

#pragma unroll
    for (int kb = 0; kb < 8; ++kb) {
        const uint32_t krow = (uint32_t)(kb * 16 * (PA * 2));
        const uint32_t a_h[4] = { ph0[2 * kb], ph1[2 * kb], ph0[2 * kb + 1], ph1[2 * kb + 1] };
#pragma unroll
        for (int vh2 = 0; vh2 < 2; ++vh2) {
            uint32_t vf[2][4];
#pragma unroll
            for (int nb8 = 0; nb8 < 2; ++nb8)
                ldmx4t(vf[nb8], vb + krow + (uint32_t)((vh2 * 32 + nb8 * 16) * 2));
#pragma unroll
            for (int nl = 0; nl < 4; ++nl) {
                const int g = nl >> 1, lo = nl & 1, idx = vh2 * 4 + nl;
                mma16816(cacc[idx], a_h, vf[g][lo], vf[g][lo + 2]);
            }
        }
    }

    // ---- ctx epilogue (normalize, single fp16, feed out-projection) ----
    {
        const int r0 = rw * 16 + (lane >> 2);
#pragma unroll
        for (int ni = 0; ni < 8; ++ni) {
            const int d = ni * 8 + (lane & 3) * 2;
            const size_t ob0 = ((size_t)r0 * CDIM + c) * EDIM + h * DDIM + d;
            const size_t ob1 = ((size_t)(r0 + 8) * CDIM + c) * EDIM + h * DDIM + d;
            *(__half2*)(g_a + ob0) = __half2(__float2half_rn(cacc[ni][0] * inv0),
                                             __float2half_rn(cacc[ni][1] * inv0));
            *(__half2*)(g_a + ob1) = __half2(__float2half_rn(cacc[ni][2] * inv1),
                                             __float2half_rn(cacc[ni][3] * inv1));
        }
    }
}

// ---------------------------------------------------------------------------
extern "C" void kernel_launch(void* const* d_in, const int* in_sizes, int n_in,
                              void* d_out, int out_size)
{
    const float* x  = (const float*)d_in[0];
    const unsigned char* mask = (const unsigned char*)d_in[2];
    const float* wq = (const float*)d_in[3];
    const float* bq = (const float*)d_in[4];
    const float* wk = (const float*)d_in[5];
    const float* bk = (const float*)d_in[6];
    const float* wv = (const float*)d_in[7];
    const float* bv = (const float*)d_in[8];
    const float* wo = (const float*)d_in[9];
    const float* bo = (const float*)d_in[10];

    float* out   = (float*)d_out;                    // (R, C, 1, E)
    float* probs = out + (size_t)MDIM * EDIM;        // (H, C, 1, R, R)

    const int gemm_smem = 2 * GBUF;                  // 73728
    cudaFuncSetAttribute(gemm_tc, cudaFuncAttributeMaxDynamicSharedMemorySize, gemm_smem);
    cudaFuncSetAttribute(attn_tc, cudaFuncAttributeMaxDynamicSharedMemorySize, ATOT);

    conv_all<<<11520, 1024>>>(x, wq, wk, wv, wo, bq, bk, bv, bo);
    gemm_tc<<<dim3(18, MDIM / 128), 256, gemm_smem>>>(0, 0, out);        // qkv
    attn_tc<<<dim3(CDIM, HDIM), 256, ATOT>>>(mask, probs);
    gemm_tc<<<dim3(6, MDIM / 128), 256, gemm_smem>>>(3 * EDIM, 1, out);  // out proj
}